// round 7
// baseline (speedup 1.0000x reference)
#include <cuda_runtime.h>
#include <cuda_bf16.h>
#include <cstdint>

#define T_DIM  128
#define B_DIM  64
#define IN_RAW 144
#define H_DIM  2048
#define C_DIM  10
#define BN_EPS 1e-5f
#define MTOT   (T_DIM*B_DIM)   // 8192
#define BH     (B_DIM*H_DIM)   // 131072
#define NC0    3               // layer0 K=144 padded to 192 = 3 chunks of 64
#define NCH    32              // 2048/64

// GEMM tile: BM=128, BN=256, KC=64 bf16; 256 threads (8 warps, 2x4, 64x64 tiles)
#define CHUNK_A 32768          // 128 rows x 128B x (hi+lo)
#define CHUNK_B 65536          // 256 rows x 128B x (hi+lo)
#define STAGE_BYTES (CHUNK_A + CHUNK_B)    // 98304
#define DSMEM_BYTES (2*STAGE_BYTES)        // 196608

// ---------------- scratch (allocation-free device globals) -----------------
__device__ __align__(128) unsigned char g_apack[64u*32u*CHUNK_A];        // 64MB
__device__ __align__(128) unsigned char g_bpack0[8u*NC0*CHUNK_B];        // 1.5MB
__device__ __align__(128) unsigned char g_bpackH[3u*8u*NCH*CHUNK_B];     // 48MB
__device__ float g_z[MTOT*H_DIM];       // 64MB
__device__ float g_h[MTOT*H_DIM];       // 64MB
__device__ float g_psum[BH];
__device__ float g_psumsq[BH];
__device__ float g_scale[H_DIM];
__device__ float g_shift[H_DIM];
__device__ float g_hlast[BH];

// ---------------- PTX helpers ----------------
__device__ __forceinline__ uint32_t smem_u32(const void* p) {
    uint32_t a;
    asm("{ .reg .u64 t; cvta.to.shared.u64 t, %1; cvt.u32.u64 %0, t; }" : "=r"(a) : "l"(p));
    return a;
}
__device__ __forceinline__ void bulk_g2s(uint32_t dst, const void* src,
                                         uint32_t bytes, uint32_t mbar) {
    asm volatile(
        "cp.async.bulk.shared::cluster.global.mbarrier::complete_tx::bytes [%0], [%1], %2, [%3];"
        :: "r"(dst), "l"(src), "r"(bytes), "r"(mbar) : "memory");
}
#define MBAR_INIT(a, c) asm volatile("mbarrier.init.shared.b64 [%0], %1;" :: "r"(a), "r"(c) : "memory")
#define MBAR_EXPECT_TX(a, b) asm volatile("mbarrier.arrive.expect_tx.shared.b64 _, [%0], %1;" :: "r"(a), "r"(b) : "memory")
#define FENCE_ASYNC() asm volatile("fence.proxy.async.shared::cta;" ::: "memory")
#define MBAR_WAIT(a, ph) do { \
    uint32_t _done; \
    asm volatile("{\n\t.reg .pred p;\n\tmbarrier.try_wait.parity.acquire.cta.shared::cta.b64 p, [%1], %2;\n\tselp.b32 %0,1,0,p;\n\t}" \
        : "=r"(_done) : "r"(a), "r"(ph) : "memory"); \
    if (!_done) { \
        asm volatile("{\n\t.reg .pred P1;\n\tWL_%=:\n\tmbarrier.try_wait.parity.acquire.cta.shared::cta.b64 P1, [%0], %1, 0x989680;\n\t@P1 bra.uni WD_%=;\n\tbra.uni WL_%=;\n\tWD_%=:\n\t}" \
            :: "r"(a), "r"(ph) : "memory"); \
    } \
} while (0)

__device__ __forceinline__ void ldsm4(uint32_t r[4], uint32_t addr) {
    asm volatile("ldmatrix.sync.aligned.m8n8.x4.shared.b16 {%0,%1,%2,%3}, [%4];"
        : "=r"(r[0]), "=r"(r[1]), "=r"(r[2]), "=r"(r[3]) : "r"(addr));
}
__device__ __forceinline__ void mma16816(float c[4], const uint32_t a[4],
                                         uint32_t b0, uint32_t b1) {
    asm volatile(
        "mma.sync.aligned.m16n8k16.row.col.f32.bf16.bf16.f32 "
        "{%0,%1,%2,%3}, {%4,%5,%6,%7}, {%8,%9}, {%0,%1,%2,%3};"
        : "+f"(c[0]), "+f"(c[1]), "+f"(c[2]), "+f"(c[3])
        : "r"(a[0]), "r"(a[1]), "r"(a[2]), "r"(a[3]), "r"(b0), "r"(b1));
}

// split 8 fp32 -> bf16 hi/lo planes, two 16B stores at off and off+planeOff
__device__ __forceinline__ void split_store8(unsigned char* base, uint32_t off,
                                             uint32_t planeOff, const float v[8]) {
    union { uint4 q; unsigned short us[8]; } Hq, Lq;
    #pragma unroll
    for (int i = 0; i < 8; ++i) {
        __nv_bfloat16 h = __float2bfloat16(v[i]);
        Hq.us[i] = __bfloat16_as_ushort(h);
        Lq.us[i] = __bfloat16_as_ushort(__float2bfloat16(v[i] - __bfloat162float(h)));
    }
    *reinterpret_cast<uint4*>(base + off)            = Hq.q;
    *reinterpret_cast<uint4*>(base + off + planeOff) = Lq.q;
}

// ---------------- GEMM: Z = A@W^T + bias (3-product bf16 split) ------------
__global__ __launch_bounds__(256, 1)
void gemm_mma(const unsigned char* __restrict__ apack,
              const unsigned char* __restrict__ bpack,
              const float* __restrict__ bias, float* __restrict__ Z, int NC)
{
    extern __shared__ unsigned char dyn[];
    __shared__ __align__(8) uint64_t mbar_s[2];
    const uint32_t sb = smem_u32(dyn);
    const uint32_t mb = smem_u32(mbar_s);

    const int tid  = threadIdx.x;
    const int lane = tid & 31;
    const int wid  = tid >> 5;
    const int wm   = wid >> 2;          // 0..1 (64 rows)
    const int wn   = wid & 3;           // 0..3 (64 cols)
    const int nblk = blockIdx.x;
    const int mblk = blockIdx.y;

    const unsigned char* aSrc = apack + (size_t)mblk * NC * CHUNK_A;
    const unsigned char* bSrc = bpack + (size_t)nblk * NC * CHUNK_B;

    if (tid == 0) {
        MBAR_INIT(mb, 1); MBAR_INIT(mb + 8, 1);
        FENCE_ASYNC();
    }
    __syncthreads();
    if (tid == 0) {
        #pragma unroll
        for (int s = 0; s < 2; ++s) {
            if (s < NC) {
                MBAR_EXPECT_TX(mb + 8 * s, STAGE_BYTES);
                bulk_g2s(sb + s * STAGE_BYTES,           aSrc + (size_t)s * CHUNK_A, CHUNK_A, mb + 8 * s);
                bulk_g2s(sb + s * STAGE_BYTES + CHUNK_A, bSrc + (size_t)s * CHUNK_B, CHUNK_B, mb + 8 * s);
            }
        }
    }

    // per-lane ldmatrix geometry (SW128 swizzle)
    const int rowA  = wm * 64 + (lane & 15);
    const int rowB  = wn * 64 + ((lane >> 4) << 3) + (lane & 7);
    const int xorC  = (lane & 7) << 4;
    const int colA0 = (lane >> 4) * 16;
    const int colB0 = ((lane >> 3) & 1) * 16;

    float acc[4][8][4];
    #pragma unroll
    for (int i = 0; i < 4; ++i)
        #pragma unroll
        for (int j = 0; j < 8; ++j)
            #pragma unroll
            for (int q = 0; q < 4; ++q) acc[i][j][q] = 0.0f;

    int ph[2] = {0, 0};
    for (int c = 0; c < NC; ++c) {
        const int s = c & 1;
        MBAR_WAIT(mb + 8 * s, ph[s]);
        ph[s] ^= 1;
        const uint32_t st = sb + s * STAGE_BYTES;

        #pragma unroll
        for (int kk = 0; kk < 4; ++kk) {
            const uint32_t cA = (uint32_t)((kk * 32 + colA0) ^ xorC);
            const uint32_t cB = (uint32_t)((kk * 32 + colB0) ^ xorC);
            uint32_t ah[4][4], al[4][4];
            #pragma unroll
            for (int mi = 0; mi < 4; ++mi) {
                const uint32_t ra = (uint32_t)(rowA + mi * 16) * 128;
                ldsm4(ah[mi], st + ra + cA);
                ldsm4(al[mi], st + 16384 + ra + cA);
            }
            #pragma unroll
            for (int nj = 0; nj < 4; ++nj) {
                const uint32_t rb = (uint32_t)(rowB + nj * 16) * 128;
                uint32_t bh[4], bl[4];
                ldsm4(bh, st + CHUNK_A + rb + cB);
                ldsm4(bl, st + CHUNK_A + 32768 + rb + cB);
                #pragma unroll
                for (int mi = 0; mi < 4; ++mi) {
                    mma16816(acc[mi][nj*2],   ah[mi], bh[0], bh[1]);
                    mma16816(acc[mi][nj*2+1], ah[mi], bh[2], bh[3]);
                }
                #pragma unroll
                for (int mi = 0; mi < 4; ++mi) {
                    mma16816(acc[mi][nj*2],   ah[mi], bl[0], bl[1]);
                    mma16816(acc[mi][nj*2+1], ah[mi], bl[2], bl[3]);
                }
                #pragma unroll
                for (int mi = 0; mi < 4; ++mi) {
                    mma16816(acc[mi][nj*2],   al[mi], bh[0], bh[1]);
                    mma16816(acc[mi][nj*2+1], al[mi], bh[2], bh[3]);
                }
            }
        }
        __syncthreads();
        if (c + 2 < NC && tid == 0) {
            MBAR_EXPECT_TX(mb + 8 * s, STAGE_BYTES);
            bulk_g2s(st,           aSrc + (size_t)(c + 2) * CHUNK_A, CHUNK_A, mb + 8 * s);
            bulk_g2s(st + CHUNK_A, bSrc + (size_t)(c + 2) * CHUNK_B, CHUNK_B, mb + 8 * s);
        }
    }

    // epilogue: + bias
    const int g  = lane >> 2;
    const int tg = lane & 3;
    #pragma unroll
    for (int mi = 0; mi < 4; ++mi) {
        const int r0 = mblk * 128 + wm * 64 + mi * 16 + g;
        #pragma unroll
        for (int ni = 0; ni < 8; ++ni) {
            const int n = nblk * 256 + wn * 64 + ni * 8 + tg * 2;
            const float2 bia = *reinterpret_cast<const float2*>(&bias[n]);
            float2 v0 = {acc[mi][ni][0] + bia.x, acc[mi][ni][1] + bia.y};
            float2 v1 = {acc[mi][ni][2] + bia.x, acc[mi][ni][3] + bia.y};
            *reinterpret_cast<float2*>(&Z[(size_t)r0 * H_DIM + n])       = v0;
            *reinterpret_cast<float2*>(&Z[(size_t)(r0 + 8) * H_DIM + n]) = v1;
        }
    }
}

// ---------------- x -> packed split A (layer 0, K padded 144->192) ---------
__global__ __launch_bounds__(32)
void quant_x(const float* __restrict__ x, unsigned char* __restrict__ apack)
{
    const int m = blockIdx.x;
    const int k0 = threadIdx.x * 8;
    if (k0 >= 192) return;
    float v[8];
    if (k0 < IN_RAW) {
        *reinterpret_cast<float4*>(&v[0]) = *reinterpret_cast<const float4*>(&x[(size_t)m * IN_RAW + k0]);
        *reinterpret_cast<float4*>(&v[4]) = *reinterpret_cast<const float4*>(&x[(size_t)m * IN_RAW + k0 + 4]);
    } else {
        #pragma unroll
        for (int i = 0; i < 8; ++i) v[i] = 0.0f;
    }
    const int mblk = m >> 7, row = m & 127, kc = k0 >> 6;
    const uint32_t off = (uint32_t)(row * 128 + (((k0 & 63) * 2) ^ ((row & 7) << 4)));
    split_store8(apack + (size_t)(mblk * NC0 + kc) * CHUNK_A, off, 16384, v);
}

// ---------------- layer-0 weights -> packed B (256-row nblk) ---------------
__global__ __launch_bounds__(32)
void prep_w0(const float* __restrict__ W0, unsigned char* __restrict__ bpack)
{
    const int n = blockIdx.x;
    const int k0 = threadIdx.x * 8;
    if (k0 >= 192) return;
    float v[8];
    if (k0 < IN_RAW) {
        *reinterpret_cast<float4*>(&v[0]) = *reinterpret_cast<const float4*>(&W0[(size_t)n * IN_RAW + k0]);
        *reinterpret_cast<float4*>(&v[4]) = *reinterpret_cast<const float4*>(&W0[(size_t)n * IN_RAW + k0 + 4]);
    } else {
        #pragma unroll
        for (int i = 0; i < 8; ++i) v[i] = 0.0f;
    }
    const int nblk = n >> 8, row = n & 255, kc = k0 >> 6;
    const uint32_t off = (uint32_t)(row * 128 + (((k0 & 63) * 2) ^ ((row & 7) << 4)));
    split_store8(bpack + (size_t)(nblk * NC0 + kc) * CHUNK_B, off, 32768, v);
}

// ---------------- H-layer weights -> packed B (all 3 layers, once) ---------
__global__ __launch_bounds__(256)
void prep_wH(const float* __restrict__ Ws, unsigned char* __restrict__ bpackH)
{
    const int n = blockIdx.x;
    const int l = blockIdx.y;
    const int k0 = threadIdx.x * 8;
    float v[8];
    const float* wrow = Ws + (size_t)l * H_DIM * H_DIM + (size_t)n * H_DIM + k0;
    *reinterpret_cast<float4*>(&v[0]) = *reinterpret_cast<const float4*>(wrow);
    *reinterpret_cast<float4*>(&v[4]) = *reinterpret_cast<const float4*>(wrow + 4);
    const int nblk = n >> 8, row = n & 255, kc = k0 >> 6;
    unsigned char* base = bpackH + (size_t)l * 8 * NCH * CHUNK_B
                                 + (size_t)(nblk * NCH + kc) * CHUNK_B;
    const uint32_t off = (uint32_t)(row * 128 + (((k0 & 63) * 2) ^ ((row & 7) << 4)));
    split_store8(base, off, 32768, v);
}

// ---------------- IndRNN scan + stats (fp32, 1 elem/thread) ----------------
__global__ __launch_bounds__(256)
void scan_kernel(const float* __restrict__ Z, const float* __restrict__ u,
                 float* __restrict__ H, float* __restrict__ hlast,
                 float* __restrict__ psum, float* __restrict__ psumsq)
{
    const int j = blockIdx.x * 256 + threadIdx.x;
    const float uh = u[j & (H_DIM - 1)];
    float hc = 0.0f, s = 0.0f, s2 = 0.0f;
    #pragma unroll 4
    for (int t = 0; t < T_DIM; ++t) {
        const float v = Z[(size_t)t * BH + j];
        hc = fmaxf(fmaf(uh, hc, v), 0.0f);
        H[(size_t)t * BH + j] = hc;
        s  += hc;
        s2 = fmaf(hc, hc, s2);
    }
    hlast[j]  = hc;
    psum[j]   = s;
    psumsq[j] = s2;
}

// ---------------- BN stats -> folded affine --------------------------------
__global__ __launch_bounds__(256)
void bn_finalize(const float* __restrict__ psum, const float* __restrict__ psumsq,
                 const float* __restrict__ gamma, const float* __restrict__ beta,
                 float* __restrict__ scale, float* __restrict__ shift)
{
    const int h = blockIdx.x * 256 + threadIdx.x;
    float s = 0.0f, s2 = 0.0f;
    #pragma unroll 8
    for (int b = 0; b < B_DIM; ++b) {
        s  += psum[b * H_DIM + h];
        s2 += psumsq[b * H_DIM + h];
    }
    const float inv_n = 1.0f / (float)(T_DIM * B_DIM);
    const float mean  = s * inv_n;
    const float var   = s2 * inv_n - mean * mean;
    const float rstd  = rsqrtf(var + BN_EPS);
    const float sc    = gamma[h] * rstd;
    scale[h] = sc;
    shift[h] = fmaf(-mean, sc, beta[h]);
}

// ---------------- BN(h) -> packed split A ----------------------------------
__global__ __launch_bounds__(256)
void quant_h(const float* __restrict__ H, const float* __restrict__ scale,
             const float* __restrict__ shift, unsigned char* __restrict__ apack)
{
    const int m = blockIdx.x;
    const int k0 = threadIdx.x * 8;
    float v[8], sc[8], sh[8];
    const float* hrow = H + (size_t)m * H_DIM + k0;
    *reinterpret_cast<float4*>(&v[0])  = *reinterpret_cast<const float4*>(hrow);
    *reinterpret_cast<float4*>(&v[4])  = *reinterpret_cast<const float4*>(hrow + 4);
    *reinterpret_cast<float4*>(&sc[0]) = *reinterpret_cast<const float4*>(&scale[k0]);
    *reinterpret_cast<float4*>(&sc[4]) = *reinterpret_cast<const float4*>(&scale[k0 + 4]);
    *reinterpret_cast<float4*>(&sh[0]) = *reinterpret_cast<const float4*>(&shift[k0]);
    *reinterpret_cast<float4*>(&sh[4]) = *reinterpret_cast<const float4*>(&shift[k0 + 4]);
    #pragma unroll
    for (int i = 0; i < 8; ++i) v[i] = fmaf(v[i], sc[i], sh[i]);
    const int mblk = m >> 7, row = m & 127, kc = k0 >> 6;
    const uint32_t off = (uint32_t)(row * 128 + (((k0 & 63) * 2) ^ ((row & 7) << 4)));
    split_store8(apack + (size_t)(mblk * NCH + kc) * CHUNK_A, off, 16384, v);
}

// ---------------- final projection -----------------------------------------
__global__ __launch_bounds__(256)
void final_proj(const float* __restrict__ Hlast,
                const float* __restrict__ scale, const float* __restrict__ shift,
                const float* __restrict__ Wl, const float* __restrict__ bl,
                float* __restrict__ out)
{
    const int b = blockIdx.x, c = blockIdx.y;
    __shared__ float red[256];
    float s = 0.0f;
    for (int h = threadIdx.x; h < H_DIM; h += 256) {
        const float hn = fmaf(Hlast[b * H_DIM + h], scale[h], shift[h]);
        s = fmaf(hn, Wl[c * H_DIM + h], s);
    }
    red[threadIdx.x] = s;
    __syncthreads();
    for (int o = 128; o > 0; o >>= 1) {
        if (threadIdx.x < o) red[threadIdx.x] += red[threadIdx.x + o];
        __syncthreads();
    }
    if (threadIdx.x == 0) out[b * C_DIM + c] = red[0] + bl[c];
}

// ---------------- launcher --------------------------------------------------
extern "C" void kernel_launch(void* const* d_in, const int* in_sizes, int n_in,
                              void* d_out, int out_size)
{
    const float* x      = (const float*)d_in[0];
    const float* W0     = (const float*)d_in[1];
    const float* Ws     = (const float*)d_in[2];
    const float* bs     = (const float*)d_in[3];
    const float* us     = (const float*)d_in[4];
    const float* gammas = (const float*)d_in[5];
    const float* betas  = (const float*)d_in[6];
    const float* Wlast  = (const float*)d_in[7];
    const float* blast  = (const float*)d_in[8];
    float* out = (float*)d_out;

    unsigned char *apack, *bpack0, *bpackH;
    float *z, *h, *psum, *psumsq, *scale, *shift, *hlast;
    cudaGetSymbolAddress((void**)&apack,  g_apack);
    cudaGetSymbolAddress((void**)&bpack0, g_bpack0);
    cudaGetSymbolAddress((void**)&bpackH, g_bpackH);
    cudaGetSymbolAddress((void**)&z,      g_z);
    cudaGetSymbolAddress((void**)&h,      g_h);
    cudaGetSymbolAddress((void**)&psum,   g_psum);
    cudaGetSymbolAddress((void**)&psumsq, g_psumsq);
    cudaGetSymbolAddress((void**)&scale,  g_scale);
    cudaGetSymbolAddress((void**)&shift,  g_shift);
    cudaGetSymbolAddress((void**)&hlast,  g_hlast);

    cudaFuncSetAttribute(gemm_mma, cudaFuncAttributeMaxDynamicSharedMemorySize, DSMEM_BYTES);

    const dim3 ggrid(H_DIM / 256, MTOT / 128);   // 8 x 64 = 512 CTAs

    quant_x<<<MTOT, 32>>>(x, apack);
    prep_w0<<<H_DIM, 32>>>(W0, bpack0);
    prep_wH<<<dim3(H_DIM, 3), 256>>>(Ws, bpackH);

    gemm_mma<<<ggrid, 256, DSMEM_BYTES>>>(apack, bpack0, bs, z, NC0);
    scan_kernel<<<BH / 256, 256>>>(z, us, h, hlast, psum, psumsq);
    bn_finalize<<<H_DIM / 256, 256>>>(psum, psumsq, gammas, betas, scale, shift);

    for (int l = 1; l < 4; ++l) {
        quant_h<<<MTOT, 256>>>(h, scale, shift, apack);
        gemm_mma<<<ggrid, 256, DSMEM_BYTES>>>(apack,
                                              bpackH + (size_t)(l - 1) * 8 * NCH * CHUNK_B,
                                              bs + l * H_DIM, z, NCH);
        scan_kernel<<<BH / 256, 256>>>(z, us + l * H_DIM, h, hlast, psum, psumsq);
        bn_finalize<<<H_DIM / 256, 256>>>(psum, psumsq, gammas + l * H_DIM,
                                          betas + l * H_DIM, scale, shift);
    }

    final_proj<<<dim3(B_DIM, C_DIM), 256>>>(hlast, scale, shift, Wlast, blast, out);
}

// round 8
// speedup vs baseline: 1.1284x; 1.1284x over previous
#include <cuda_runtime.h>
#include <cuda_bf16.h>
#include <cstdint>

#define T_DIM  128
#define B_DIM  64
#define IN_RAW 144
#define H_DIM  2048
#define C_DIM  10
#define BN_EPS 1e-5f
#define MTOT   (T_DIM*B_DIM)   // 8192
#define BH     (B_DIM*H_DIM)   // 131072
#define NC0    6               // layer0 K=144 padded to 192 = 6 chunks of 32
#define NCH    64              // 2048/32

// GEMM tile: BM=BN=128, KC=32 bf16 (64B rows, SW64); 256 thr (8 warps, 2x4, 64x32)
#define CHUNK_BYTES 16384      // 128 rows x 64B x (hi+lo planes of 8KB)
#define STAGE_BYTES 32768      // A chunk + B chunk
#define NSTAGE 3
#define DSMEM_BYTES (NSTAGE*STAGE_BYTES)   // 98304 per CTA -> 2 CTAs = 192KB

// ---------------- scratch (allocation-free device globals) -----------------
__device__ __align__(128) unsigned char g_apack[64u*64u*CHUNK_BYTES];     // 64MB
__device__ __align__(128) unsigned char g_bpack0[16u*NC0*CHUNK_BYTES];    // 1.5MB
__device__ __align__(128) unsigned char g_bpackH[3u*16u*NCH*CHUNK_BYTES]; // 48MB
__device__ float g_z[MTOT*H_DIM];       // 64MB
__device__ float g_h[MTOT*H_DIM];       // 64MB
__device__ float g_psum[BH];
__device__ float g_psumsq[BH];
__device__ float g_scale[H_DIM];
__device__ float g_shift[H_DIM];
__device__ float g_hlast[BH];

// ---------------- PTX helpers ----------------
__device__ __forceinline__ uint32_t smem_u32(const void* p) {
    uint32_t a;
    asm("{ .reg .u64 t; cvta.to.shared.u64 t, %1; cvt.u32.u64 %0, t; }" : "=r"(a) : "l"(p));
    return a;
}
__device__ __forceinline__ void bulk_g2s(uint32_t dst, const void* src,
                                         uint32_t bytes, uint32_t mbar) {
    asm volatile(
        "cp.async.bulk.shared::cluster.global.mbarrier::complete_tx::bytes [%0], [%1], %2, [%3];"
        :: "r"(dst), "l"(src), "r"(bytes), "r"(mbar) : "memory");
}
#define MBAR_INIT(a, c) asm volatile("mbarrier.init.shared.b64 [%0], %1;" :: "r"(a), "r"(c) : "memory")
#define MBAR_EXPECT_TX(a, b) asm volatile("mbarrier.arrive.expect_tx.shared.b64 _, [%0], %1;" :: "r"(a), "r"(b) : "memory")
#define FENCE_ASYNC() asm volatile("fence.proxy.async.shared::cta;" ::: "memory")
#define MBAR_WAIT(a, ph) do { \
    uint32_t _done; \
    asm volatile("{\n\t.reg .pred p;\n\tmbarrier.try_wait.parity.acquire.cta.shared::cta.b64 p, [%1], %2;\n\tselp.b32 %0,1,0,p;\n\t}" \
        : "=r"(_done) : "r"(a), "r"(ph) : "memory"); \
    if (!_done) { \
        asm volatile("{\n\t.reg .pred P1;\n\tWL_%=:\n\tmbarrier.try_wait.parity.acquire.cta.shared::cta.b64 P1, [%0], %1, 0x989680;\n\t@P1 bra.uni WD_%=;\n\tbra.uni WL_%=;\n\tWD_%=:\n\t}" \
            :: "r"(a), "r"(ph) : "memory"); \
    } \
} while (0)

__device__ __forceinline__ void ldsm4(uint32_t r[4], uint32_t addr) {
    asm volatile("ldmatrix.sync.aligned.m8n8.x4.shared.b16 {%0,%1,%2,%3}, [%4];"
        : "=r"(r[0]), "=r"(r[1]), "=r"(r[2]), "=r"(r[3]) : "r"(addr));
}
__device__ __forceinline__ void mma16816(float c[4], const uint32_t a[4],
                                         uint32_t b0, uint32_t b1) {
    asm volatile(
        "mma.sync.aligned.m16n8k16.row.col.f32.bf16.bf16.f32 "
        "{%0,%1,%2,%3}, {%4,%5,%6,%7}, {%8,%9}, {%0,%1,%2,%3};"
        : "+f"(c[0]), "+f"(c[1]), "+f"(c[2]), "+f"(c[3])
        : "r"(a[0]), "r"(a[1]), "r"(a[2]), "r"(a[3]), "r"(b0), "r"(b1));
}

// SW64 swizzle for 64B rows: byte_off ^ ((byte_off>>3)&0x30)
__device__ __forceinline__ uint32_t swz64(uint32_t off) { return off ^ ((off >> 3) & 0x30); }

// split 8 fp32 -> bf16 hi/lo planes (16B granules), planes 8KB apart
__device__ __forceinline__ void split_store8(unsigned char* base, uint32_t off,
                                             const float v[8]) {
    union { uint4 q; unsigned short us[8]; } Hq, Lq;
    #pragma unroll
    for (int i = 0; i < 8; ++i) {
        __nv_bfloat16 h = __float2bfloat16(v[i]);
        Hq.us[i] = __bfloat16_as_ushort(h);
        Lq.us[i] = __bfloat16_as_ushort(__float2bfloat16(v[i] - __bfloat162float(h)));
    }
    *reinterpret_cast<uint4*>(base + off)        = Hq.q;
    *reinterpret_cast<uint4*>(base + off + 8192) = Lq.q;
}

// ---------------- GEMM: Z = A@W^T + bias (3-product bf16 split) ------------
__global__ __launch_bounds__(256, 2)
void gemm_mma(const unsigned char* __restrict__ apack,
              const unsigned char* __restrict__ bpack,
              const float* __restrict__ bias, float* __restrict__ Z, int NC)
{
    extern __shared__ unsigned char dyn[];
    __shared__ __align__(8) uint64_t mbar_s[NSTAGE];
    const uint32_t sb = smem_u32(dyn);
    const uint32_t mb = smem_u32(mbar_s);

    const int tid  = threadIdx.x;
    const int lane = tid & 31;
    const int wid  = tid >> 5;
    const int wm   = wid >> 2;          // 0..1 (64 rows)
    const int wn   = wid & 3;           // 0..3 (32 cols)
    const int nblk = blockIdx.x;
    const int mblk = blockIdx.y;

    const unsigned char* aSrc = apack + (size_t)mblk * NC * CHUNK_BYTES;
    const unsigned char* bSrc = bpack + (size_t)nblk * NC * CHUNK_BYTES;

    if (tid == 0) {
        #pragma unroll
        for (int s = 0; s < NSTAGE; ++s) MBAR_INIT(mb + 8 * s, 1);
        FENCE_ASYNC();
    }
    __syncthreads();
    if (tid == 0) {
        #pragma unroll
        for (int s = 0; s < NSTAGE; ++s) {
            MBAR_EXPECT_TX(mb + 8 * s, STAGE_BYTES);
            bulk_g2s(sb + s * STAGE_BYTES,         aSrc + (size_t)s * CHUNK_BYTES, CHUNK_BYTES, mb + 8 * s);
            bulk_g2s(sb + s * STAGE_BYTES + 16384, bSrc + (size_t)s * CHUNK_BYTES, CHUNK_BYTES, mb + 8 * s);
        }
    }

    // per-lane geometry (SW64)
    const int rowA  = wm * 64 + (lane & 15);
    const int rowB  = wn * 32 + ((lane >> 4) << 3) + (lane & 7);
    const uint32_t xorA = (uint32_t)(((rowA >> 1) & 3) << 4);
    const uint32_t xorB = (uint32_t)(((rowB >> 1) & 3) << 4);
    const uint32_t colA0 = (uint32_t)((lane >> 4) * 16);
    const uint32_t colB0 = (uint32_t)(((lane >> 3) & 1) * 16);
    const uint32_t baseA = (uint32_t)rowA * 64;
    const uint32_t baseB = (uint32_t)rowB * 64;

    float acc[4][4][4];
    #pragma unroll
    for (int i = 0; i < 4; ++i)
        #pragma unroll
        for (int j = 0; j < 4; ++j)
            #pragma unroll
            for (int q = 0; q < 4; ++q) acc[i][j][q] = 0.0f;

    int ph[NSTAGE] = {0, 0, 0};
    for (int c = 0; c < NC; ++c) {
        const int s = (c < NSTAGE) ? c : (c % NSTAGE);
        MBAR_WAIT(mb + 8 * s, ph[s]);
        ph[s] ^= 1;
        const uint32_t st = sb + s * STAGE_BYTES;

        #pragma unroll
        for (int kk = 0; kk < 2; ++kk) {
            const uint32_t cA = (uint32_t)(kk * 32 + colA0) ^ xorA;
            const uint32_t cB = (uint32_t)(kk * 32 + colB0) ^ xorB;
            uint32_t ah[4][4], al[4][4], bh[2][4], bl[2][4];
            #pragma unroll
            for (int mi = 0; mi < 4; ++mi) {
                const uint32_t ra = baseA + (uint32_t)mi * 1024;   // 16 rows * 64B
                ldsm4(ah[mi], st + ra + cA);
                ldsm4(al[mi], st + 8192 + ra + cA);
            }
            #pragma unroll
            for (int nj = 0; nj < 2; ++nj) {
                const uint32_t rb = baseB + (uint32_t)nj * 1024;
                ldsm4(bh[nj], st + 16384 + rb + cB);
                ldsm4(bl[nj], st + 24576 + rb + cB);
            }
            #pragma unroll
            for (int nj = 0; nj < 2; ++nj) {
                // pass 1: Ah*Bh
                #pragma unroll
                for (int mi = 0; mi < 4; ++mi) {
                    mma16816(acc[mi][nj*2],   ah[mi], bh[nj][0], bh[nj][1]);
                    mma16816(acc[mi][nj*2+1], ah[mi], bh[nj][2], bh[nj][3]);
                }
                // pass 2: Ah*Bl
                #pragma unroll
                for (int mi = 0; mi < 4; ++mi) {
                    mma16816(acc[mi][nj*2],   ah[mi], bl[nj][0], bl[nj][1]);
                    mma16816(acc[mi][nj*2+1], ah[mi], bl[nj][2], bl[nj][3]);
                }
                // pass 3: Al*Bh
                #pragma unroll
                for (int mi = 0; mi < 4; ++mi) {
                    mma16816(acc[mi][nj*2],   al[mi], bh[nj][0], bh[nj][1]);
                    mma16816(acc[mi][nj*2+1], al[mi], bh[nj][2], bh[nj][3]);
                }
            }
        }
        __syncthreads();
        if (c + NSTAGE < NC && tid == 0) {
            MBAR_EXPECT_TX(mb + 8 * s, STAGE_BYTES);
            bulk_g2s(st,         aSrc + (size_t)(c + NSTAGE) * CHUNK_BYTES, CHUNK_BYTES, mb + 8 * s);
            bulk_g2s(st + 16384, bSrc + (size_t)(c + NSTAGE) * CHUNK_BYTES, CHUNK_BYTES, mb + 8 * s);
        }
    }

    // epilogue: + bias
    const int g  = lane >> 2;
    const int tg = lane & 3;
    #pragma unroll
    for (int mi = 0; mi < 4; ++mi) {
        const int r0 = mblk * 128 + wm * 64 + mi * 16 + g;
        #pragma unroll
        for (int ni = 0; ni < 4; ++ni) {
            const int n = nblk * 128 + wn * 32 + ni * 8 + tg * 2;
            const float2 bia = *reinterpret_cast<const float2*>(&bias[n]);
            float2 v0 = {acc[mi][ni][0] + bia.x, acc[mi][ni][1] + bia.y};
            float2 v1 = {acc[mi][ni][2] + bia.x, acc[mi][ni][3] + bia.y};
            *reinterpret_cast<float2*>(&Z[(size_t)r0 * H_DIM + n])       = v0;
            *reinterpret_cast<float2*>(&Z[(size_t)(r0 + 8) * H_DIM + n]) = v1;
        }
    }
}

// ---------------- x -> packed split A (layer 0, K padded 144->192) ---------
__global__ __launch_bounds__(32)
void quant_x(const float* __restrict__ x, unsigned char* __restrict__ apack)
{
    const int m = blockIdx.x;
    const int k0 = threadIdx.x * 8;
    if (k0 >= 192) return;
    float v[8];
    if (k0 < IN_RAW) {
        *reinterpret_cast<float4*>(&v[0]) = *reinterpret_cast<const float4*>(&x[(size_t)m * IN_RAW + k0]);
        *reinterpret_cast<float4*>(&v[4]) = *reinterpret_cast<const float4*>(&x[(size_t)m * IN_RAW + k0 + 4]);
    } else {
        #pragma unroll
        for (int i = 0; i < 8; ++i) v[i] = 0.0f;
    }
    const int mblk = m >> 7, row = m & 127, kc = k0 >> 5;
    const uint32_t off = (uint32_t)row * 64 + swz64((uint32_t)((k0 & 31) * 2)) ^ 0u;
    split_store8(apack + (size_t)(mblk * NC0 + kc) * CHUNK_BYTES,
                 (uint32_t)row * 64 + (((uint32_t)((k0 & 31) * 2)) ^ (uint32_t)(((row >> 1) & 3) << 4)), v);
    (void)off;
}

// ---------------- layer-0 weights -> packed B ------------------------------
__global__ __launch_bounds__(32)
void prep_w0(const float* __restrict__ W0, unsigned char* __restrict__ bpack)
{
    const int n = blockIdx.x;
    const int k0 = threadIdx.x * 8;
    if (k0 >= 192) return;
    float v[8];
    if (k0 < IN_RAW) {
        *reinterpret_cast<float4*>(&v[0]) = *reinterpret_cast<const float4*>(&W0[(size_t)n * IN_RAW + k0]);
        *reinterpret_cast<float4*>(&v[4]) = *reinterpret_cast<const float4*>(&W0[(size_t)n * IN_RAW + k0 + 4]);
    } else {
        #pragma unroll
        for (int i = 0; i < 8; ++i) v[i] = 0.0f;
    }
    const int nblk = n >> 7, row = n & 127, kc = k0 >> 5;
    const uint32_t off = (uint32_t)row * 64 + (((uint32_t)((k0 & 31) * 2)) ^ (uint32_t)(((row >> 1) & 3) << 4));
    split_store8(bpack + (size_t)(nblk * NC0 + kc) * CHUNK_BYTES, off, v);
}

// ---------------- H-layer weights -> packed B (all 3 layers, once) ---------
__global__ __launch_bounds__(256)
void prep_wH(const float* __restrict__ Ws, unsigned char* __restrict__ bpackH)
{
    const int n = blockIdx.x;
    const int l = blockIdx.y;
    const int k0 = threadIdx.x * 8;
    float v[8];
    const float* wrow = Ws + (size_t)l * H_DIM * H_DIM + (size_t)n * H_DIM + k0;
    *reinterpret_cast<float4*>(&v[0]) = *reinterpret_cast<const float4*>(wrow);
    *reinterpret_cast<float4*>(&v[4]) = *reinterpret_cast<const float4*>(wrow + 4);
    const int nblk = n >> 7, row = n & 127, kc = k0 >> 5;
    unsigned char* base = bpackH + (size_t)l * 16 * NCH * CHUNK_BYTES
                                 + (size_t)(nblk * NCH + kc) * CHUNK_BYTES;
    const uint32_t off = (uint32_t)row * 64 + (((uint32_t)((k0 & 31) * 2)) ^ (uint32_t)(((row >> 1) & 3) << 4));
    split_store8(base, off, v);
}

// ---------------- IndRNN scan + stats (fp32, 1 elem/thread) ----------------
__global__ __launch_bounds__(256)
void scan_kernel(const float* __restrict__ Z, const float* __restrict__ u,
                 float* __restrict__ H, float* __restrict__ hlast,
                 float* __restrict__ psum, float* __restrict__ psumsq)
{
    const int j = blockIdx.x * 256 + threadIdx.x;
    const float uh = u[j & (H_DIM - 1)];
    float hc = 0.0f, s = 0.0f, s2 = 0.0f;
    #pragma unroll 4
    for (int t = 0; t < T_DIM; ++t) {
        const float v = Z[(size_t)t * BH + j];
        hc = fmaxf(fmaf(uh, hc, v), 0.0f);
        H[(size_t)t * BH + j] = hc;
        s  += hc;
        s2 = fmaf(hc, hc, s2);
    }
    hlast[j]  = hc;
    psum[j]   = s;
    psumsq[j] = s2;
}

// ---------------- BN stats -> folded affine --------------------------------
__global__ __launch_bounds__(256)
void bn_finalize(const float* __restrict__ psum, const float* __restrict__ psumsq,
                 const float* __restrict__ gamma, const float* __restrict__ beta,
                 float* __restrict__ scale, float* __restrict__ shift)
{
    const int h = blockIdx.x * 256 + threadIdx.x;
    float s = 0.0f, s2 = 0.0f;
    #pragma unroll 8
    for (int b = 0; b < B_DIM; ++b) {
        s  += psum[b * H_DIM + h];
        s2 += psumsq[b * H_DIM + h];
    }
    const float inv_n = 1.0f / (float)(T_DIM * B_DIM);
    const float mean  = s * inv_n;
    const float var   = s2 * inv_n - mean * mean;
    const float rstd  = rsqrtf(var + BN_EPS);
    const float sc    = gamma[h] * rstd;
    scale[h] = sc;
    shift[h] = fmaf(-mean, sc, beta[h]);
}

// ---------------- BN(h) -> packed split A ----------------------------------
__global__ __launch_bounds__(256)
void quant_h(const float* __restrict__ H, const float* __restrict__ scale,
             const float* __restrict__ shift, unsigned char* __restrict__ apack)
{
    const int m = blockIdx.x;
    const int k0 = threadIdx.x * 8;
    float v[8], sc[8], sh[8];
    const float* hrow = H + (size_t)m * H_DIM + k0;
    *reinterpret_cast<float4*>(&v[0])  = *reinterpret_cast<const float4*>(hrow);
    *reinterpret_cast<float4*>(&v[4])  = *reinterpret_cast<const float4*>(hrow + 4);
    *reinterpret_cast<float4*>(&sc[0]) = *reinterpret_cast<const float4*>(&scale[k0]);
    *reinterpret_cast<float4*>(&sc[4]) = *reinterpret_cast<const float4*>(&scale[k0 + 4]);
    *reinterpret_cast<float4*>(&sh[0]) = *reinterpret_cast<const float4*>(&shift[k0]);
    *reinterpret_cast<float4*>(&sh[4]) = *reinterpret_cast<const float4*>(&shift[k0 + 4]);
    #pragma unroll
    for (int i = 0; i < 8; ++i) v[i] = fmaf(v[i], sc[i], sh[i]);
    const int mblk = m >> 7, row = m & 127, kc = k0 >> 5;
    const uint32_t off = (uint32_t)row * 64 + (((uint32_t)((k0 & 31) * 2)) ^ (uint32_t)(((row >> 1) & 3) << 4));
    split_store8(apack + (size_t)(mblk * NCH + kc) * CHUNK_BYTES, off, v);
}

// ---------------- final projection -----------------------------------------
__global__ __launch_bounds__(256)
void final_proj(const float* __restrict__ Hlast,
                const float* __restrict__ scale, const float* __restrict__ shift,
                const float* __restrict__ Wl, const float* __restrict__ bl,
                float* __restrict__ out)
{
    const int b = blockIdx.x, c = blockIdx.y;
    __shared__ float red[256];
    float s = 0.0f;
    for (int h = threadIdx.x; h < H_DIM; h += 256) {
        const float hn = fmaf(Hlast[b * H_DIM + h], scale[h], shift[h]);
        s = fmaf(hn, Wl[c * H_DIM + h], s);
    }
    red[threadIdx.x] = s;
    __syncthreads();
    for (int o = 128; o > 0; o >>= 1) {
        if (threadIdx.x < o) red[threadIdx.x] += red[threadIdx.x + o];
        __syncthreads();
    }
    if (threadIdx.x == 0) out[b * C_DIM + c] = red[0] + bl[c];
}

// ---------------- launcher --------------------------------------------------
extern "C" void kernel_launch(void* const* d_in, const int* in_sizes, int n_in,
                              void* d_out, int out_size)
{
    const float* x      = (const float*)d_in[0];
    const float* W0     = (const float*)d_in[1];
    const float* Ws     = (const float*)d_in[2];
    const float* bs     = (const float*)d_in[3];
    const float* us     = (const float*)d_in[4];
    const float* gammas = (const float*)d_in[5];
    const float* betas  = (const float*)d_in[6];
    const float* Wlast  = (const float*)d_in[7];
    const float* blast  = (const float*)d_in[8];
    float* out = (float*)d_out;

    unsigned char *apack, *bpack0, *bpackH;
    float *z, *h, *psum, *psumsq, *scale, *shift, *hlast;
    cudaGetSymbolAddress((void**)&apack,  g_apack);
    cudaGetSymbolAddress((void**)&bpack0, g_bpack0);
    cudaGetSymbolAddress((void**)&bpackH, g_bpackH);
    cudaGetSymbolAddress((void**)&z,      g_z);
    cudaGetSymbolAddress((void**)&h,      g_h);
    cudaGetSymbolAddress((void**)&psum,   g_psum);
    cudaGetSymbolAddress((void**)&psumsq, g_psumsq);
    cudaGetSymbolAddress((void**)&scale,  g_scale);
    cudaGetSymbolAddress((void**)&shift,  g_shift);
    cudaGetSymbolAddress((void**)&hlast,  g_hlast);

    cudaFuncSetAttribute(gemm_mma, cudaFuncAttributeMaxDynamicSharedMemorySize, DSMEM_BYTES);

    const dim3 ggrid(H_DIM / 128, MTOT / 128);   // 16 x 64 = 1024 CTAs, 2/SM

    quant_x<<<MTOT, 32>>>(x, apack);
    prep_w0<<<H_DIM, 32>>>(W0, bpack0);
    prep_wH<<<dim3(H_DIM, 3), 256>>>(Ws, bpackH);

    gemm_mma<<<ggrid, 256, DSMEM_BYTES>>>(apack, bpack0, bs, z, NC0);
    scan_kernel<<<BH / 256, 256>>>(z, us, h, hlast, psum, psumsq);
    bn_finalize<<<H_DIM / 256, 256>>>(psum, psumsq, gammas, betas, scale, shift);

    for (int l = 1; l < 4; ++l) {
        quant_h<<<MTOT, 256>>>(h, scale, shift, apack);
        gemm_mma<<<ggrid, 256, DSMEM_BYTES>>>(apack,
                                              bpackH + (size_t)(l - 1) * 16 * NCH * CHUNK_BYTES,
                                              bs + l * H_DIM, z, NCH);
        scan_kernel<<<BH / 256, 256>>>(z, us + l * H_DIM, h, hlast, psum, psumsq);
        bn_finalize<<<H_DIM / 256, 256>>>(psum, psumsq, gammas + l * H_DIM,
                                          betas + l * H_DIM, scale, shift);
    }

    final_proj<<<dim3(B_DIM, C_DIM), 256>>>(hlast, scale, shift, Wlast, blast, out);
}

// round 9
// speedup vs baseline: 1.4716x; 1.3042x over previous
#include <cuda_runtime.h>
#include <cuda_fp16.h>
#include <cstdint>

#define T_DIM  128
#define B_DIM  64
#define IN_RAW 144
#define H_DIM  2048
#define C_DIM  10
#define BN_EPS 1e-5f
#define MTOT   (T_DIM*B_DIM)   // 8192
#define BH     (B_DIM*H_DIM)   // 131072
#define NC0    6               // layer0 K=144 padded to 192 = 6 chunks of 32
#define NCH    64              // 2048/32

// GEMM tile: BM=BN=128, KC=32 fp16 (64B rows, SW64); 256 thr (8 warps, 2x4, 64x32)
// A: hi+lo fp16 planes (16KB/chunk); B: single fp16 plane (8KB/chunk)
#define CHUNK_A 16384
#define CHUNK_B 8192
#define STAGE_BYTES (CHUNK_A + CHUNK_B)    // 24576
#define NSTAGE 4
#define DSMEM_BYTES (NSTAGE*STAGE_BYTES)   // 98304/CTA -> 2 CTAs = 192KB

// ---------------- scratch (allocation-free device globals) -----------------
__device__ __align__(128) unsigned char g_apack[64u*64u*CHUNK_A];      // 64MB
__device__ __align__(128) unsigned char g_bpack0[16u*NC0*CHUNK_B];     // 0.75MB
__device__ __align__(128) unsigned char g_bpackH[3u*16u*NCH*CHUNK_B];  // 24MB
__device__ float g_z[MTOT*H_DIM];       // 64MB
__device__ float g_h[MTOT*H_DIM];       // 64MB
__device__ float g_psum[BH];
__device__ float g_psumsq[BH];
__device__ float g_scale[H_DIM];
__device__ float g_shift[H_DIM];
__device__ float g_hlast[BH];

// ---------------- PTX helpers ----------------
__device__ __forceinline__ uint32_t smem_u32(const void* p) {
    uint32_t a;
    asm("{ .reg .u64 t; cvta.to.shared.u64 t, %1; cvt.u32.u64 %0, t; }" : "=r"(a) : "l"(p));
    return a;
}
__device__ __forceinline__ void bulk_g2s(uint32_t dst, const void* src,
                                         uint32_t bytes, uint32_t mbar) {
    asm volatile(
        "cp.async.bulk.shared::cluster.global.mbarrier::complete_tx::bytes [%0], [%1], %2, [%3];"
        :: "r"(dst), "l"(src), "r"(bytes), "r"(mbar) : "memory");
}
#define MBAR_INIT(a, c) asm volatile("mbarrier.init.shared.b64 [%0], %1;" :: "r"(a), "r"(c) : "memory")
#define MBAR_EXPECT_TX(a, b) asm volatile("mbarrier.arrive.expect_tx.shared.b64 _, [%0], %1;" :: "r"(a), "r"(b) : "memory")
#define FENCE_ASYNC() asm volatile("fence.proxy.async.shared::cta;" ::: "memory")
#define MBAR_WAIT(a, ph) do { \
    uint32_t _done; \
    asm volatile("{\n\t.reg .pred p;\n\tmbarrier.try_wait.parity.acquire.cta.shared::cta.b64 p, [%1], %2;\n\tselp.b32 %0,1,0,p;\n\t}" \
        : "=r"(_done) : "r"(a), "r"(ph) : "memory"); \
    if (!_done) { \
        asm volatile("{\n\t.reg .pred P1;\n\tWL_%=:\n\tmbarrier.try_wait.parity.acquire.cta.shared::cta.b64 P1, [%0], %1, 0x989680;\n\t@P1 bra.uni WD_%=;\n\tbra.uni WL_%=;\n\tWD_%=:\n\t}" \
            :: "r"(a), "r"(ph) : "memory"); \
    } \
} while (0)

__device__ __forceinline__ void ldsm4(uint32_t r[4], uint32_t addr) {
    asm volatile("ldmatrix.sync.aligned.m8n8.x4.shared.b16 {%0,%1,%2,%3}, [%4];"
        : "=r"(r[0]), "=r"(r[1]), "=r"(r[2]), "=r"(r[3]) : "r"(addr));
}
__device__ __forceinline__ void mma16816(float c[4], const uint32_t a[4],
                                         uint32_t b0, uint32_t b1) {
    asm volatile(
        "mma.sync.aligned.m16n8k16.row.col.f32.f16.f16.f32 "
        "{%0,%1,%2,%3}, {%4,%5,%6,%7}, {%8,%9}, {%0,%1,%2,%3};"
        : "+f"(c[0]), "+f"(c[1]), "+f"(c[2]), "+f"(c[3])
        : "r"(a[0]), "r"(a[1]), "r"(a[2]), "r"(a[3]), "r"(b0), "r"(b1));
}

// SW64 swizzled byte offset inside one 128-row x 64B plane
__device__ __forceinline__ uint32_t sw64_off(int row, int colBytes) {
    return (uint32_t)row * 64 + (((uint32_t)colBytes) ^ (uint32_t)(((row >> 1) & 3) << 4));
}

// A: split 8 fp32 -> fp16 hi/lo planes (8KB apart)
__device__ __forceinline__ void split_store8(unsigned char* base, uint32_t off,
                                             const float v[8]) {
    union { uint4 q; unsigned short us[8]; } Hq, Lq;
    #pragma unroll
    for (int i = 0; i < 8; ++i) {
        __half h = __float2half(v[i]);
        Hq.us[i] = __half_as_ushort(h);
        Lq.us[i] = __half_as_ushort(__float2half(v[i] - __half2float(h)));
    }
    *reinterpret_cast<uint4*>(base + off)        = Hq.q;
    *reinterpret_cast<uint4*>(base + off + 8192) = Lq.q;
}
// B: 8 fp32 -> single fp16 plane
__device__ __forceinline__ void half_store8(unsigned char* base, uint32_t off,
                                            const float v[8]) {
    union { uint4 q; unsigned short us[8]; } Hq;
    #pragma unroll
    for (int i = 0; i < 8; ++i) Hq.us[i] = __half_as_ushort(__float2half(v[i]));
    *reinterpret_cast<uint4*>(base + off) = Hq.q;
}

// ---------------- GEMM: Z = A@W^T + bias (fp16 2-product split) ------------
__global__ __launch_bounds__(256, 2)
void gemm_mma(const unsigned char* __restrict__ apack,
              const unsigned char* __restrict__ bpack,
              const float* __restrict__ bias, float* __restrict__ Z, int NC)
{
    extern __shared__ unsigned char dyn[];
    __shared__ __align__(8) uint64_t mbar_s[NSTAGE];
    const uint32_t sb = smem_u32(dyn);
    const uint32_t mb = smem_u32(mbar_s);

    const int tid  = threadIdx.x;
    const int lane = tid & 31;
    const int wid  = tid >> 5;
    const int wm   = wid >> 2;          // 0..1 (64 rows)
    const int wn   = wid & 3;           // 0..3 (32 cols)
    const int nblk = blockIdx.x;
    const int mblk = blockIdx.y;

    const unsigned char* aSrc = apack + (size_t)mblk * NC * CHUNK_A;
    const unsigned char* bSrc = bpack + (size_t)nblk * NC * CHUNK_B;

    if (tid == 0) {
        #pragma unroll
        for (int s = 0; s < NSTAGE; ++s) MBAR_INIT(mb + 8 * s, 1);
        FENCE_ASYNC();
    }
    __syncthreads();
    if (tid == 0) {
        #pragma unroll
        for (int s = 0; s < NSTAGE; ++s) {
            if (s < NC) {
                MBAR_EXPECT_TX(mb + 8 * s, STAGE_BYTES);
                bulk_g2s(sb + s * STAGE_BYTES,           aSrc + (size_t)s * CHUNK_A, CHUNK_A, mb + 8 * s);
                bulk_g2s(sb + s * STAGE_BYTES + CHUNK_A, bSrc + (size_t)s * CHUNK_B, CHUNK_B, mb + 8 * s);
            }
        }
    }

    // per-lane geometry (SW64)
    const int rowA  = wm * 64 + (lane & 15);
    const int rowB  = wn * 32 + ((lane >> 4) << 3) + (lane & 7);
    const uint32_t xorA = (uint32_t)(((rowA >> 1) & 3) << 4);
    const uint32_t xorB = (uint32_t)(((rowB >> 1) & 3) << 4);
    const uint32_t colA0 = (uint32_t)((lane >> 4) * 16);
    const uint32_t colB0 = (uint32_t)(((lane >> 3) & 1) * 16);
    const uint32_t baseA = (uint32_t)rowA * 64;
    const uint32_t baseB = (uint32_t)rowB * 64;

    float acc[4][4][4];
    #pragma unroll
    for (int i = 0; i < 4; ++i)
        #pragma unroll
        for (int j = 0; j < 4; ++j)
            #pragma unroll
            for (int q = 0; q < 4; ++q) acc[i][j][q] = 0.0f;

    int ph[NSTAGE] = {0, 0, 0, 0};
    for (int c = 0; c < NC; ++c) {
        const int s = c & (NSTAGE - 1);
        MBAR_WAIT(mb + 8 * s, ph[s]);
        ph[s] ^= 1;
        const uint32_t st = sb + s * STAGE_BYTES;

        #pragma unroll
        for (int kk = 0; kk < 2; ++kk) {
            const uint32_t cA = (uint32_t)(kk * 32 + colA0) ^ xorA;
            const uint32_t cB = (uint32_t)(kk * 32 + colB0) ^ xorB;
            uint32_t ah[4][4], al[4][4], bb[2][4];
            #pragma unroll
            for (int mi = 0; mi < 4; ++mi) {
                const uint32_t ra = baseA + (uint32_t)mi * 1024;   // 16 rows * 64B
                ldsm4(ah[mi], st + ra + cA);
                ldsm4(al[mi], st + 8192 + ra + cA);
            }
            #pragma unroll
            for (int nj = 0; nj < 2; ++nj)
                ldsm4(bb[nj], st + CHUNK_A + baseB + (uint32_t)nj * 1024 + cB);
            #pragma unroll
            for (int nj = 0; nj < 2; ++nj) {
                #pragma unroll
                for (int mi = 0; mi < 4; ++mi) {
                    mma16816(acc[mi][nj*2],   ah[mi], bb[nj][0], bb[nj][1]);
                    mma16816(acc[mi][nj*2+1], ah[mi], bb[nj][2], bb[nj][3]);
                }
                #pragma unroll
                for (int mi = 0; mi < 4; ++mi) {
                    mma16816(acc[mi][nj*2],   al[mi], bb[nj][0], bb[nj][1]);
                    mma16816(acc[mi][nj*2+1], al[mi], bb[nj][2], bb[nj][3]);
                }
            }
        }
        __syncthreads();
        if (c + NSTAGE < NC && tid == 0) {
            MBAR_EXPECT_TX(mb + 8 * s, STAGE_BYTES);
            bulk_g2s(st,           aSrc + (size_t)(c + NSTAGE) * CHUNK_A, CHUNK_A, mb + 8 * s);
            bulk_g2s(st + CHUNK_A, bSrc + (size_t)(c + NSTAGE) * CHUNK_B, CHUNK_B, mb + 8 * s);
        }
    }

    // epilogue: + bias
    const int g  = lane >> 2;
    const int tg = lane & 3;
    #pragma unroll
    for (int mi = 0; mi < 4; ++mi) {
        const int r0 = mblk * 128 + wm * 64 + mi * 16 + g;
        #pragma unroll
        for (int ni = 0; ni < 4; ++ni) {
            const int n = nblk * 128 + wn * 32 + ni * 8 + tg * 2;
            const float2 bia = *reinterpret_cast<const float2*>(&bias[n]);
            float2 v0 = {acc[mi][ni][0] + bia.x, acc[mi][ni][1] + bia.y};
            float2 v1 = {acc[mi][ni][2] + bia.x, acc[mi][ni][3] + bia.y};
            *reinterpret_cast<float2*>(&Z[(size_t)r0 * H_DIM + n])       = v0;
            *reinterpret_cast<float2*>(&Z[(size_t)(r0 + 8) * H_DIM + n]) = v1;
        }
    }
}

// ---------------- x -> packed split A (layer 0, K padded 144->192) ---------
__global__ __launch_bounds__(32)
void quant_x(const float* __restrict__ x, unsigned char* __restrict__ apack)
{
    const int m = blockIdx.x;
    const int k0 = threadIdx.x * 8;
    if (k0 >= 192) return;
    float v[8];
    if (k0 < IN_RAW) {
        *reinterpret_cast<float4*>(&v[0]) = *reinterpret_cast<const float4*>(&x[(size_t)m * IN_RAW + k0]);
        *reinterpret_cast<float4*>(&v[4]) = *reinterpret_cast<const float4*>(&x[(size_t)m * IN_RAW + k0 + 4]);
    } else {
        #pragma unroll
        for (int i = 0; i < 8; ++i) v[i] = 0.0f;
    }
    const int mblk = m >> 7, row = m & 127, kc = k0 >> 5;
    split_store8(apack + (size_t)(mblk * NC0 + kc) * CHUNK_A,
                 sw64_off(row, (k0 & 31) * 2), v);
}

// ---------------- layer-0 weights -> packed B ------------------------------
__global__ __launch_bounds__(32)
void prep_w0(const float* __restrict__ W0, unsigned char* __restrict__ bpack)
{
    const int n = blockIdx.x;
    const int k0 = threadIdx.x * 8;
    if (k0 >= 192) return;
    float v[8];
    if (k0 < IN_RAW) {
        *reinterpret_cast<float4*>(&v[0]) = *reinterpret_cast<const float4*>(&W0[(size_t)n * IN_RAW + k0]);
        *reinterpret_cast<float4*>(&v[4]) = *reinterpret_cast<const float4*>(&W0[(size_t)n * IN_RAW + k0 + 4]);
    } else {
        #pragma unroll
        for (int i = 0; i < 8; ++i) v[i] = 0.0f;
    }
    const int nblk = n >> 7, row = n & 127, kc = k0 >> 5;
    half_store8(bpack + (size_t)(nblk * NC0 + kc) * CHUNK_B,
                sw64_off(row, (k0 & 31) * 2), v);
}

// ---------------- H-layer weights -> packed B (all 3 layers, once) ---------
__global__ __launch_bounds__(256)
void prep_wH(const float* __restrict__ Ws, unsigned char* __restrict__ bpackH)
{
    const int n = blockIdx.x;
    const int l = blockIdx.y;
    const int k0 = threadIdx.x * 8;
    float v[8];
    const float* wrow = Ws + (size_t)l * H_DIM * H_DIM + (size_t)n * H_DIM + k0;
    *reinterpret_cast<float4*>(&v[0]) = *reinterpret_cast<const float4*>(wrow);
    *reinterpret_cast<float4*>(&v[4]) = *reinterpret_cast<const float4*>(wrow + 4);
    const int nblk = n >> 7, row = n & 127, kc = k0 >> 5;
    unsigned char* base = bpackH + (size_t)l * 16 * NCH * CHUNK_B
                                 + (size_t)(nblk * NCH + kc) * CHUNK_B;
    half_store8(base, sw64_off(row, (k0 & 31) * 2), v);
}

// ---------------- IndRNN scan + stats (fp32, 1 elem/thread) ----------------
__global__ __launch_bounds__(256)
void scan_kernel(const float* __restrict__ Z, const float* __restrict__ u,
                 float* __restrict__ H, float* __restrict__ hlast,
                 float* __restrict__ psum, float* __restrict__ psumsq)
{
    const int j = blockIdx.x * 256 + threadIdx.x;
    const float uh = u[j & (H_DIM - 1)];
    float hc = 0.0f, s = 0.0f, s2 = 0.0f;
    #pragma unroll 4
    for (int t = 0; t < T_DIM; ++t) {
        const float v = Z[(size_t)t * BH + j];
        hc = fmaxf(fmaf(uh, hc, v), 0.0f);
        H[(size_t)t * BH + j] = hc;
        s  += hc;
        s2 = fmaf(hc, hc, s2);
    }
    hlast[j]  = hc;
    psum[j]   = s;
    psumsq[j] = s2;
}

// ---------------- BN stats -> folded affine --------------------------------
__global__ __launch_bounds__(256)
void bn_finalize(const float* __restrict__ psum, const float* __restrict__ psumsq,
                 const float* __restrict__ gamma, const float* __restrict__ beta,
                 float* __restrict__ scale, float* __restrict__ shift)
{
    const int h = blockIdx.x * 256 + threadIdx.x;
    float s = 0.0f, s2 = 0.0f;
    #pragma unroll 8
    for (int b = 0; b < B_DIM; ++b) {
        s  += psum[b * H_DIM + h];
        s2 += psumsq[b * H_DIM + h];
    }
    const float inv_n = 1.0f / (float)(T_DIM * B_DIM);
    const float mean  = s * inv_n;
    const float var   = s2 * inv_n - mean * mean;
    const float rstd  = rsqrtf(var + BN_EPS);
    const float sc    = gamma[h] * rstd;
    scale[h] = sc;
    shift[h] = fmaf(-mean, sc, beta[h]);
}

// ---------------- BN(h) -> packed split A ----------------------------------
__global__ __launch_bounds__(256)
void quant_h(const float* __restrict__ H, const float* __restrict__ scale,
             const float* __restrict__ shift, unsigned char* __restrict__ apack)
{
    const int m = blockIdx.x;
    const int k0 = threadIdx.x * 8;
    float v[8], sc[8], sh[8];
    const float* hrow = H + (size_t)m * H_DIM + k0;
    *reinterpret_cast<float4*>(&v[0])  = *reinterpret_cast<const float4*>(hrow);
    *reinterpret_cast<float4*>(&v[4])  = *reinterpret_cast<const float4*>(hrow + 4);
    *reinterpret_cast<float4*>(&sc[0]) = *reinterpret_cast<const float4*>(&scale[k0]);
    *reinterpret_cast<float4*>(&sc[4]) = *reinterpret_cast<const float4*>(&scale[k0 + 4]);
    *reinterpret_cast<float4*>(&sh[0]) = *reinterpret_cast<const float4*>(&shift[k0]);
    *reinterpret_cast<float4*>(&sh[4]) = *reinterpret_cast<const float4*>(&shift[k0 + 4]);
    #pragma unroll
    for (int i = 0; i < 8; ++i) v[i] = fmaf(v[i], sc[i], sh[i]);
    const int mblk = m >> 7, row = m & 127, kc = k0 >> 5;
    split_store8(apack + (size_t)(mblk * NCH + kc) * CHUNK_A,
                 sw64_off(row, (k0 & 31) * 2), v);
}

// ---------------- final projection -----------------------------------------
__global__ __launch_bounds__(256)
void final_proj(const float* __restrict__ Hlast,
                const float* __restrict__ scale, const float* __restrict__ shift,
                const float* __restrict__ Wl, const float* __restrict__ bl,
                float* __restrict__ out)
{
    const int b = blockIdx.x, c = blockIdx.y;
    __shared__ float red[256];
    float s = 0.0f;
    for (int h = threadIdx.x; h < H_DIM; h += 256) {
        const float hn = fmaf(Hlast[b * H_DIM + h], scale[h], shift[h]);
        s = fmaf(hn, Wl[c * H_DIM + h], s);
    }
    red[threadIdx.x] = s;
    __syncthreads();
    for (int o = 128; o > 0; o >>= 1) {
        if (threadIdx.x < o) red[threadIdx.x] += red[threadIdx.x + o];
        __syncthreads();
    }
    if (threadIdx.x == 0) out[b * C_DIM + c] = red[0] + bl[c];
}

// ---------------- launcher --------------------------------------------------
extern "C" void kernel_launch(void* const* d_in, const int* in_sizes, int n_in,
                              void* d_out, int out_size)
{
    const float* x      = (const float*)d_in[0];
    const float* W0     = (const float*)d_in[1];
    const float* Ws     = (const float*)d_in[2];
    const float* bs     = (const float*)d_in[3];
    const float* us     = (const float*)d_in[4];
    const float* gammas = (const float*)d_in[5];
    const float* betas  = (const float*)d_in[6];
    const float* Wlast  = (const float*)d_in[7];
    const float* blast  = (const float*)d_in[8];
    float* out = (float*)d_out;

    unsigned char *apack, *bpack0, *bpackH;
    float *z, *h, *psum, *psumsq, *scale, *shift, *hlast;
    cudaGetSymbolAddress((void**)&apack,  g_apack);
    cudaGetSymbolAddress((void**)&bpack0, g_bpack0);
    cudaGetSymbolAddress((void**)&bpackH, g_bpackH);
    cudaGetSymbolAddress((void**)&z,      g_z);
    cudaGetSymbolAddress((void**)&h,      g_h);
    cudaGetSymbolAddress((void**)&psum,   g_psum);
    cudaGetSymbolAddress((void**)&psumsq, g_psumsq);
    cudaGetSymbolAddress((void**)&scale,  g_scale);
    cudaGetSymbolAddress((void**)&shift,  g_shift);
    cudaGetSymbolAddress((void**)&hlast,  g_hlast);

    cudaFuncSetAttribute(gemm_mma, cudaFuncAttributeMaxDynamicSharedMemorySize, DSMEM_BYTES);

    const dim3 ggrid(H_DIM / 128, MTOT / 128);   // 16 x 64 = 1024 CTAs, 2/SM

    quant_x<<<MTOT, 32>>>(x, apack);
    prep_w0<<<H_DIM, 32>>>(W0, bpack0);
    prep_wH<<<dim3(H_DIM, 3), 256>>>(Ws, bpackH);

    gemm_mma<<<ggrid, 256, DSMEM_BYTES>>>(apack, bpack0, bs, z, NC0);
    scan_kernel<<<BH / 256, 256>>>(z, us, h, hlast, psum, psumsq);
    bn_finalize<<<H_DIM / 256, 256>>>(psum, psumsq, gammas, betas, scale, shift);

    for (int l = 1; l < 4; ++l) {
        quant_h<<<MTOT, 256>>>(h, scale, shift, apack);
        gemm_mma<<<ggrid, 256, DSMEM_BYTES>>>(apack,
                                              bpackH + (size_t)(l - 1) * 16 * NCH * CHUNK_B,
                                              bs + l * H_DIM, z, NCH);
        scan_kernel<<<BH / 256, 256>>>(z, us + l * H_DIM, h, hlast, psum, psumsq);
        bn_finalize<<<H_DIM / 256, 256>>>(psum, psumsq, gammas + l * H_DIM,
                                          betas + l * H_DIM, scale, shift);
    }

    final_proj<<<dim3(B_DIM, C_DIM), 256>>>(hlast, scale, shift, Wlast, blast, out);
}

// round 10
// speedup vs baseline: 1.5400x; 1.0465x over previous
#include <cuda_runtime.h>
#include <cuda_fp16.h>
#include <cstdint>

#define T_DIM  128
#define B_DIM  64
#define IN_RAW 144
#define H_DIM  2048
#define C_DIM  10
#define BN_EPS 1e-5f
#define MTOT   (T_DIM*B_DIM)   // 8192
#define BH     (B_DIM*H_DIM)   // 131072
#define NC0    6               // layer0 K=144 padded to 192 = 6 chunks of 32
#define NCH    64              // 2048/32

// GEMM tile: BM=BN=128, KC=32 fp16 (64B rows, SW64); 256 thr (8 warps, 2x4, 64x32)
#define CHUNK_A 16384          // A: hi+lo fp16 planes (8KB each)
#define CHUNK_B 8192           // B: single fp16 plane
#define STAGE_BYTES (CHUNK_A + CHUNK_B)    // 24576
#define NSTAGE 4
#define DSMEM_BYTES (NSTAGE*STAGE_BYTES)   // 98304/CTA -> 2 CTAs = 192KB

// ---------------- scratch (allocation-free device globals) -----------------
__device__ __align__(128) unsigned char g_apack[64u*64u*CHUNK_A];     // 64MB
__device__ __align__(128) unsigned char g_bpack0[16u*NC0*CHUNK_B];    // 0.75MB
__device__ __align__(128) unsigned char g_bpackW[16u*NCH*CHUNK_B];    // 8MB, per-layer
__device__ float g_z[MTOT*H_DIM];       // 64MB
__device__ float g_biasadj[H_DIM];
__device__ float g_psum[BH];
__device__ float g_psumsq[BH];
__device__ float g_scale[H_DIM];
__device__ float g_shift[H_DIM];
__device__ float g_hlast[BH];

// ---------------- PTX helpers ----------------
__device__ __forceinline__ uint32_t smem_u32(const void* p) {
    uint32_t a;
    asm("{ .reg .u64 t; cvta.to.shared.u64 t, %1; cvt.u32.u64 %0, t; }" : "=r"(a) : "l"(p));
    return a;
}
__device__ __forceinline__ void bulk_g2s(uint32_t dst, const void* src,
                                         uint32_t bytes, uint32_t mbar) {
    asm volatile(
        "cp.async.bulk.shared::cluster.global.mbarrier::complete_tx::bytes [%0], [%1], %2, [%3];"
        :: "r"(dst), "l"(src), "r"(bytes), "r"(mbar) : "memory");
}
#define MBAR_INIT(a, c) asm volatile("mbarrier.init.shared.b64 [%0], %1;" :: "r"(a), "r"(c) : "memory")
#define MBAR_EXPECT_TX(a, b) asm volatile("mbarrier.arrive.expect_tx.shared.b64 _, [%0], %1;" :: "r"(a), "r"(b) : "memory")
#define FENCE_ASYNC() asm volatile("fence.proxy.async.shared::cta;" ::: "memory")
#define MBAR_WAIT(a, ph) do { \
    uint32_t _done; \
    asm volatile("{\n\t.reg .pred p;\n\tmbarrier.try_wait.parity.acquire.cta.shared::cta.b64 p, [%1], %2;\n\tselp.b32 %0,1,0,p;\n\t}" \
        : "=r"(_done) : "r"(a), "r"(ph) : "memory"); \
    if (!_done) { \
        asm volatile("{\n\t.reg .pred P1;\n\tWL_%=:\n\tmbarrier.try_wait.parity.acquire.cta.shared::cta.b64 P1, [%0], %1, 0x989680;\n\t@P1 bra.uni WD_%=;\n\tbra.uni WL_%=;\n\tWD_%=:\n\t}" \
            :: "r"(a), "r"(ph) : "memory"); \
    } \
} while (0)

__device__ __forceinline__ void ldsm4(uint32_t r[4], uint32_t addr) {
    asm volatile("ldmatrix.sync.aligned.m8n8.x4.shared.b16 {%0,%1,%2,%3}, [%4];"
        : "=r"(r[0]), "=r"(r[1]), "=r"(r[2]), "=r"(r[3]) : "r"(addr));
}
__device__ __forceinline__ void mma16816(float c[4], const uint32_t a[4],
                                         uint32_t b0, uint32_t b1) {
    asm volatile(
        "mma.sync.aligned.m16n8k16.row.col.f32.f16.f16.f32 "
        "{%0,%1,%2,%3}, {%4,%5,%6,%7}, {%8,%9}, {%0,%1,%2,%3};"
        : "+f"(c[0]), "+f"(c[1]), "+f"(c[2]), "+f"(c[3])
        : "r"(a[0]), "r"(a[1]), "r"(a[2]), "r"(a[3]), "r"(b0), "r"(b1));
}

// SW64 swizzled byte offset inside one 128-row x 64B plane
__device__ __forceinline__ uint32_t sw64_off(int row, int colBytes) {
    return (uint32_t)row * 64 + (((uint32_t)colBytes) ^ (uint32_t)(((row >> 1) & 3) << 4));
}

// A: split 8 fp32 -> fp16 hi/lo planes (8KB apart)
__device__ __forceinline__ void split_store8(unsigned char* base, uint32_t off,
                                             const float v[8]) {
    union { uint4 q; unsigned short us[8]; } Hq, Lq;
    #pragma unroll
    for (int i = 0; i < 8; ++i) {
        __half h = __float2half(v[i]);
        Hq.us[i] = __half_as_ushort(h);
        Lq.us[i] = __half_as_ushort(__float2half(v[i] - __half2float(h)));
    }
    *reinterpret_cast<uint4*>(base + off)        = Hq.q;
    *reinterpret_cast<uint4*>(base + off + 8192) = Lq.q;
}
// B: 8 fp32 -> single fp16 plane
__device__ __forceinline__ void half_store8(unsigned char* base, uint32_t off,
                                            const float v[8]) {
    union { uint4 q; unsigned short us[8]; } Hq;
    #pragma unroll
    for (int i = 0; i < 8; ++i) Hq.us[i] = __half_as_ushort(__float2half(v[i]));
    *reinterpret_cast<uint4*>(base + off) = Hq.q;
}

// ---------------- GEMM: Z = A@W^T + bias (fp16 2-product split) ------------
__global__ __launch_bounds__(256, 2)
void gemm_mma(const unsigned char* __restrict__ apack,
              const unsigned char* __restrict__ bpack,
              const float* __restrict__ bias, float* __restrict__ Z, int NC)
{
    extern __shared__ unsigned char dyn[];
    __shared__ __align__(8) uint64_t mbar_s[NSTAGE];
    const uint32_t sb = smem_u32(dyn);
    const uint32_t mb = smem_u32(mbar_s);

    const int tid  = threadIdx.x;
    const int lane = tid & 31;
    const int wid  = tid >> 5;
    const int wm   = wid >> 2;
    const int wn   = wid & 3;
    const int nblk = blockIdx.x;
    const int mblk = blockIdx.y;

    const unsigned char* aSrc = apack + (size_t)mblk * NC * CHUNK_A;
    const unsigned char* bSrc = bpack + (size_t)nblk * NC * CHUNK_B;

    if (tid == 0) {
        #pragma unroll
        for (int s = 0; s < NSTAGE; ++s) MBAR_INIT(mb + 8 * s, 1);
        FENCE_ASYNC();
    }
    __syncthreads();
    if (tid == 0) {
        #pragma unroll
        for (int s = 0; s < NSTAGE; ++s) {
            if (s < NC) {
                MBAR_EXPECT_TX(mb + 8 * s, STAGE_BYTES);
                bulk_g2s(sb + s * STAGE_BYTES,           aSrc + (size_t)s * CHUNK_A, CHUNK_A, mb + 8 * s);
                bulk_g2s(sb + s * STAGE_BYTES + CHUNK_A, bSrc + (size_t)s * CHUNK_B, CHUNK_B, mb + 8 * s);
            }
        }
    }

    const int rowA  = wm * 64 + (lane & 15);
    const int rowB  = wn * 32 + ((lane >> 4) << 3) + (lane & 7);
    const uint32_t xorA = (uint32_t)(((rowA >> 1) & 3) << 4);
    const uint32_t xorB = (uint32_t)(((rowB >> 1) & 3) << 4);
    const uint32_t colA0 = (uint32_t)((lane >> 4) * 16);
    const uint32_t colB0 = (uint32_t)(((lane >> 3) & 1) * 16);
    const uint32_t baseA = (uint32_t)rowA * 64;
    const uint32_t baseB = (uint32_t)rowB * 64;

    float acc[4][4][4];
    #pragma unroll
    for (int i = 0; i < 4; ++i)
        #pragma unroll
        for (int j = 0; j < 4; ++j)
            #pragma unroll
            for (int q = 0; q < 4; ++q) acc[i][j][q] = 0.0f;

    int ph[NSTAGE] = {0, 0, 0, 0};
    for (int c = 0; c < NC; ++c) {
        const int s = c & (NSTAGE - 1);
        MBAR_WAIT(mb + 8 * s, ph[s]);
        ph[s] ^= 1;
        const uint32_t st = sb + s * STAGE_BYTES;

        #pragma unroll
        for (int kk = 0; kk < 2; ++kk) {
            const uint32_t cA = (uint32_t)(kk * 32 + colA0) ^ xorA;
            const uint32_t cB = (uint32_t)(kk * 32 + colB0) ^ xorB;
            uint32_t ah[4][4], al[4][4], bb[2][4];
            #pragma unroll
            for (int mi = 0; mi < 4; ++mi) {
                const uint32_t ra = baseA + (uint32_t)mi * 1024;
                ldsm4(ah[mi], st + ra + cA);
                ldsm4(al[mi], st + 8192 + ra + cA);
            }
            #pragma unroll
            for (int nj = 0; nj < 2; ++nj)
                ldsm4(bb[nj], st + CHUNK_A + baseB + (uint32_t)nj * 1024 + cB);
            #pragma unroll
            for (int nj = 0; nj < 2; ++nj) {
                #pragma unroll
                for (int mi = 0; mi < 4; ++mi) {
                    mma16816(acc[mi][nj*2],   ah[mi], bb[nj][0], bb[nj][1]);
                    mma16816(acc[mi][nj*2+1], ah[mi], bb[nj][2], bb[nj][3]);
                }
                #pragma unroll
                for (int mi = 0; mi < 4; ++mi) {
                    mma16816(acc[mi][nj*2],   al[mi], bb[nj][0], bb[nj][1]);
                    mma16816(acc[mi][nj*2+1], al[mi], bb[nj][2], bb[nj][3]);
                }
            }
        }
        __syncthreads();
        if (c + NSTAGE < NC && tid == 0) {
            MBAR_EXPECT_TX(mb + 8 * s, STAGE_BYTES);
            bulk_g2s(st,           aSrc + (size_t)(c + NSTAGE) * CHUNK_A, CHUNK_A, mb + 8 * s);
            bulk_g2s(st + CHUNK_A, bSrc + (size_t)(c + NSTAGE) * CHUNK_B, CHUNK_B, mb + 8 * s);
        }
    }

    const int g  = lane >> 2;
    const int tg = lane & 3;
    #pragma unroll
    for (int mi = 0; mi < 4; ++mi) {
        const int r0 = mblk * 128 + wm * 64 + mi * 16 + g;
        #pragma unroll
        for (int ni = 0; ni < 4; ++ni) {
            const int n = nblk * 128 + wn * 32 + ni * 8 + tg * 2;
            const float2 bia = *reinterpret_cast<const float2*>(&bias[n]);
            float2 v0 = {acc[mi][ni][0] + bia.x, acc[mi][ni][1] + bia.y};
            float2 v1 = {acc[mi][ni][2] + bia.x, acc[mi][ni][3] + bia.y};
            *reinterpret_cast<float2*>(&Z[(size_t)r0 * H_DIM + n])       = v0;
            *reinterpret_cast<float2*>(&Z[(size_t)(r0 + 8) * H_DIM + n]) = v1;
        }
    }
}

// ---------------- x -> packed split A (layer 0, K padded 144->192) ---------
__global__ __launch_bounds__(32)
void quant_x(const float* __restrict__ x, unsigned char* __restrict__ apack)
{
    const int m = blockIdx.x;
    const int k0 = threadIdx.x * 8;
    if (k0 >= 192) return;
    float v[8];
    if (k0 < IN_RAW) {
        *reinterpret_cast<float4*>(&v[0]) = *reinterpret_cast<const float4*>(&x[(size_t)m * IN_RAW + k0]);
        *reinterpret_cast<float4*>(&v[4]) = *reinterpret_cast<const float4*>(&x[(size_t)m * IN_RAW + k0 + 4]);
    } else {
        #pragma unroll
        for (int i = 0; i < 8; ++i) v[i] = 0.0f;
    }
    const int mblk = m >> 7, row = m & 127, kc = k0 >> 5;
    split_store8(apack + (size_t)(mblk * NC0 + kc) * CHUNK_A,
                 sw64_off(row, (k0 & 31) * 2), v);
}

// ---------------- layer-0 weights -> packed B (raw, bias = bs row 0) -------
__global__ __launch_bounds__(32)
void prep_w0(const float* __restrict__ W0, unsigned char* __restrict__ bpack)
{
    const int n = blockIdx.x;
    const int k0 = threadIdx.x * 8;
    if (k0 >= 192) return;
    float v[8];
    if (k0 < IN_RAW) {
        *reinterpret_cast<float4*>(&v[0]) = *reinterpret_cast<const float4*>(&W0[(size_t)n * IN_RAW + k0]);
        *reinterpret_cast<float4*>(&v[4]) = *reinterpret_cast<const float4*>(&W0[(size_t)n * IN_RAW + k0 + 4]);
    } else {
        #pragma unroll
        for (int i = 0; i < 8; ++i) v[i] = 0.0f;
    }
    const int nblk = n >> 7, row = n & 127, kc = k0 >> 5;
    half_store8(bpack + (size_t)(nblk * NC0 + kc) * CHUNK_B,
                sw64_off(row, (k0 & 31) * 2), v);
}

// ---------------- per-layer weight prep: fold BN scale into W, shift into bias
// W'[n,k] = W[n,k]*scale[k]; biasadj[n] = b[n] + sum_k shift[k]*W[n,k]
__global__ __launch_bounds__(256)
void prep_w(const float* __restrict__ W, const float* __restrict__ scale,
            const float* __restrict__ shift, const float* __restrict__ bias_in,
            unsigned char* __restrict__ bpack, float* __restrict__ biasadj)
{
    __shared__ float red[256];
    const int n = blockIdx.x;
    const int tid = threadIdx.x;
    const int k0 = tid * 8;

    float w[8], v[8], sc[8], sh[8];
    const float* wrow = W + (size_t)n * H_DIM + k0;
    *reinterpret_cast<float4*>(&w[0])  = *reinterpret_cast<const float4*>(wrow);
    *reinterpret_cast<float4*>(&w[4])  = *reinterpret_cast<const float4*>(wrow + 4);
    *reinterpret_cast<float4*>(&sc[0]) = *reinterpret_cast<const float4*>(&scale[k0]);
    *reinterpret_cast<float4*>(&sc[4]) = *reinterpret_cast<const float4*>(&scale[k0 + 4]);
    *reinterpret_cast<float4*>(&sh[0]) = *reinterpret_cast<const float4*>(&shift[k0]);
    *reinterpret_cast<float4*>(&sh[4]) = *reinterpret_cast<const float4*>(&shift[k0 + 4]);

    float s = 0.0f;
    #pragma unroll
    for (int i = 0; i < 8; ++i) {
        v[i] = w[i] * sc[i];
        s = fmaf(sh[i], w[i], s);
    }
    const int nblk = n >> 7, row = n & 127, kc = k0 >> 5;
    half_store8(bpack + (size_t)(nblk * NCH + kc) * CHUNK_B,
                sw64_off(row, (k0 & 31) * 2), v);

    red[tid] = s;
    __syncthreads();
    for (int o = 128; o > 0; o >>= 1) {
        if (tid < o) red[tid] += red[tid + o];
        __syncthreads();
    }
    if (tid == 0) biasadj[n] = bias_in[n] + red[0];
}

// ---------------- IndRNN scan: fp32, 2 h/thread; writes raw-h A planes -----
__global__ __launch_bounds__(256)
void scan_pack(const float* __restrict__ Z, const float* __restrict__ u,
               unsigned char* __restrict__ apack, float* __restrict__ hlast,
               float* __restrict__ psum, float* __restrict__ psumsq, int writeA)
{
    const int j2 = blockIdx.x * 256 + threadIdx.x;   // 0..65535 (h-pair index)
    const int b  = j2 >> 10;                         // 0..63
    const int h0 = (j2 & 1023) * 2;                  // even h
    const int kc = h0 >> 5;
    const int colB = (h0 & 31) * 2;                  // byte col, 4-aligned

    const float2 uh = *reinterpret_cast<const float2*>(&u[h0]);
    float hc0 = 0.0f, hc1 = 0.0f, s0 = 0.0f, s1 = 0.0f, q0 = 0.0f, q1 = 0.0f;

    const float* zp = Z + (size_t)b * H_DIM + h0;
    unsigned char* chunkBase = apack + (size_t)kc * CHUNK_A;

    #pragma unroll 4
    for (int t = 0; t < T_DIM; ++t) {
        const float2 zv = *reinterpret_cast<const float2*>(zp + (size_t)t * BH);
        hc0 = fmaxf(fmaf(uh.x, hc0, zv.x), 0.0f);
        hc1 = fmaxf(fmaf(uh.y, hc1, zv.y), 0.0f);
        s0 += hc0; s1 += hc1;
        q0 = fmaf(hc0, hc0, q0); q1 = fmaf(hc1, hc1, q1);
        if (writeA) {
            const int m = t * B_DIM + b;
            const int mblk = m >> 7, row = m & 127;
            const __half h0h = __float2half(hc0);
            const __half h1h = __float2half(hc1);
            const uint32_t hi = (uint32_t)__half_as_ushort(h0h)
                              | ((uint32_t)__half_as_ushort(h1h) << 16);
            const uint32_t lo = (uint32_t)__half_as_ushort(__float2half(hc0 - __half2float(h0h)))
                              | ((uint32_t)__half_as_ushort(__float2half(hc1 - __half2float(h1h))) << 16);
            unsigned char* d = chunkBase + (size_t)mblk * (NCH * CHUNK_A)
                             + sw64_off(row, colB);
            *reinterpret_cast<uint32_t*>(d)        = hi;
            *reinterpret_cast<uint32_t*>(d + 8192) = lo;
        }
    }
    const int j = b * H_DIM + h0;
    *reinterpret_cast<float2*>(&hlast[j])  = make_float2(hc0, hc1);
    *reinterpret_cast<float2*>(&psum[j])   = make_float2(s0, s1);
    *reinterpret_cast<float2*>(&psumsq[j]) = make_float2(q0, q1);
}

// ---------------- BN stats -> folded affine --------------------------------
__global__ __launch_bounds__(256)
void bn_finalize(const float* __restrict__ psum, const float* __restrict__ psumsq,
                 const float* __restrict__ gamma, const float* __restrict__ beta,
                 float* __restrict__ scale, float* __restrict__ shift)
{
    const int h = blockIdx.x * 256 + threadIdx.x;
    float s = 0.0f, s2 = 0.0f;
    #pragma unroll 8
    for (int b = 0; b < B_DIM; ++b) {
        s  += psum[b * H_DIM + h];
        s2 += psumsq[b * H_DIM + h];
    }
    const float inv_n = 1.0f / (float)(T_DIM * B_DIM);
    const float mean  = s * inv_n;
    const float var   = s2 * inv_n - mean * mean;
    const float rstd  = rsqrtf(var + BN_EPS);
    const float sc    = gamma[h] * rstd;
    scale[h] = sc;
    shift[h] = fmaf(-mean, sc, beta[h]);
}

// ---------------- final projection -----------------------------------------
__global__ __launch_bounds__(256)
void final_proj(const float* __restrict__ Hlast,
                const float* __restrict__ scale, const float* __restrict__ shift,
                const float* __restrict__ Wl, const float* __restrict__ bl,
                float* __restrict__ out)
{
    const int b = blockIdx.x, c = blockIdx.y;
    __shared__ float red[256];
    float s = 0.0f;
    for (int h = threadIdx.x; h < H_DIM; h += 256) {
        const float hn = fmaf(Hlast[b * H_DIM + h], scale[h], shift[h]);
        s = fmaf(hn, Wl[c * H_DIM + h], s);
    }
    red[threadIdx.x] = s;
    __syncthreads();
    for (int o = 128; o > 0; o >>= 1) {
        if (threadIdx.x < o) red[threadIdx.x] += red[threadIdx.x + o];
        __syncthreads();
    }
    if (threadIdx.x == 0) out[b * C_DIM + c] = red[0] + bl[c];
}

// ---------------- launcher --------------------------------------------------
extern "C" void kernel_launch(void* const* d_in, const int* in_sizes, int n_in,
                              void* d_out, int out_size)
{
    const float* x      = (const float*)d_in[0];
    const float* W0     = (const float*)d_in[1];
    const float* Ws     = (const float*)d_in[2];
    const float* bs     = (const float*)d_in[3];
    const float* us     = (const float*)d_in[4];
    const float* gammas = (const float*)d_in[5];
    const float* betas  = (const float*)d_in[6];
    const float* Wlast  = (const float*)d_in[7];
    const float* blast  = (const float*)d_in[8];
    float* out = (float*)d_out;

    unsigned char *apack, *bpack0, *bpackW;
    float *z, *biasadj, *psum, *psumsq, *scale, *shift, *hlast;
    cudaGetSymbolAddress((void**)&apack,   g_apack);
    cudaGetSymbolAddress((void**)&bpack0,  g_bpack0);
    cudaGetSymbolAddress((void**)&bpackW,  g_bpackW);
    cudaGetSymbolAddress((void**)&z,       g_z);
    cudaGetSymbolAddress((void**)&biasadj, g_biasadj);
    cudaGetSymbolAddress((void**)&psum,    g_psum);
    cudaGetSymbolAddress((void**)&psumsq,  g_psumsq);
    cudaGetSymbolAddress((void**)&scale,   g_scale);
    cudaGetSymbolAddress((void**)&shift,   g_shift);
    cudaGetSymbolAddress((void**)&hlast,   g_hlast);

    cudaFuncSetAttribute(gemm_mma, cudaFuncAttributeMaxDynamicSharedMemorySize, DSMEM_BYTES);

    const dim3 ggrid(H_DIM / 128, MTOT / 128);   // 16 x 64 = 1024 CTAs, 2/SM
    const int scanBlocks = (BH / 2) / 256;       // 256

    // ---- layer 0: A = x (packed), B = raw W0, bias = bs[0] ----
    quant_x<<<MTOT, 32>>>(x, apack);
    prep_w0<<<H_DIM, 32>>>(W0, bpack0);
    gemm_mma<<<ggrid, 256, DSMEM_BYTES>>>(apack, bpack0, bs, z, NC0);
    scan_pack<<<scanBlocks, 256>>>(z, us, apack, hlast, psum, psumsq, 1);
    bn_finalize<<<H_DIM / 256, 256>>>(psum, psumsq, gammas, betas, scale, shift);

    // ---- layers 1..3: B = scale-folded W, bias = b + shift.W ----
    for (int l = 1; l < 4; ++l) {
        prep_w<<<H_DIM, 256>>>(Ws + (size_t)(l - 1) * H_DIM * H_DIM, scale, shift,
                               bs + l * H_DIM, bpackW, biasadj);
        gemm_mma<<<ggrid, 256, DSMEM_BYTES>>>(apack, bpackW, biasadj, z, NCH);
        scan_pack<<<scanBlocks, 256>>>(z, us + l * H_DIM, apack, hlast, psum, psumsq,
                                       (l < 3) ? 1 : 0);
        bn_finalize<<<H_DIM / 256, 256>>>(psum, psumsq, gammas + l * H_DIM,
                                          betas + l * H_DIM, scale, shift);
    }

    final_proj<<<dim3(B_DIM, C_DIM), 256>>>(hlast, scale, shift, Wlast, blast, out);
}

// round 12
// speedup vs baseline: 1.6397x; 1.0647x over previous
#include <cuda_runtime.h>
#include <cuda_fp16.h>
#include <cstdint>

#define T_DIM  128
#define B_DIM  64
#define IN_RAW 144
#define H_DIM  2048
#define C_DIM  10
#define BN_EPS 1e-5f
#define MTOT   (T_DIM*B_DIM)   // 8192
#define BH     (B_DIM*H_DIM)   // 131072
#define NC0    6               // layer0 K=144 padded to 192 = 6 chunks of 32
#define NCH    64              // 2048/32

// GEMM tile: BM=BN=128, KC=32 fp16 (64B rows, SW64); 256 thr (8 warps, 2x4, 64x32)
#define CHUNK_A 16384          // A: hi+lo fp16 planes (8KB each)
#define CHUNK_B 8192           // B: single fp16 plane
#define STAGE_BYTES (CHUNK_A + CHUNK_B)    // 24576
#define NSTAGE 4
#define DSMEM_BYTES (NSTAGE*STAGE_BYTES)   // 98304/CTA -> 2 CTAs = 192KB

// ---------------- scratch (allocation-free device globals) -----------------
__device__ __align__(128) unsigned char g_apack[64u*64u*CHUNK_A];     // 64MB
__device__ __align__(128) unsigned char g_bpack0[16u*NC0*CHUNK_B];    // 0.75MB
__device__ __align__(128) unsigned char g_bpackW[16u*NCH*CHUNK_B];    // 8MB, per-layer
__device__ __half g_z[MTOT*H_DIM];      // 32MB (fp16 pre-activation)
__device__ float g_biasadj[H_DIM];
__device__ float g_psum[BH];
__device__ float g_psumsq[BH];
__device__ float g_scale[H_DIM];
__device__ float g_shift[H_DIM];
__device__ float g_hlast[BH];

// ---------------- PTX helpers ----------------
__device__ __forceinline__ uint32_t smem_u32(const void* p) {
    uint32_t a;
    asm("{ .reg .u64 t; cvta.to.shared.u64 t, %1; cvt.u32.u64 %0, t; }" : "=r"(a) : "l"(p));
    return a;
}
__device__ __forceinline__ void bulk_g2s(uint32_t dst, const void* src,
                                         uint32_t bytes, uint32_t mbar) {
    asm volatile(
        "cp.async.bulk.shared::cluster.global.mbarrier::complete_tx::bytes [%0], [%1], %2, [%3];"
        :: "r"(dst), "l"(src), "r"(bytes), "r"(mbar) : "memory");
}
#define MBAR_INIT(a, c) asm volatile("mbarrier.init.shared.b64 [%0], %1;" :: "r"(a), "r"(c) : "memory")
#define MBAR_EXPECT_TX(a, b) asm volatile("mbarrier.arrive.expect_tx.shared.b64 _, [%0], %1;" :: "r"(a), "r"(b) : "memory")
#define FENCE_ASYNC() asm volatile("fence.proxy.async.shared::cta;" ::: "memory")
#define MBAR_WAIT(a, ph) do { \
    uint32_t _done; \
    asm volatile("{\n\t.reg .pred p;\n\tmbarrier.try_wait.parity.acquire.cta.shared::cta.b64 p, [%1], %2;\n\tselp.b32 %0,1,0,p;\n\t}" \
        : "=r"(_done) : "r"(a), "r"(ph) : "memory"); \
    if (!_done) { \
        asm volatile("{\n\t.reg .pred P1;\n\tWL_%=:\n\tmbarrier.try_wait.parity.acquire.cta.shared::cta.b64 P1, [%0], %1, 0x989680;\n\t@P1 bra.uni WD_%=;\n\tbra.uni WL_%=;\n\tWD_%=:\n\t}" \
            :: "r"(a), "r"(ph) : "memory"); \
    } \
} while (0)

__device__ __forceinline__ void ldsm4(uint32_t r[4], uint32_t addr) {
    asm volatile("ldmatrix.sync.aligned.m8n8.x4.shared.b16 {%0,%1,%2,%3}, [%4];"
        : "=r"(r[0]), "=r"(r[1]), "=r"(r[2]), "=r"(r[3]) : "r"(addr));
}
__device__ __forceinline__ void mma16816(float c[4], const uint32_t a[4],
                                         uint32_t b0, uint32_t b1) {
    asm volatile(
        "mma.sync.aligned.m16n8k16.row.col.f32.f16.f16.f32 "
        "{%0,%1,%2,%3}, {%4,%5,%6,%7}, {%8,%9}, {%0,%1,%2,%3};"
        : "+f"(c[0]), "+f"(c[1]), "+f"(c[2]), "+f"(c[3])
        : "r"(a[0]), "r"(a[1]), "r"(a[2]), "r"(a[3]), "r"(b0), "r"(b1));
}

// SW64 swizzled byte offset inside one 128-row x 64B plane
__device__ __forceinline__ uint32_t sw64_off(int row, int colBytes) {
    return (uint32_t)row * 64 + (((uint32_t)colBytes) ^ (uint32_t)(((row >> 1) & 3) << 4));
}

// A: split 8 fp32 -> fp16 hi/lo planes (8KB apart)
__device__ __forceinline__ void split_store8(unsigned char* base, uint32_t off,
                                             const float v[8]) {
    union { uint4 q; unsigned short us[8]; } Hq, Lq;
    #pragma unroll
    for (int i = 0; i < 8; ++i) {
        __half h = __float2half(v[i]);
        Hq.us[i] = __half_as_ushort(h);
        Lq.us[i] = __half_as_ushort(__float2half(v[i] - __half2float(h)));
    }
    *reinterpret_cast<uint4*>(base + off)        = Hq.q;
    *reinterpret_cast<uint4*>(base + off + 8192) = Lq.q;
}
// B: 8 fp32 -> single fp16 plane
__device__ __forceinline__ void half_store8(unsigned char* base, uint32_t off,
                                            const float v[8]) {
    union { uint4 q; unsigned short us[8]; } Hq;
    #pragma unroll
    for (int i = 0; i < 8; ++i) Hq.us[i] = __half_as_ushort(__float2half(v[i]));
    *reinterpret_cast<uint4*>(base + off) = Hq.q;
}

// ---------------- GEMM: Z = A@W^T + bias (fp16 2-product split) ------------
__global__ __launch_bounds__(256, 2)
void gemm_mma(const unsigned char* __restrict__ apack,
              const unsigned char* __restrict__ bpack,
              const float* __restrict__ bias, __half* __restrict__ Z, int NC)
{
    extern __shared__ unsigned char dyn[];
    __shared__ __align__(8) uint64_t mbar_s[NSTAGE];
    const uint32_t sb = smem_u32(dyn);
    const uint32_t mb = smem_u32(mbar_s);

    const int tid  = threadIdx.x;
    const int lane = tid & 31;
    const int wid  = tid >> 5;
    const int wm   = wid >> 2;
    const int wn   = wid & 3;
    const int nblk = blockIdx.x;
    const int mblk = blockIdx.y;

    const unsigned char* aSrc = apack + (size_t)mblk * NC * CHUNK_A;
    const unsigned char* bSrc = bpack + (size_t)nblk * NC * CHUNK_B;

    if (tid == 0) {
        #pragma unroll
        for (int s = 0; s < NSTAGE; ++s) MBAR_INIT(mb + 8 * s, 1);
        FENCE_ASYNC();
    }
    __syncthreads();
    if (tid == 0) {
        #pragma unroll
        for (int s = 0; s < NSTAGE; ++s) {
            if (s < NC) {
                MBAR_EXPECT_TX(mb + 8 * s, STAGE_BYTES);
                bulk_g2s(sb + s * STAGE_BYTES,           aSrc + (size_t)s * CHUNK_A, CHUNK_A, mb + 8 * s);
                bulk_g2s(sb + s * STAGE_BYTES + CHUNK_A, bSrc + (size_t)s * CHUNK_B, CHUNK_B, mb + 8 * s);
            }
        }
    }

    const int rowA  = wm * 64 + (lane & 15);
    const int rowB  = wn * 32 + ((lane >> 4) << 3) + (lane & 7);
    const uint32_t xorA = (uint32_t)(((rowA >> 1) & 3) << 4);
    const uint32_t xorB = (uint32_t)(((rowB >> 1) & 3) << 4);
    const uint32_t colA0 = (uint32_t)((lane >> 4) * 16);
    const uint32_t colB0 = (uint32_t)(((lane >> 3) & 1) * 16);
    const uint32_t baseA = (uint32_t)rowA * 64;
    const uint32_t baseB = (uint32_t)rowB * 64;

    float acc[4][4][4];
    #pragma unroll
    for (int i = 0; i < 4; ++i)
        #pragma unroll
        for (int j = 0; j < 4; ++j)
            #pragma unroll
            for (int q = 0; q < 4; ++q) acc[i][j][q] = 0.0f;

    int ph[NSTAGE] = {0, 0, 0, 0};
    for (int c = 0; c < NC; ++c) {
        const int s = c & (NSTAGE - 1);
        MBAR_WAIT(mb + 8 * s, ph[s]);
        ph[s] ^= 1;
        const uint32_t st = sb + s * STAGE_BYTES;

        #pragma unroll
        for (int kk = 0; kk < 2; ++kk) {
            const uint32_t cA = (uint32_t)(kk * 32 + colA0) ^ xorA;
            const uint32_t cB = (uint32_t)(kk * 32 + colB0) ^ xorB;
            uint32_t ah[4][4], al[4][4], bb[2][4];
            #pragma unroll
            for (int mi = 0; mi < 4; ++mi) {
                const uint32_t ra = baseA + (uint32_t)mi * 1024;
                ldsm4(ah[mi], st + ra + cA);
                ldsm4(al[mi], st + 8192 + ra + cA);
            }
            #pragma unroll
            for (int nj = 0; nj < 2; ++nj)
                ldsm4(bb[nj], st + CHUNK_A + baseB + (uint32_t)nj * 1024 + cB);
            #pragma unroll
            for (int nj = 0; nj < 2; ++nj) {
                #pragma unroll
                for (int mi = 0; mi < 4; ++mi) {
                    mma16816(acc[mi][nj*2],   ah[mi], bb[nj][0], bb[nj][1]);
                    mma16816(acc[mi][nj*2+1], ah[mi], bb[nj][2], bb[nj][3]);
                }
                #pragma unroll
                for (int mi = 0; mi < 4; ++mi) {
                    mma16816(acc[mi][nj*2],   al[mi], bb[nj][0], bb[nj][1]);
                    mma16816(acc[mi][nj*2+1], al[mi], bb[nj][2], bb[nj][3]);
                }
            }
        }
        __syncthreads();
        if (c + NSTAGE < NC && tid == 0) {
            MBAR_EXPECT_TX(mb + 8 * s, STAGE_BYTES);
            bulk_g2s(st,           aSrc + (size_t)(c + NSTAGE) * CHUNK_A, CHUNK_A, mb + 8 * s);
            bulk_g2s(st + CHUNK_A, bSrc + (size_t)(c + NSTAGE) * CHUNK_B, CHUNK_B, mb + 8 * s);
        }
    }

    // epilogue: + bias, store fp16 z
    const int g  = lane >> 2;
    const int tg = lane & 3;
    #pragma unroll
    for (int mi = 0; mi < 4; ++mi) {
        const int r0 = mblk * 128 + wm * 64 + mi * 16 + g;
        #pragma unroll
        for (int ni = 0; ni < 4; ++ni) {
            const int n = nblk * 128 + wn * 32 + ni * 8 + tg * 2;
            const float2 bia = *reinterpret_cast<const float2*>(&bias[n]);
            const __half2 v0 = __floats2half2_rn(acc[mi][ni][0] + bia.x,
                                                 acc[mi][ni][1] + bia.y);
            const __half2 v1 = __floats2half2_rn(acc[mi][ni][2] + bia.x,
                                                 acc[mi][ni][3] + bia.y);
            *reinterpret_cast<__half2*>(&Z[(size_t)r0 * H_DIM + n])       = v0;
            *reinterpret_cast<__half2*>(&Z[(size_t)(r0 + 8) * H_DIM + n]) = v1;
        }
    }
}

// ---------------- x -> packed split A (layer 0, K padded 144->192) ---------
__global__ __launch_bounds__(32)
void quant_x(const float* __restrict__ x, unsigned char* __restrict__ apack)
{
    const int m = blockIdx.x;
    const int k0 = threadIdx.x * 8;
    if (k0 >= 192) return;
    float v[8];
    if (k0 < IN_RAW) {
        *reinterpret_cast<float4*>(&v[0]) = *reinterpret_cast<const float4*>(&x[(size_t)m * IN_RAW + k0]);
        *reinterpret_cast<float4*>(&v[4]) = *reinterpret_cast<const float4*>(&x[(size_t)m * IN_RAW + k0 + 4]);
    } else {
        #pragma unroll
        for (int i = 0; i < 8; ++i) v[i] = 0.0f;
    }
    const int mblk = m >> 7, row = m & 127, kc = k0 >> 5;
    split_store8(apack + (size_t)(mblk * NC0 + kc) * CHUNK_A,
                 sw64_off(row, (k0 & 31) * 2), v);
}

// ---------------- layer-0 weights -> packed B ------------------------------
__global__ __launch_bounds__(32)
void prep_w0(const float* __restrict__ W0, unsigned char* __restrict__ bpack)
{
    const int n = blockIdx.x;
    const int k0 = threadIdx.x * 8;
    if (k0 >= 192) return;
    float v[8];
    if (k0 < IN_RAW) {
        *reinterpret_cast<float4*>(&v[0]) = *reinterpret_cast<const float4*>(&W0[(size_t)n * IN_RAW + k0]);
        *reinterpret_cast<float4*>(&v[4]) = *reinterpret_cast<const float4*>(&W0[(size_t)n * IN_RAW + k0 + 4]);
    } else {
        #pragma unroll
        for (int i = 0; i < 8; ++i) v[i] = 0.0f;
    }
    const int nblk = n >> 7, row = n & 127, kc = k0 >> 5;
    half_store8(bpack + (size_t)(nblk * NC0 + kc) * CHUNK_B,
                sw64_off(row, (k0 & 31) * 2), v);
}

// ---------------- per-layer weight prep: fold BN scale into W, shift into bias
__global__ __launch_bounds__(256)
void prep_w(const float* __restrict__ W, const float* __restrict__ scale,
            const float* __restrict__ shift, const float* __restrict__ bias_in,
            unsigned char* __restrict__ bpack, float* __restrict__ biasadj)
{
    __shared__ float red[256];
    const int n = blockIdx.x;
    const int tid = threadIdx.x;
    const int k0 = tid * 8;

    float w[8], v[8], sc[8], sh[8];
    const float* wrow = W + (size_t)n * H_DIM + k0;
    *reinterpret_cast<float4*>(&w[0])  = *reinterpret_cast<const float4*>(wrow);
    *reinterpret_cast<float4*>(&w[4])  = *reinterpret_cast<const float4*>(wrow + 4);
    *reinterpret_cast<float4*>(&sc[0]) = *reinterpret_cast<const float4*>(&scale[k0]);
    *reinterpret_cast<float4*>(&sc[4]) = *reinterpret_cast<const float4*>(&scale[k0 + 4]);
    *reinterpret_cast<float4*>(&sh[0]) = *reinterpret_cast<const float4*>(&shift[k0]);
    *reinterpret_cast<float4*>(&sh[4]) = *reinterpret_cast<const float4*>(&shift[k0 + 4]);

    float s = 0.0f;
    #pragma unroll
    for (int i = 0; i < 8; ++i) {
        v[i] = w[i] * sc[i];
        s = fmaf(sh[i], w[i], s);
    }
    const int nblk = n >> 7, row = n & 127, kc = k0 >> 5;
    half_store8(bpack + (size_t)(nblk * NCH + kc) * CHUNK_B,
                sw64_off(row, (k0 & 31) * 2), v);

    red[tid] = s;
    __syncthreads();
    for (int o = 128; o > 0; o >>= 1) {
        if (tid < o) red[tid] += red[tid + o];
        __syncthreads();
    }
    if (tid == 0) biasadj[n] = bias_in[n] + red[0];
}

// ---------------- IndRNN scan: fp16 z in, 2 h/thread, packs raw-h A --------
__global__ __launch_bounds__(256)
void scan_pack(const __half* __restrict__ Z, const float* __restrict__ u,
               unsigned char* __restrict__ apack, float* __restrict__ hlast,
               float* __restrict__ psum, float* __restrict__ psumsq, int writeA)
{
    const int j2 = blockIdx.x * 256 + threadIdx.x;   // 0..65535 (h-pair index)
    const int b  = j2 >> 10;                         // 0..63
    const int h0 = (j2 & 1023) * 2;                  // even h
    const int kc = h0 >> 5;
    const int colB = (h0 & 31) * 2;

    const float2 uh = *reinterpret_cast<const float2*>(&u[h0]);
    float hc0 = 0.0f, hc1 = 0.0f, s0 = 0.0f, s1 = 0.0f, q0 = 0.0f, q1 = 0.0f;

    const __half* zp = Z + (size_t)b * H_DIM + h0;
    unsigned char* chunkBase = apack + (size_t)kc * CHUNK_A;

    #pragma unroll 4
    for (int t = 0; t < T_DIM; ++t) {
        const __half2 zh = *reinterpret_cast<const __half2*>(zp + (size_t)t * BH);
        const float2 zv = __half22float2(zh);
        hc0 = fmaxf(fmaf(uh.x, hc0, zv.x), 0.0f);
        hc1 = fmaxf(fmaf(uh.y, hc1, zv.y), 0.0f);
        s0 += hc0; s1 += hc1;
        q0 = fmaf(hc0, hc0, q0); q1 = fmaf(hc1, hc1, q1);
        if (writeA) {
            const int m = t * B_DIM + b;
            const int mblk = m >> 7, row = m & 127;
            const __half h0h = __float2half(hc0);
            const __half h1h = __float2half(hc1);
            const uint32_t hi = (uint32_t)__half_as_ushort(h0h)
                              | ((uint32_t)__half_as_ushort(h1h) << 16);
            const uint32_t lo = (uint32_t)__half_as_ushort(__float2half(hc0 - __half2float(h0h)))
                              | ((uint32_t)__half_as_ushort(__float2half(hc1 - __half2float(h1h))) << 16);
            unsigned char* d = chunkBase + (size_t)mblk * (NCH * CHUNK_A)
                             + sw64_off(row, colB);
            *reinterpret_cast<uint32_t*>(d)        = hi;
            *reinterpret_cast<uint32_t*>(d + 8192) = lo;
        }
    }
    const int j = b * H_DIM + h0;
    *reinterpret_cast<float2*>(&hlast[j])  = make_float2(hc0, hc1);
    *reinterpret_cast<float2*>(&psum[j])   = make_float2(s0, s1);
    *reinterpret_cast<float2*>(&psumsq[j]) = make_float2(q0, q1);
}

// ---------------- BN stats -> folded affine --------------------------------
__global__ __launch_bounds__(256)
void bn_finalize(const float* __restrict__ psum, const float* __restrict__ psumsq,
                 const float* __restrict__ gamma, const float* __restrict__ beta,
                 float* __restrict__ scale, float* __restrict__ shift)
{
    const int h = blockIdx.x * 256 + threadIdx.x;
    float s = 0.0f, s2 = 0.0f;
    #pragma unroll 8
    for (int b = 0; b < B_DIM; ++b) {
        s  += psum[b * H_DIM + h];
        s2 += psumsq[b * H_DIM + h];
    }
    const float inv_n = 1.0f / (float)(T_DIM * B_DIM);
    const float mean  = s * inv_n;
    const float var   = s2 * inv_n - mean * mean;
    const float rstd  = rsqrtf(var + BN_EPS);
    const float sc    = gamma[h] * rstd;
    scale[h] = sc;
    shift[h] = fmaf(-mean, sc, beta[h]);
}

// ---------------- final projection -----------------------------------------
__global__ __launch_bounds__(256)
void final_proj(const float* __restrict__ Hlast,
                const float* __restrict__ scale, const float* __restrict__ shift,
                const float* __restrict__ Wl, const float* __restrict__ bl,
                float* __restrict__ out)
{
    const int b = blockIdx.x, c = blockIdx.y;
    __shared__ float red[256];
    float s = 0.0f;
    for (int h = threadIdx.x; h < H_DIM; h += 256) {
        const float hn = fmaf(Hlast[b * H_DIM + h], scale[h], shift[h]);
        s = fmaf(hn, Wl[c * H_DIM + h], s);
    }
    red[threadIdx.x] = s;
    __syncthreads();
    for (int o = 128; o > 0; o >>= 1) {
        if (threadIdx.x < o) red[threadIdx.x] += red[threadIdx.x + o];
        __syncthreads();
    }
    if (threadIdx.x == 0) out[b * C_DIM + c] = red[0] + bl[c];
}

// ---------------- launcher --------------------------------------------------
extern "C" void kernel_launch(void* const* d_in, const int* in_sizes, int n_in,
                              void* d_out, int out_size)
{
    const float* x      = (const float*)d_in[0];
    const float* W0     = (const float*)d_in[1];
    const float* Ws     = (const float*)d_in[2];
    const float* bs     = (const float*)d_in[3];
    const float* us     = (const float*)d_in[4];
    const float* gammas = (const float*)d_in[5];
    const float* betas  = (const float*)d_in[6];
    const float* Wlast  = (const float*)d_in[7];
    const float* blast  = (const float*)d_in[8];
    float* out = (float*)d_out;

    unsigned char *apack, *bpack0, *bpackW;
    __half* z;
    float *biasadj, *psum, *psumsq, *scale, *shift, *hlast;
    cudaGetSymbolAddress((void**)&apack,   g_apack);
    cudaGetSymbolAddress((void**)&bpack0,  g_bpack0);
    cudaGetSymbolAddress((void**)&bpackW,  g_bpackW);
    cudaGetSymbolAddress((void**)&z,       g_z);
    cudaGetSymbolAddress((void**)&biasadj, g_biasadj);
    cudaGetSymbolAddress((void**)&psum,    g_psum);
    cudaGetSymbolAddress((void**)&psumsq,  g_psumsq);
    cudaGetSymbolAddress((void**)&scale,   g_scale);
    cudaGetSymbolAddress((void**)&shift,   g_shift);
    cudaGetSymbolAddress((void**)&hlast,   g_hlast);

    cudaFuncSetAttribute(gemm_mma, cudaFuncAttributeMaxDynamicSharedMemorySize, DSMEM_BYTES);

    const dim3 ggrid(H_DIM / 128, MTOT / 128);   // 16 x 64 = 1024 CTAs, 2/SM
    const int scanBlocks = (BH / 2) / 256;       // 256

    // ---- layer 0 ----
    quant_x<<<MTOT, 32>>>(x, apack);
    prep_w0<<<H_DIM, 32>>>(W0, bpack0);
    gemm_mma<<<ggrid, 256, DSMEM_BYTES>>>(apack, bpack0, bs, z, NC0);
    scan_pack<<<scanBlocks, 256>>>(z, us, apack, hlast, psum, psumsq, 1);
    bn_finalize<<<H_DIM / 256, 256>>>(psum, psumsq, gammas, betas, scale, shift);

    // ---- layers 1..3 ----
    for (int l = 1; l < 4; ++l) {
        prep_w<<<H_DIM, 256>>>(Ws + (size_t)(l - 1) * H_DIM * H_DIM, scale, shift,
                               bs + l * H_DIM, bpackW, biasadj);
        gemm_mma<<<ggrid, 256, DSMEM_BYTES>>>(apack, bpackW, biasadj, z, NCH);
        scan_pack<<<scanBlocks, 256>>>(z, us + l * H_DIM, apack, hlast, psum, psumsq,
                                       (l < 3) ? 1 : 0);
        bn_finalize<<<H_DIM / 256, 256>>>(psum, psumsq, gammas + l * H_DIM,
                                          betas + l * H_DIM, scale, shift);
    }

    final_proj<<<dim3(B_DIM, C_DIM), 256>>>(hlast, scale, shift, Wlast, blast, out);
}

// round 13
// speedup vs baseline: 1.6846x; 1.0273x over previous
#include <cuda_runtime.h>
#include <cuda_fp16.h>
#include <cstdint>

#define T_DIM  128
#define B_DIM  64
#define IN_RAW 144
#define H_DIM  2048
#define C_DIM  10
#define BN_EPS 1e-5f
#define MTOT   (T_DIM*B_DIM)   // 8192
#define BH     (B_DIM*H_DIM)   // 131072
#define NC0    6               // layer0 K=144 padded to 192 = 6 chunks of 32
#define NCH    64              // 2048/32

// GEMM tile: BM=BN=128, KC=32 fp16 (64B rows, SW64); 256 thr (8 warps, 2x4, 64x32)
#define CHUNK_A 16384          // A: hi+lo fp16 planes (8KB each)
#define CHUNK_B 8192           // B: single fp16 plane
#define STAGE_BYTES (CHUNK_A + CHUNK_B)    // 24576
#define NSTAGE 4
#define DSMEM_BYTES (NSTAGE*STAGE_BYTES)   // 98304/CTA -> 2 CTAs = 192KB

// ---------------- scratch (allocation-free device globals) -----------------
__device__ __align__(128) unsigned char g_apack[64u*64u*CHUNK_A];     // 64MB
__device__ __align__(128) unsigned char g_bpack0[16u*NC0*CHUNK_B];    // 0.75MB
__device__ __align__(128) unsigned char g_bpackW[16u*NCH*CHUNK_B];    // 8MB, per-layer
__device__ __half g_z[MTOT*H_DIM];      // 32MB (fp16 pre-activation)
__device__ float g_biasadj[H_DIM];
__device__ float g_psum[BH];
__device__ float g_psumsq[BH];
__device__ float g_scale[H_DIM];
__device__ float g_shift[H_DIM];
__device__ float g_hlast[BH];

// ---------------- PTX helpers ----------------
__device__ __forceinline__ uint32_t smem_u32(const void* p) {
    uint32_t a;
    asm("{ .reg .u64 t; cvta.to.shared.u64 t, %1; cvt.u32.u64 %0, t; }" : "=r"(a) : "l"(p));
    return a;
}
__device__ __forceinline__ void bulk_g2s(uint32_t dst, const void* src,
                                         uint32_t bytes, uint32_t mbar) {
    asm volatile(
        "cp.async.bulk.shared::cluster.global.mbarrier::complete_tx::bytes [%0], [%1], %2, [%3];"
        :: "r"(dst), "l"(src), "r"(bytes), "r"(mbar) : "memory");
}
#define MBAR_INIT(a, c) asm volatile("mbarrier.init.shared.b64 [%0], %1;" :: "r"(a), "r"(c) : "memory")
#define MBAR_EXPECT_TX(a, b) asm volatile("mbarrier.arrive.expect_tx.shared.b64 _, [%0], %1;" :: "r"(a), "r"(b) : "memory")
#define FENCE_ASYNC() asm volatile("fence.proxy.async.shared::cta;" ::: "memory")
#define MBAR_WAIT(a, ph) do { \
    uint32_t _done; \
    asm volatile("{\n\t.reg .pred p;\n\tmbarrier.try_wait.parity.acquire.cta.shared::cta.b64 p, [%1], %2;\n\tselp.b32 %0,1,0,p;\n\t}" \
        : "=r"(_done) : "r"(a), "r"(ph) : "memory"); \
    if (!_done) { \
        asm volatile("{\n\t.reg .pred P1;\n\tWL_%=:\n\tmbarrier.try_wait.parity.acquire.cta.shared::cta.b64 P1, [%0], %1, 0x989680;\n\t@P1 bra.uni WD_%=;\n\tbra.uni WL_%=;\n\tWD_%=:\n\t}" \
            :: "r"(a), "r"(ph) : "memory"); \
    } \
} while (0)

__device__ __forceinline__ void ldsm4(uint32_t r[4], uint32_t addr) {
    asm volatile("ldmatrix.sync.aligned.m8n8.x4.shared.b16 {%0,%1,%2,%3}, [%4];"
        : "=r"(r[0]), "=r"(r[1]), "=r"(r[2]), "=r"(r[3]) : "r"(addr));
}
__device__ __forceinline__ void mma16816(float c[4], const uint32_t a[4],
                                         uint32_t b0, uint32_t b1) {
    asm volatile(
        "mma.sync.aligned.m16n8k16.row.col.f32.f16.f16.f32 "
        "{%0,%1,%2,%3}, {%4,%5,%6,%7}, {%8,%9}, {%0,%1,%2,%3};"
        : "+f"(c[0]), "+f"(c[1]), "+f"(c[2]), "+f"(c[3])
        : "r"(a[0]), "r"(a[1]), "r"(a[2]), "r"(a[3]), "r"(b0), "r"(b1));
}

// SW64 swizzled byte offset inside one 128-row x 64B plane
__device__ __forceinline__ uint32_t sw64_off(int row, int colBytes) {
    return (uint32_t)row * 64 + (((uint32_t)colBytes) ^ (uint32_t)(((row >> 1) & 3) << 4));
}

// A: split 8 fp32 -> fp16 hi/lo planes (8KB apart)
__device__ __forceinline__ void split_store8(unsigned char* base, uint32_t off,
                                             const float v[8]) {
    union { uint4 q; unsigned short us[8]; } Hq, Lq;
    #pragma unroll
    for (int i = 0; i < 8; ++i) {
        __half h = __float2half(v[i]);
        Hq.us[i] = __half_as_ushort(h);
        Lq.us[i] = __half_as_ushort(__float2half(v[i] - __half2float(h)));
    }
    *reinterpret_cast<uint4*>(base + off)        = Hq.q;
    *reinterpret_cast<uint4*>(base + off + 8192) = Lq.q;
}
// B: 8 fp32 -> single fp16 plane
__device__ __forceinline__ void half_store8(unsigned char* base, uint32_t off,
                                            const float v[8]) {
    union { uint4 q; unsigned short us[8]; } Hq;
    #pragma unroll
    for (int i = 0; i < 8; ++i) Hq.us[i] = __half_as_ushort(__float2half(v[i]));
    *reinterpret_cast<uint4*>(base + off) = Hq.q;
}

// ---------------- GEMM: Z = A@W^T + bias (fp16 2-product split) ------------
__global__ __launch_bounds__(256, 2)
void gemm_mma(const unsigned char* __restrict__ apack,
              const unsigned char* __restrict__ bpack,
              const float* __restrict__ bias, __half* __restrict__ Z, int NC)
{
    extern __shared__ unsigned char dyn[];
    __shared__ __align__(8) uint64_t mbar_s[NSTAGE];
    const uint32_t sb = smem_u32(dyn);
    const uint32_t mb = smem_u32(mbar_s);

    const int tid  = threadIdx.x;
    const int lane = tid & 31;
    const int wid  = tid >> 5;
    const int wm   = wid >> 2;
    const int wn   = wid & 3;
    const int nblk = blockIdx.x;
    const int mblk = blockIdx.y;

    const unsigned char* aSrc = apack + (size_t)mblk * NC * CHUNK_A;
    const unsigned char* bSrc = bpack + (size_t)nblk * NC * CHUNK_B;

    if (tid == 0) {
        #pragma unroll
        for (int s = 0; s < NSTAGE; ++s) MBAR_INIT(mb + 8 * s, 1);
        FENCE_ASYNC();
    }
    __syncthreads();
    if (tid == 0) {
        #pragma unroll
        for (int s = 0; s < NSTAGE; ++s) {
            if (s < NC) {
                MBAR_EXPECT_TX(mb + 8 * s, STAGE_BYTES);
                bulk_g2s(sb + s * STAGE_BYTES,           aSrc + (size_t)s * CHUNK_A, CHUNK_A, mb + 8 * s);
                bulk_g2s(sb + s * STAGE_BYTES + CHUNK_A, bSrc + (size_t)s * CHUNK_B, CHUNK_B, mb + 8 * s);
            }
        }
    }

    const int rowA  = wm * 64 + (lane & 15);
    const int rowB  = wn * 32 + ((lane >> 4) << 3) + (lane & 7);
    const uint32_t xorA = (uint32_t)(((rowA >> 1) & 3) << 4);
    const uint32_t xorB = (uint32_t)(((rowB >> 1) & 3) << 4);
    const uint32_t colA0 = (uint32_t)((lane >> 4) * 16);
    const uint32_t colB0 = (uint32_t)(((lane >> 3) & 1) * 16);
    const uint32_t baseA = (uint32_t)rowA * 64;
    const uint32_t baseB = (uint32_t)rowB * 64;

    float acc[4][4][4];
    #pragma unroll
    for (int i = 0; i < 4; ++i)
        #pragma unroll
        for (int j = 0; j < 4; ++j)
            #pragma unroll
            for (int q = 0; q < 4; ++q) acc[i][j][q] = 0.0f;

    int ph[NSTAGE] = {0, 0, 0, 0};
    for (int c = 0; c < NC; ++c) {
        const int s = c & (NSTAGE - 1);
        MBAR_WAIT(mb + 8 * s, ph[s]);
        ph[s] ^= 1;
        const uint32_t st = sb + s * STAGE_BYTES;

        #pragma unroll
        for (int kk = 0; kk < 2; ++kk) {
            const uint32_t cA = (uint32_t)(kk * 32 + colA0) ^ xorA;
            const uint32_t cB = (uint32_t)(kk * 32 + colB0) ^ xorB;
            uint32_t ah[4][4], al[4][4], bb[2][4];
            #pragma unroll
            for (int mi = 0; mi < 4; ++mi) {
                const uint32_t ra = baseA + (uint32_t)mi * 1024;
                ldsm4(ah[mi], st + ra + cA);
                ldsm4(al[mi], st + 8192 + ra + cA);
            }
            #pragma unroll
            for (int nj = 0; nj < 2; ++nj)
                ldsm4(bb[nj], st + CHUNK_A + baseB + (uint32_t)nj * 1024 + cB);
            #pragma unroll
            for (int nj = 0; nj < 2; ++nj) {
                #pragma unroll
                for (int mi = 0; mi < 4; ++mi) {
                    mma16816(acc[mi][nj*2],   ah[mi], bb[nj][0], bb[nj][1]);
                    mma16816(acc[mi][nj*2+1], ah[mi], bb[nj][2], bb[nj][3]);
                }
                #pragma unroll
                for (int mi = 0; mi < 4; ++mi) {
                    mma16816(acc[mi][nj*2],   al[mi], bb[nj][0], bb[nj][1]);
                    mma16816(acc[mi][nj*2+1], al[mi], bb[nj][2], bb[nj][3]);
                }
            }
        }
        __syncthreads();
        if (c + NSTAGE < NC && tid == 0) {
            MBAR_EXPECT_TX(mb + 8 * s, STAGE_BYTES);
            bulk_g2s(st,           aSrc + (size_t)(c + NSTAGE) * CHUNK_A, CHUNK_A, mb + 8 * s);
            bulk_g2s(st + CHUNK_A, bSrc + (size_t)(c + NSTAGE) * CHUNK_B, CHUNK_B, mb + 8 * s);
        }
    }

    // epilogue: + bias, store fp16 z
    const int g  = lane >> 2;
    const int tg = lane & 3;
    #pragma unroll
    for (int mi = 0; mi < 4; ++mi) {
        const int r0 = mblk * 128 + wm * 64 + mi * 16 + g;
        #pragma unroll
        for (int ni = 0; ni < 4; ++ni) {
            const int n = nblk * 128 + wn * 32 + ni * 8 + tg * 2;
            const float2 bia = *reinterpret_cast<const float2*>(&bias[n]);
            const __half2 v0 = __floats2half2_rn(acc[mi][ni][0] + bia.x,
                                                 acc[mi][ni][1] + bia.y);
            const __half2 v1 = __floats2half2_rn(acc[mi][ni][2] + bia.x,
                                                 acc[mi][ni][3] + bia.y);
            *reinterpret_cast<__half2*>(&Z[(size_t)r0 * H_DIM + n])       = v0;
            *reinterpret_cast<__half2*>(&Z[(size_t)(r0 + 8) * H_DIM + n]) = v1;
        }
    }
}

// ---------------- layer-0 prep: x pack + W0 pack in ONE launch -------------
// blocks [0, MTOT): quant x row; blocks [MTOT, MTOT+H_DIM): pack W0 row
__global__ __launch_bounds__(32)
void prep_layer0(const float* __restrict__ x, const float* __restrict__ W0,
                 unsigned char* __restrict__ apack, unsigned char* __restrict__ bpack)
{
    const int blk = blockIdx.x;
    const int k0 = threadIdx.x * 8;
    if (k0 >= 192) return;
    if (blk < MTOT) {
        const int m = blk;
        float v[8];
        if (k0 < IN_RAW) {
            *reinterpret_cast<float4*>(&v[0]) = *reinterpret_cast<const float4*>(&x[(size_t)m * IN_RAW + k0]);
            *reinterpret_cast<float4*>(&v[4]) = *reinterpret_cast<const float4*>(&x[(size_t)m * IN_RAW + k0 + 4]);
        } else {
            #pragma unroll
            for (int i = 0; i < 8; ++i) v[i] = 0.0f;
        }
        const int mblk = m >> 7, row = m & 127, kc = k0 >> 5;
        split_store8(apack + (size_t)(mblk * NC0 + kc) * CHUNK_A,
                     sw64_off(row, (k0 & 31) * 2), v);
    } else {
        const int n = blk - MTOT;
        float v[8];
        if (k0 < IN_RAW) {
            *reinterpret_cast<float4*>(&v[0]) = *reinterpret_cast<const float4*>(&W0[(size_t)n * IN_RAW + k0]);
            *reinterpret_cast<float4*>(&v[4]) = *reinterpret_cast<const float4*>(&W0[(size_t)n * IN_RAW + k0 + 4]);
        } else {
            #pragma unroll
            for (int i = 0; i < 8; ++i) v[i] = 0.0f;
        }
        const int nblk = n >> 7, row = n & 127, kc = k0 >> 5;
        half_store8(bpack + (size_t)(nblk * NC0 + kc) * CHUNK_B,
                    sw64_off(row, (k0 & 31) * 2), v);
    }
}

// ---------------- per-layer weight prep: fold BN scale into W, shift into bias
__global__ __launch_bounds__(256)
void prep_w(const float* __restrict__ W, const float* __restrict__ scale,
            const float* __restrict__ shift, const float* __restrict__ bias_in,
            unsigned char* __restrict__ bpack, float* __restrict__ biasadj)
{
    __shared__ float red[256];
    const int n = blockIdx.x;
    const int tid = threadIdx.x;
    const int k0 = tid * 8;

    float w[8], v[8], sc[8], sh[8];
    const float* wrow = W + (size_t)n * H_DIM + k0;
    *reinterpret_cast<float4*>(&w[0])  = *reinterpret_cast<const float4*>(wrow);
    *reinterpret_cast<float4*>(&w[4])  = *reinterpret_cast<const float4*>(wrow + 4);
    *reinterpret_cast<float4*>(&sc[0]) = *reinterpret_cast<const float4*>(&scale[k0]);
    *reinterpret_cast<float4*>(&sc[4]) = *reinterpret_cast<const float4*>(&scale[k0 + 4]);
    *reinterpret_cast<float4*>(&sh[0]) = *reinterpret_cast<const float4*>(&shift[k0]);
    *reinterpret_cast<float4*>(&sh[4]) = *reinterpret_cast<const float4*>(&shift[k0 + 4]);

    float s = 0.0f;
    #pragma unroll
    for (int i = 0; i < 8; ++i) {
        v[i] = w[i] * sc[i];
        s = fmaf(sh[i], w[i], s);
    }
    const int nblk = n >> 7, row = n & 127, kc = k0 >> 5;
    half_store8(bpack + (size_t)(nblk * NCH + kc) * CHUNK_B,
                sw64_off(row, (k0 & 31) * 2), v);

    red[tid] = s;
    __syncthreads();
    for (int o = 128; o > 0; o >>= 1) {
        if (tid < o) red[tid] += red[tid + o];
        __syncthreads();
    }
    if (tid == 0) biasadj[n] = bias_in[n] + red[0];
}

// ---------------- IndRNN scan: fp16 z, 8-deep z prefetch, packs raw-h A ----
__global__ __launch_bounds__(256)
void scan_pack(const __half* __restrict__ Z, const float* __restrict__ u,
               unsigned char* __restrict__ apack, float* __restrict__ hlast,
               float* __restrict__ psum, float* __restrict__ psumsq, int writeA)
{
    const int j2 = blockIdx.x * 256 + threadIdx.x;   // 0..65535 (h-pair index)
    const int b  = j2 >> 10;                         // 0..63
    const int h0 = (j2 & 1023) * 2;                  // even h
    const int kc = h0 >> 5;
    const int colB = (h0 & 31) * 2;

    const float2 uh = *reinterpret_cast<const float2*>(&u[h0]);
    float hc0 = 0.0f, hc1 = 0.0f, s0 = 0.0f, s1 = 0.0f, q0 = 0.0f, q1 = 0.0f;

    const __half2* zp = reinterpret_cast<const __half2*>(Z + (size_t)b * H_DIM + h0);
    unsigned char* chunkBase = apack + (size_t)kc * CHUNK_A;
    const uint32_t swc = (uint32_t)colB;

    #pragma unroll 1
    for (int tb = 0; tb < T_DIM; tb += 8) {
        // batch-issue 8 independent streaming loads (MLP=8)
        __half2 zl[8];
        #pragma unroll
        for (int i = 0; i < 8; ++i)
            zl[i] = __ldcs(zp + (size_t)(tb + i) * (BH / 2));
        #pragma unroll
        for (int i = 0; i < 8; ++i) {
            const int t = tb + i;
            const float2 zv = __half22float2(zl[i]);
            hc0 = fmaxf(fmaf(uh.x, hc0, zv.x), 0.0f);
            hc1 = fmaxf(fmaf(uh.y, hc1, zv.y), 0.0f);
            s0 += hc0; s1 += hc1;
            q0 = fmaf(hc0, hc0, q0); q1 = fmaf(hc1, hc1, q1);
            if (writeA) {
                const int m = t * B_DIM + b;
                const int mblk = m >> 7, row = m & 127;
                const __half h0h = __float2half(hc0);
                const __half h1h = __float2half(hc1);
                const uint32_t hi = (uint32_t)__half_as_ushort(h0h)
                                  | ((uint32_t)__half_as_ushort(h1h) << 16);
                const uint32_t lo = (uint32_t)__half_as_ushort(__float2half(hc0 - __half2float(h0h)))
                                  | ((uint32_t)__half_as_ushort(__float2half(hc1 - __half2float(h1h))) << 16);
                unsigned char* d = chunkBase + (size_t)mblk * (NCH * CHUNK_A)
                                 + (uint32_t)row * 64
                                 + (swc ^ (uint32_t)(((row >> 1) & 3) << 4));
                *reinterpret_cast<uint32_t*>(d)        = hi;
                *reinterpret_cast<uint32_t*>(d + 8192) = lo;
            }
        }
    }
    const int j = b * H_DIM + h0;
    *reinterpret_cast<float2*>(&hlast[j])  = make_float2(hc0, hc1);
    *reinterpret_cast<float2*>(&psum[j])   = make_float2(s0, s1);
    *reinterpret_cast<float2*>(&psumsq[j]) = make_float2(q0, q1);
}

// ---------------- BN stats -> folded affine --------------------------------
__global__ __launch_bounds__(256)
void bn_finalize(const float* __restrict__ psum, const float* __restrict__ psumsq,
                 const float* __restrict__ gamma, const float* __restrict__ beta,
                 float* __restrict__ scale, float* __restrict__ shift)
{
    const int h = blockIdx.x * 256 + threadIdx.x;
    float s = 0.0f, s2 = 0.0f;
    #pragma unroll 8
    for (int b = 0; b < B_DIM; ++b) {
        s  += psum[b * H_DIM + h];
        s2 += psumsq[b * H_DIM + h];
    }
    const float inv_n = 1.0f / (float)(T_DIM * B_DIM);
    const float mean  = s * inv_n;
    const float var   = s2 * inv_n - mean * mean;
    const float rstd  = rsqrtf(var + BN_EPS);
    const float sc    = gamma[h] * rstd;
    scale[h] = sc;
    shift[h] = fmaf(-mean, sc, beta[h]);
}

// ---------------- final projection -----------------------------------------
__global__ __launch_bounds__(256)
void final_proj(const float* __restrict__ Hlast,
                const float* __restrict__ scale, const float* __restrict__ shift,
                const float* __restrict__ Wl, const float* __restrict__ bl,
                float* __restrict__ out)
{
    const int b = blockIdx.x, c = blockIdx.y;
    __shared__ float red[256];
    float s = 0.0f;
    for (int h = threadIdx.x; h < H_DIM; h += 256) {
        const float hn = fmaf(Hlast[b * H_DIM + h], scale[h], shift[h]);
        s = fmaf(hn, Wl[c * H_DIM + h], s);
    }
    red[threadIdx.x] = s;
    __syncthreads();
    for (int o = 128; o > 0; o >>= 1) {
        if (threadIdx.x < o) red[threadIdx.x] += red[threadIdx.x + o];
        __syncthreads();
    }
    if (threadIdx.x == 0) out[b * C_DIM + c] = red[0] + bl[c];
}

// ---------------- launcher --------------------------------------------------
extern "C" void kernel_launch(void* const* d_in, const int* in_sizes, int n_in,
                              void* d_out, int out_size)
{
    const float* x      = (const float*)d_in[0];
    const float* W0     = (const float*)d_in[1];
    const float* Ws     = (const float*)d_in[2];
    const float* bs     = (const float*)d_in[3];
    const float* us     = (const float*)d_in[4];
    const float* gammas = (const float*)d_in[5];
    const float* betas  = (const float*)d_in[6];
    const float* Wlast  = (const float*)d_in[7];
    const float* blast  = (const float*)d_in[8];
    float* out = (float*)d_out;

    unsigned char *apack, *bpack0, *bpackW;
    __half* z;
    float *biasadj, *psum, *psumsq, *scale, *shift, *hlast;
    cudaGetSymbolAddress((void**)&apack,   g_apack);
    cudaGetSymbolAddress((void**)&bpack0,  g_bpack0);
    cudaGetSymbolAddress((void**)&bpackW,  g_bpackW);
    cudaGetSymbolAddress((void**)&z,       g_z);
    cudaGetSymbolAddress((void**)&biasadj, g_biasadj);
    cudaGetSymbolAddress((void**)&psum,    g_psum);
    cudaGetSymbolAddress((void**)&psumsq,  g_psumsq);
    cudaGetSymbolAddress((void**)&scale,   g_scale);
    cudaGetSymbolAddress((void**)&shift,   g_shift);
    cudaGetSymbolAddress((void**)&hlast,   g_hlast);

    cudaFuncSetAttribute(gemm_mma, cudaFuncAttributeMaxDynamicSharedMemorySize, DSMEM_BYTES);

    const dim3 ggrid(H_DIM / 128, MTOT / 128);   // 16 x 64 = 1024 CTAs, 2/SM
    const int scanBlocks = (BH / 2) / 256;       // 256

    // ---- layer 0 ----
    prep_layer0<<<MTOT + H_DIM, 32>>>(x, W0, apack, bpack0);
    gemm_mma<<<ggrid, 256, DSMEM_BYTES>>>(apack, bpack0, bs, z, NC0);
    scan_pack<<<scanBlocks, 256>>>(z, us, apack, hlast, psum, psumsq, 1);
    bn_finalize<<<H_DIM / 256, 256>>>(psum, psumsq, gammas, betas, scale, shift);

    // ---- layers 1..3 ----
    for (int l = 1; l < 4; ++l) {
        prep_w<<<H_DIM, 256>>>(Ws + (size_t)(l - 1) * H_DIM * H_DIM, scale, shift,
                               bs + l * H_DIM, bpackW, biasadj);
        gemm_mma<<<ggrid, 256, DSMEM_BYTES>>>(apack, bpackW, biasadj, z, NCH);
        scan_pack<<<scanBlocks, 256>>>(z, us + l * H_DIM, apack, hlast, psum, psumsq,
                                       (l < 3) ? 1 : 0);
        bn_finalize<<<H_DIM / 256, 256>>>(psum, psumsq, gammas + l * H_DIM,
                                          betas + l * H_DIM, scale, shift);
    }

    final_proj<<<dim3(B_DIM, C_DIM), 256>>>(hlast, scale, shift, Wlast, blast, out);
}

// round 14
// speedup vs baseline: 1.7098x; 1.0150x over previous
#include <cuda_runtime.h>
#include <cuda_fp16.h>
#include <cstdint>

#define T_DIM  128
#define B_DIM  64
#define IN_RAW 144
#define H_DIM  2048
#define C_DIM  10
#define BN_EPS 1e-5f
#define MTOT   (T_DIM*B_DIM)   // 8192
#define BH     (B_DIM*H_DIM)   // 131072
#define NC0    6               // layer0 K=144 padded to 192 = 6 chunks of 32
#define NCH    64              // 2048/32

// GEMM tile: BM=BN=128, KC=32 fp16 (64B rows, SW64); 256 thr (8 warps, 2x4, 64x32)
#define CHUNK_A 16384          // A: hi+lo fp16 planes (8KB each)
#define CHUNK_B 8192           // B: single fp16 plane
#define STAGE_BYTES (CHUNK_A + CHUNK_B)    // 24576
#define NSTAGE 4
#define DSMEM_BYTES (NSTAGE*STAGE_BYTES)   // 98304/CTA -> 2 CTAs = 192KB

// ---------------- scratch (allocation-free device globals) -----------------
__device__ __align__(128) unsigned char g_apack[64u*64u*CHUNK_A];     // 64MB
__device__ __align__(128) unsigned char g_bpack0[16u*NC0*CHUNK_B];    // 0.75MB
__device__ __align__(128) unsigned char g_bpackW[16u*NCH*CHUNK_B];    // 8MB, per-layer
__device__ __half g_z[MTOT*H_DIM];      // 32MB (fp16 pre-activation)
__device__ float g_biasadj[H_DIM];
__device__ float g_psum[BH];
__device__ float g_psumsq[BH];
__device__ float g_scale[H_DIM];
__device__ float g_shift[H_DIM];
__device__ float g_hlast[BH];

// ---------------- PTX helpers ----------------
__device__ __forceinline__ uint32_t smem_u32(const void* p) {
    uint32_t a;
    asm("{ .reg .u64 t; cvta.to.shared.u64 t, %1; cvt.u32.u64 %0, t; }" : "=r"(a) : "l"(p));
    return a;
}
__device__ __forceinline__ void bulk_g2s(uint32_t dst, const void* src,
                                         uint32_t bytes, uint32_t mbar) {
    asm volatile(
        "cp.async.bulk.shared::cluster.global.mbarrier::complete_tx::bytes [%0], [%1], %2, [%3];"
        :: "r"(dst), "l"(src), "r"(bytes), "r"(mbar) : "memory");
}
#define MBAR_INIT(a, c) asm volatile("mbarrier.init.shared.b64 [%0], %1;" :: "r"(a), "r"(c) : "memory")
#define MBAR_EXPECT_TX(a, b) asm volatile("mbarrier.arrive.expect_tx.shared.b64 _, [%0], %1;" :: "r"(a), "r"(b) : "memory")
#define FENCE_ASYNC() asm volatile("fence.proxy.async.shared::cta;" ::: "memory")
#define MBAR_WAIT(a, ph) do { \
    uint32_t _done; \
    asm volatile("{\n\t.reg .pred p;\n\tmbarrier.try_wait.parity.acquire.cta.shared::cta.b64 p, [%1], %2;\n\tselp.b32 %0,1,0,p;\n\t}" \
        : "=r"(_done) : "r"(a), "r"(ph) : "memory"); \
    if (!_done) { \
        asm volatile("{\n\t.reg .pred P1;\n\tWL_%=:\n\tmbarrier.try_wait.parity.acquire.cta.shared::cta.b64 P1, [%0], %1, 0x989680;\n\t@P1 bra.uni WD_%=;\n\tbra.uni WL_%=;\n\tWD_%=:\n\t}" \
            :: "r"(a), "r"(ph) : "memory"); \
    } \
} while (0)

__device__ __forceinline__ void ldsm4(uint32_t r[4], uint32_t addr) {
    asm volatile("ldmatrix.sync.aligned.m8n8.x4.shared.b16 {%0,%1,%2,%3}, [%4];"
        : "=r"(r[0]), "=r"(r[1]), "=r"(r[2]), "=r"(r[3]) : "r"(addr));
}
__device__ __forceinline__ void mma16816(float c[4], const uint32_t a[4],
                                         uint32_t b0, uint32_t b1) {
    asm volatile(
        "mma.sync.aligned.m16n8k16.row.col.f32.f16.f16.f32 "
        "{%0,%1,%2,%3}, {%4,%5,%6,%7}, {%8,%9}, {%0,%1,%2,%3};"
        : "+f"(c[0]), "+f"(c[1]), "+f"(c[2]), "+f"(c[3])
        : "r"(a[0]), "r"(a[1]), "r"(a[2]), "r"(a[3]), "r"(b0), "r"(b1));
}

// SW64 swizzled byte offset inside one 128-row x 64B plane
__device__ __forceinline__ uint32_t sw64_off(int row, int colBytes) {
    return (uint32_t)row * 64 + (((uint32_t)colBytes) ^ (uint32_t)(((row >> 1) & 3) << 4));
}

// A: split 8 fp32 -> fp16 hi/lo planes (8KB apart)
__device__ __forceinline__ void split_store8(unsigned char* base, uint32_t off,
                                             const float v[8]) {
    union { uint4 q; unsigned short us[8]; } Hq, Lq;
    #pragma unroll
    for (int i = 0; i < 8; ++i) {
        __half h = __float2half(v[i]);
        Hq.us[i] = __half_as_ushort(h);
        Lq.us[i] = __half_as_ushort(__float2half(v[i] - __half2float(h)));
    }
    *reinterpret_cast<uint4*>(base + off)        = Hq.q;
    *reinterpret_cast<uint4*>(base + off + 8192) = Lq.q;
}
// B: 8 fp32 -> single fp16 plane
__device__ __forceinline__ void half_store8(unsigned char* base, uint32_t off,
                                            const float v[8]) {
    union { uint4 q; unsigned short us[8]; } Hq;
    #pragma unroll
    for (int i = 0; i < 8; ++i) Hq.us[i] = __half_as_ushort(__float2half(v[i]));
    *reinterpret_cast<uint4*>(base + off) = Hq.q;
}

// ---------------- GEMM: Z = A@W^T + bias (fp16 2-product split) ------------
__global__ __launch_bounds__(256, 2)
void gemm_mma(const unsigned char* __restrict__ apack,
              const unsigned char* __restrict__ bpack,
              const float* __restrict__ bias, __half* __restrict__ Z, int NC)
{
    extern __shared__ unsigned char dyn[];
    __shared__ __align__(8) uint64_t mbar_s[NSTAGE];
    const uint32_t sb = smem_u32(dyn);
    const uint32_t mb = smem_u32(mbar_s);

    const int tid  = threadIdx.x;
    const int lane = tid & 31;
    const int wid  = tid >> 5;
    const int wm   = wid >> 2;
    const int wn   = wid & 3;
    const int nblk = blockIdx.x;
    const int mblk = blockIdx.y;

    const unsigned char* aSrc = apack + (size_t)mblk * NC * CHUNK_A;
    const unsigned char* bSrc = bpack + (size_t)nblk * NC * CHUNK_B;

    if (tid == 0) {
        #pragma unroll
        for (int s = 0; s < NSTAGE; ++s) MBAR_INIT(mb + 8 * s, 1);
        FENCE_ASYNC();
    }
    __syncthreads();
    if (tid == 0) {
        #pragma unroll
        for (int s = 0; s < NSTAGE; ++s) {
            if (s < NC) {
                MBAR_EXPECT_TX(mb + 8 * s, STAGE_BYTES);
                bulk_g2s(sb + s * STAGE_BYTES,           aSrc + (size_t)s * CHUNK_A, CHUNK_A, mb + 8 * s);
                bulk_g2s(sb + s * STAGE_BYTES + CHUNK_A, bSrc + (size_t)s * CHUNK_B, CHUNK_B, mb + 8 * s);
            }
        }
    }

    const int rowA  = wm * 64 + (lane & 15);
    const int rowB  = wn * 32 + ((lane >> 4) << 3) + (lane & 7);
    const uint32_t xorA = (uint32_t)(((rowA >> 1) & 3) << 4);
    const uint32_t xorB = (uint32_t)(((rowB >> 1) & 3) << 4);
    const uint32_t colA0 = (uint32_t)((lane >> 4) * 16);
    const uint32_t colB0 = (uint32_t)(((lane >> 3) & 1) * 16);
    const uint32_t baseA = (uint32_t)rowA * 64;
    const uint32_t baseB = (uint32_t)rowB * 64;

    float acc[4][4][4];
    #pragma unroll
    for (int i = 0; i < 4; ++i)
        #pragma unroll
        for (int j = 0; j < 4; ++j)
            #pragma unroll
            for (int q = 0; q < 4; ++q) acc[i][j][q] = 0.0f;

    int ph[NSTAGE] = {0, 0, 0, 0};
    for (int c = 0; c < NC; ++c) {
        const int s = c & (NSTAGE - 1);
        MBAR_WAIT(mb + 8 * s, ph[s]);
        ph[s] ^= 1;
        const uint32_t st = sb + s * STAGE_BYTES;

        #pragma unroll
        for (int kk = 0; kk < 2; ++kk) {
            const uint32_t cA = (uint32_t)(kk * 32 + colA0) ^ xorA;
            const uint32_t cB = (uint32_t)(kk * 32 + colB0) ^ xorB;
            uint32_t ah[4][4], al[4][4], bb[2][4];
            #pragma unroll
            for (int mi = 0; mi < 4; ++mi) {
                const uint32_t ra = baseA + (uint32_t)mi * 1024;
                ldsm4(ah[mi], st + ra + cA);
                ldsm4(al[mi], st + 8192 + ra + cA);
            }
            #pragma unroll
            for (int nj = 0; nj < 2; ++nj)
                ldsm4(bb[nj], st + CHUNK_A + baseB + (uint32_t)nj * 1024 + cB);
            #pragma unroll
            for (int nj = 0; nj < 2; ++nj) {
                #pragma unroll
                for (int mi = 0; mi < 4; ++mi) {
                    mma16816(acc[mi][nj*2],   ah[mi], bb[nj][0], bb[nj][1]);
                    mma16816(acc[mi][nj*2+1], ah[mi], bb[nj][2], bb[nj][3]);
                }
                #pragma unroll
                for (int mi = 0; mi < 4; ++mi) {
                    mma16816(acc[mi][nj*2],   al[mi], bb[nj][0], bb[nj][1]);
                    mma16816(acc[mi][nj*2+1], al[mi], bb[nj][2], bb[nj][3]);
                }
            }
        }
        __syncthreads();
        if (c + NSTAGE < NC && tid == 0) {
            MBAR_EXPECT_TX(mb + 8 * s, STAGE_BYTES);
            bulk_g2s(st,           aSrc + (size_t)(c + NSTAGE) * CHUNK_A, CHUNK_A, mb + 8 * s);
            bulk_g2s(st + CHUNK_A, bSrc + (size_t)(c + NSTAGE) * CHUNK_B, CHUNK_B, mb + 8 * s);
        }
    }

    // epilogue: + bias, store fp16 z
    const int g  = lane >> 2;
    const int tg = lane & 3;
    #pragma unroll
    for (int mi = 0; mi < 4; ++mi) {
        const int r0 = mblk * 128 + wm * 64 + mi * 16 + g;
        #pragma unroll
        for (int ni = 0; ni < 4; ++ni) {
            const int n = nblk * 128 + wn * 32 + ni * 8 + tg * 2;
            const float2 bia = *reinterpret_cast<const float2*>(&bias[n]);
            const __half2 v0 = __floats2half2_rn(acc[mi][ni][0] + bia.x,
                                                 acc[mi][ni][1] + bia.y);
            const __half2 v1 = __floats2half2_rn(acc[mi][ni][2] + bia.x,
                                                 acc[mi][ni][3] + bia.y);
            *reinterpret_cast<__half2*>(&Z[(size_t)r0 * H_DIM + n])       = v0;
            *reinterpret_cast<__half2*>(&Z[(size_t)(r0 + 8) * H_DIM + n]) = v1;
        }
    }
}

// ---------------- layer-0 prep: x pack + W0 pack in ONE launch -------------
__global__ __launch_bounds__(32)
void prep_layer0(const float* __restrict__ x, const float* __restrict__ W0,
                 unsigned char* __restrict__ apack, unsigned char* __restrict__ bpack)
{
    const int blk = blockIdx.x;
    const int k0 = threadIdx.x * 8;
    if (k0 >= 192) return;
    if (blk < MTOT) {
        const int m = blk;
        float v[8];
        if (k0 < IN_RAW) {
            *reinterpret_cast<float4*>(&v[0]) = *reinterpret_cast<const float4*>(&x[(size_t)m * IN_RAW + k0]);
            *reinterpret_cast<float4*>(&v[4]) = *reinterpret_cast<const float4*>(&x[(size_t)m * IN_RAW + k0 + 4]);
        } else {
            #pragma unroll
            for (int i = 0; i < 8; ++i) v[i] = 0.0f;
        }
        const int mblk = m >> 7, row = m & 127, kc = k0 >> 5;
        split_store8(apack + (size_t)(mblk * NC0 + kc) * CHUNK_A,
                     sw64_off(row, (k0 & 31) * 2), v);
    } else {
        const int n = blk - MTOT;
        float v[8];
        if (k0 < IN_RAW) {
            *reinterpret_cast<float4*>(&v[0]) = *reinterpret_cast<const float4*>(&W0[(size_t)n * IN_RAW + k0]);
            *reinterpret_cast<float4*>(&v[4]) = *reinterpret_cast<const float4*>(&W0[(size_t)n * IN_RAW + k0 + 4]);
        } else {
            #pragma unroll
            for (int i = 0; i < 8; ++i) v[i] = 0.0f;
        }
        const int nblk = n >> 7, row = n & 127, kc = k0 >> 5;
        half_store8(bpack + (size_t)(nblk * NC0 + kc) * CHUNK_B,
                    sw64_off(row, (k0 & 31) * 2), v);
    }
}

// ---------------- per-layer weight prep: fold BN scale into W, shift into bias
__global__ __launch_bounds__(256)
void prep_w(const float* __restrict__ W, const float* __restrict__ scale,
            const float* __restrict__ shift, const float* __restrict__ bias_in,
            unsigned char* __restrict__ bpack, float* __restrict__ biasadj)
{
    __shared__ float red[8];
    const int n = blockIdx.x;
    const int tid = threadIdx.x;
    const int lane = tid & 31;
    const int wrp  = tid >> 5;
    const int k0 = tid * 8;

    float w[8], v[8], sc[8], sh[8];
    const float* wrow = W + (size_t)n * H_DIM + k0;
    *reinterpret_cast<float4*>(&w[0])  = *reinterpret_cast<const float4*>(wrow);
    *reinterpret_cast<float4*>(&w[4])  = *reinterpret_cast<const float4*>(wrow + 4);
    *reinterpret_cast<float4*>(&sc[0]) = *reinterpret_cast<const float4*>(&scale[k0]);
    *reinterpret_cast<float4*>(&sc[4]) = *reinterpret_cast<const float4*>(&scale[k0 + 4]);
    *reinterpret_cast<float4*>(&sh[0]) = *reinterpret_cast<const float4*>(&shift[k0]);
    *reinterpret_cast<float4*>(&sh[4]) = *reinterpret_cast<const float4*>(&shift[k0 + 4]);

    float s = 0.0f;
    #pragma unroll
    for (int i = 0; i < 8; ++i) {
        v[i] = w[i] * sc[i];
        s = fmaf(sh[i], w[i], s);
    }
    const int nblk = n >> 7, row = n & 127, kc = k0 >> 5;
    half_store8(bpack + (size_t)(nblk * NCH + kc) * CHUNK_B,
                sw64_off(row, (k0 & 31) * 2), v);

    // warp shuffle reduction, then 8-slot combine
    #pragma unroll
    for (int o = 16; o > 0; o >>= 1) s += __shfl_xor_sync(0xFFFFFFFFu, s, o);
    if (lane == 0) red[wrp] = s;
    __syncthreads();
    if (tid == 0) {
        float t = 0.0f;
        #pragma unroll
        for (int i = 0; i < 8; ++i) t += red[i];
        biasadj[n] = bias_in[n] + t;
    }
}

// ---------------- IndRNN scan: fp16 z, 8-deep z prefetch, packs raw-h A ----
__global__ __launch_bounds__(256)
void scan_pack(const __half* __restrict__ Z, const float* __restrict__ u,
               unsigned char* __restrict__ apack, float* __restrict__ hlast,
               float* __restrict__ psum, float* __restrict__ psumsq, int writeA)
{
    const int j2 = blockIdx.x * 256 + threadIdx.x;   // 0..65535 (h-pair index)
    const int b  = j2 >> 10;                         // 0..63
    const int h0 = (j2 & 1023) * 2;                  // even h
    const int kc = h0 >> 5;
    const int colB = (h0 & 31) * 2;

    const float2 uh = *reinterpret_cast<const float2*>(&u[h0]);
    float hc0 = 0.0f, hc1 = 0.0f, s0 = 0.0f, s1 = 0.0f, q0 = 0.0f, q1 = 0.0f;

    const __half2* zp = reinterpret_cast<const __half2*>(Z + (size_t)b * H_DIM + h0);
    unsigned char* chunkBase = apack + (size_t)kc * CHUNK_A;
    const uint32_t swc = (uint32_t)colB;

    #pragma unroll 1
    for (int tb = 0; tb < T_DIM; tb += 8) {
        __half2 zl[8];
        #pragma unroll
        for (int i = 0; i < 8; ++i)
            zl[i] = __ldcs(zp + (size_t)(tb + i) * (BH / 2));
        #pragma unroll
        for (int i = 0; i < 8; ++i) {
            const int t = tb + i;
            const float2 zv = __half22float2(zl[i]);
            hc0 = fmaxf(fmaf(uh.x, hc0, zv.x), 0.0f);
            hc1 = fmaxf(fmaf(uh.y, hc1, zv.y), 0.0f);
            s0 += hc0; s1 += hc1;
            q0 = fmaf(hc0, hc0, q0); q1 = fmaf(hc1, hc1, q1);
            if (writeA) {
                const int m = t * B_DIM + b;
                const int mblk = m >> 7, row = m & 127;
                const __half h0h = __float2half(hc0);
                const __half h1h = __float2half(hc1);
                const uint32_t hi = (uint32_t)__half_as_ushort(h0h)
                                  | ((uint32_t)__half_as_ushort(h1h) << 16);
                const uint32_t lo = (uint32_t)__half_as_ushort(__float2half(hc0 - __half2float(h0h)))
                                  | ((uint32_t)__half_as_ushort(__float2half(hc1 - __half2float(h1h))) << 16);
                unsigned char* d = chunkBase + (size_t)mblk * (NCH * CHUNK_A)
                                 + (uint32_t)row * 64
                                 + (swc ^ (uint32_t)(((row >> 1) & 3) << 4));
                *reinterpret_cast<uint32_t*>(d)        = hi;
                *reinterpret_cast<uint32_t*>(d + 8192) = lo;
            }
        }
    }
    const int j = b * H_DIM + h0;
    *reinterpret_cast<float2*>(&hlast[j])  = make_float2(hc0, hc1);
    *reinterpret_cast<float2*>(&psum[j])   = make_float2(s0, s1);
    *reinterpret_cast<float2*>(&psumsq[j]) = make_float2(q0, q1);
}

// ---------------- BN stats -> folded affine (parallel: 8 thr per h) --------
__global__ __launch_bounds__(256)
void bn_finalize(const float* __restrict__ psum, const float* __restrict__ psumsq,
                 const float* __restrict__ gamma, const float* __restrict__ beta,
                 float* __restrict__ scale, float* __restrict__ shift)
{
    __shared__ float ss[2][256];
    const int tid = threadIdx.x;
    const int hl  = tid >> 3;            // 0..31
    const int bg  = tid & 7;             // 0..7
    const int h   = blockIdx.x * 32 + hl;

    float s = 0.0f, s2 = 0.0f;
    #pragma unroll
    for (int i = 0; i < 8; ++i) {
        const int b = bg * 8 + i;
        s  += psum[b * H_DIM + h];
        s2 += psumsq[b * H_DIM + h];
    }
    ss[0][tid] = s;
    ss[1][tid] = s2;
    __syncthreads();
    if (bg == 0) {
        float S = 0.0f, S2 = 0.0f;
        #pragma unroll
        for (int i = 0; i < 8; ++i) {
            S  += ss[0][hl * 8 + i];
            S2 += ss[1][hl * 8 + i];
        }
        const float inv_n = 1.0f / (float)(T_DIM * B_DIM);
        const float mean  = S * inv_n;
        const float var   = S2 * inv_n - mean * mean;
        const float rstd  = rsqrtf(var + BN_EPS);
        const float sc    = gamma[h] * rstd;
        scale[h] = sc;
        shift[h] = fmaf(-mean, sc, beta[h]);
    }
}

// ---------------- final projection -----------------------------------------
__global__ __launch_bounds__(256)
void final_proj(const float* __restrict__ Hlast,
                const float* __restrict__ scale, const float* __restrict__ shift,
                const float* __restrict__ Wl, const float* __restrict__ bl,
                float* __restrict__ out)
{
    const int b = blockIdx.x, c = blockIdx.y;
    __shared__ float red[256];
    float s = 0.0f;
    for (int h = threadIdx.x; h < H_DIM; h += 256) {
        const float hn = fmaf(Hlast[b * H_DIM + h], scale[h], shift[h]);
        s = fmaf(hn, Wl[c * H_DIM + h], s);
    }
    red[threadIdx.x] = s;
    __syncthreads();
    for (int o = 128; o > 0; o >>= 1) {
        if (threadIdx.x < o) red[threadIdx.x] += red[threadIdx.x + o];
        __syncthreads();
    }
    if (threadIdx.x == 0) out[b * C_DIM + c] = red[0] + bl[c];
}

// ---------------- launcher --------------------------------------------------
extern "C" void kernel_launch(void* const* d_in, const int* in_sizes, int n_in,
                              void* d_out, int out_size)
{
    const float* x      = (const float*)d_in[0];
    const float* W0     = (const float*)d_in[1];
    const float* Ws     = (const float*)d_in[2];
    const float* bs     = (const float*)d_in[3];
    const float* us     = (const float*)d_in[4];
    const float* gammas = (const float*)d_in[5];
    const float* betas  = (const float*)d_in[6];
    const float* Wlast  = (const float*)d_in[7];
    const float* blast  = (const float*)d_in[8];
    float* out = (float*)d_out;

    unsigned char *apack, *bpack0, *bpackW;
    __half* z;
    float *biasadj, *psum, *psumsq, *scale, *shift, *hlast;
    cudaGetSymbolAddress((void**)&apack,   g_apack);
    cudaGetSymbolAddress((void**)&bpack0,  g_bpack0);
    cudaGetSymbolAddress((void**)&bpackW,  g_bpackW);
    cudaGetSymbolAddress((void**)&z,       g_z);
    cudaGetSymbolAddress((void**)&biasadj, g_biasadj);
    cudaGetSymbolAddress((void**)&psum,    g_psum);
    cudaGetSymbolAddress((void**)&psumsq,  g_psumsq);
    cudaGetSymbolAddress((void**)&scale,   g_scale);
    cudaGetSymbolAddress((void**)&shift,   g_shift);
    cudaGetSymbolAddress((void**)&hlast,   g_hlast);

    cudaFuncSetAttribute(gemm_mma, cudaFuncAttributeMaxDynamicSharedMemorySize, DSMEM_BYTES);

    const dim3 ggrid(H_DIM / 128, MTOT / 128);   // 16 x 64 = 1024 CTAs, 2/SM
    const int scanBlocks = (BH / 2) / 256;       // 256

    // ---- layer 0 ----
    prep_layer0<<<MTOT + H_DIM, 32>>>(x, W0, apack, bpack0);
    gemm_mma<<<ggrid, 256, DSMEM_BYTES>>>(apack, bpack0, bs, z, NC0);
    scan_pack<<<scanBlocks, 256>>>(z, us, apack, hlast, psum, psumsq, 1);
    bn_finalize<<<H_DIM / 32, 256>>>(psum, psumsq, gammas, betas, scale, shift);

    // ---- layers 1..3 ----
    for (int l = 1; l < 4; ++l) {
        prep_w<<<H_DIM, 256>>>(Ws + (size_t)(l - 1) * H_DIM * H_DIM, scale, shift,
                               bs + l * H_DIM, bpackW, biasadj);
        gemm_mma<<<ggrid, 256, DSMEM_BYTES>>>(apack, bpackW, biasadj, z, NCH);
        scan_pack<<<scanBlocks, 256>>>(z, us + l * H_DIM, apack, hlast, psum, psumsq,
                                       (l < 3) ? 1 : 0);
        bn_finalize<<<H_DIM / 32, 256>>>(psum, psumsq, gammas + l * H_DIM,
                                         betas + l * H_DIM, scale, shift);
    }

    final_proj<<<dim3(B_DIM, C_DIM), 256>>>(hlast, scale, shift, Wlast, blast, out);
}

// round 15
// speedup vs baseline: 1.7419x; 1.0188x over previous
#include <cuda_runtime.h>
#include <cuda_fp16.h>
#include <cstdint>

#define T_DIM  128
#define B_DIM  64
#define IN_RAW 144
#define H_DIM  2048
#define C_DIM  10
#define BN_EPS 1e-5f
#define MTOT   (T_DIM*B_DIM)   // 8192
#define BH     (B_DIM*H_DIM)   // 131072
#define NC0    5               // layer0 K=144 padded to 160 = 5 chunks of 32
#define NCH    64              // 2048/32

// GEMM tile: BM=BN=128, KC=32 fp16 (64B rows, SW64); 256 thr (8 warps, 2x4, 64x32)
#define CHUNK_A 16384          // A: hi+lo fp16 planes (8KB each)
#define CHUNK_B 8192           // B: single fp16 plane
#define STAGE_BYTES (CHUNK_A + CHUNK_B)    // 24576
#define NSTAGE 4
#define DSMEM_BYTES (NSTAGE*STAGE_BYTES)   // 98304/CTA -> 2 CTAs = 192KB

// ---------------- scratch (allocation-free device globals) -----------------
__device__ __align__(128) unsigned char g_apack[64u*64u*CHUNK_A];     // 64MB
__device__ __align__(128) unsigned char g_bpack0[16u*NC0*CHUNK_B];
__device__ __align__(128) unsigned char g_bpackW[16u*NCH*CHUNK_B];    // 8MB, per-layer
__device__ __half g_z[MTOT*H_DIM];      // 32MB (fp16 pre-activation)
__device__ float g_biasadj[H_DIM];
__device__ float g_psum[BH];
__device__ float g_psumsq[BH];
__device__ float g_scale[H_DIM];
__device__ float g_shift[H_DIM];
__device__ float g_hlast[BH];

// ---------------- PTX helpers ----------------
__device__ __forceinline__ uint32_t smem_u32(const void* p) {
    uint32_t a;
    asm("{ .reg .u64 t; cvta.to.shared.u64 t, %1; cvt.u32.u64 %0, t; }" : "=r"(a) : "l"(p));
    return a;
}
__device__ __forceinline__ void bulk_g2s(uint32_t dst, const void* src,
                                         uint32_t bytes, uint32_t mbar) {
    asm volatile(
        "cp.async.bulk.shared::cluster.global.mbarrier::complete_tx::bytes [%0], [%1], %2, [%3];"
        :: "r"(dst), "l"(src), "r"(bytes), "r"(mbar) : "memory");
}
#define MBAR_INIT(a, c) asm volatile("mbarrier.init.shared.b64 [%0], %1;" :: "r"(a), "r"(c) : "memory")
#define MBAR_EXPECT_TX(a, b) asm volatile("mbarrier.arrive.expect_tx.shared.b64 _, [%0], %1;" :: "r"(a), "r"(b) : "memory")
#define FENCE_ASYNC() asm volatile("fence.proxy.async.shared::cta;" ::: "memory")
#define MBAR_WAIT(a, ph) do { \
    uint32_t _done; \
    asm volatile("{\n\t.reg .pred p;\n\tmbarrier.try_wait.parity.acquire.cta.shared::cta.b64 p, [%1], %2;\n\tselp.b32 %0,1,0,p;\n\t}" \
        : "=r"(_done) : "r"(a), "r"(ph) : "memory"); \
    if (!_done) { \
        asm volatile("{\n\t.reg .pred P1;\n\tWL_%=:\n\tmbarrier.try_wait.parity.acquire.cta.shared::cta.b64 P1, [%0], %1, 0x989680;\n\t@P1 bra.uni WD_%=;\n\tbra.uni WL_%=;\n\tWD_%=:\n\t}" \
            :: "r"(a), "r"(ph) : "memory"); \
    } \
} while (0)

__device__ __forceinline__ void ldsm4(uint32_t r[4], uint32_t addr) {
    asm volatile("ldmatrix.sync.aligned.m8n8.x4.shared.b16 {%0,%1,%2,%3}, [%4];"
        : "=r"(r[0]), "=r"(r[1]), "=r"(r[2]), "=r"(r[3]) : "r"(addr));
}
__device__ __forceinline__ void mma16816(float c[4], const uint32_t a[4],
                                         uint32_t b0, uint32_t b1) {
    asm volatile(
        "mma.sync.aligned.m16n8k16.row.col.f32.f16.f16.f32 "
        "{%0,%1,%2,%3}, {%4,%5,%6,%7}, {%8,%9}, {%0,%1,%2,%3};"
        : "+f"(c[0]), "+f"(c[1]), "+f"(c[2]), "+f"(c[3])
        : "r"(a[0]), "r"(a[1]), "r"(a[2]), "r"(a[3]), "r"(b0), "r"(b1));
}

// SW64 swizzled byte offset inside one 128-row x 64B plane
__device__ __forceinline__ uint32_t sw64_off(int row, int colBytes) {
    return (uint32_t)row * 64 + (((uint32_t)colBytes) ^ (uint32_t)(((row >> 1) & 3) << 4));
}

// A: split 8 fp32 -> fp16 hi/lo planes (8KB apart)
__device__ __forceinline__ void split_store8(unsigned char* base, uint32_t off,
                                             const float v[8]) {
    union { uint4 q; unsigned short us[8]; } Hq, Lq;
    #pragma unroll
    for (int i = 0; i < 8; ++i) {
        __half h = __float2half(v[i]);
        Hq.us[i] = __half_as_ushort(h);
        Lq.us[i] = __half_as_ushort(__float2half(v[i] - __half2float(h)));
    }
    *reinterpret_cast<uint4*>(base + off)        = Hq.q;
    *reinterpret_cast<uint4*>(base + off + 8192) = Lq.q;
}
// B: 8 fp32 -> single fp16 plane
__device__ __forceinline__ void half_store8(unsigned char* base, uint32_t off,
                                            const float v[8]) {
    union { uint4 q; unsigned short us[8]; } Hq;
    #pragma unroll
    for (int i = 0; i < 8; ++i) Hq.us[i] = __half_as_ushort(__float2half(v[i]));
    *reinterpret_cast<uint4*>(base + off) = Hq.q;
}

// ---------------- GEMM: Z = A@W^T + bias (fp16 2-product split) ------------
__global__ __launch_bounds__(256, 2)
void gemm_mma(const unsigned char* __restrict__ apack,
              const unsigned char* __restrict__ bpack,
              const float* __restrict__ bias, __half* __restrict__ Z, int NC)
{
    extern __shared__ unsigned char dyn[];
    __shared__ __align__(8) uint64_t mbar_s[NSTAGE];
    const uint32_t sb = smem_u32(dyn);
    const uint32_t mb = smem_u32(mbar_s);

    const int tid  = threadIdx.x;
    const int lane = tid & 31;
    const int wid  = tid >> 5;
    const int wm   = wid >> 2;
    const int wn   = wid & 3;
    const int nblk = blockIdx.x;
    const int mblk = blockIdx.y;

    const unsigned char* aSrc = apack + (size_t)mblk * NC * CHUNK_A;
    const unsigned char* bSrc = bpack + (size_t)nblk * NC * CHUNK_B;

    if (tid == 0) {
        #pragma unroll
        for (int s = 0; s < NSTAGE; ++s) MBAR_INIT(mb + 8 * s, 1);
        FENCE_ASYNC();
    }
    __syncthreads();
    if (tid == 0) {
        #pragma unroll
        for (int s = 0; s < NSTAGE; ++s) {
            if (s < NC) {
                MBAR_EXPECT_TX(mb + 8 * s, STAGE_BYTES);
                bulk_g2s(sb + s * STAGE_BYTES,           aSrc + (size_t)s * CHUNK_A, CHUNK_A, mb + 8 * s);
                bulk_g2s(sb + s * STAGE_BYTES + CHUNK_A, bSrc + (size_t)s * CHUNK_B, CHUNK_B, mb + 8 * s);
            }
        }
    }

    const int rowA  = wm * 64 + (lane & 15);
    const int rowB  = wn * 32 + ((lane >> 4) << 3) + (lane & 7);
    const uint32_t xorA = (uint32_t)(((rowA >> 1) & 3) << 4);
    const uint32_t xorB = (uint32_t)(((rowB >> 1) & 3) << 4);
    const uint32_t colA0 = (uint32_t)((lane >> 4) * 16);
    const uint32_t colB0 = (uint32_t)(((lane >> 3) & 1) * 16);
    const uint32_t baseA = (uint32_t)rowA * 64;
    const uint32_t baseB = (uint32_t)rowB * 64;

    float acc[4][4][4];
    #pragma unroll
    for (int i = 0; i < 4; ++i)
        #pragma unroll
        for (int j = 0; j < 4; ++j)
            #pragma unroll
            for (int q = 0; q < 4; ++q) acc[i][j][q] = 0.0f;

    int ph[NSTAGE] = {0, 0, 0, 0};
    for (int c = 0; c < NC; ++c) {
        const int s = c & (NSTAGE - 1);
        MBAR_WAIT(mb + 8 * s, ph[s]);
        ph[s] ^= 1;
        const uint32_t st = sb + s * STAGE_BYTES;

        #pragma unroll
        for (int kk = 0; kk < 2; ++kk) {
            const uint32_t cA = (uint32_t)(kk * 32 + colA0) ^ xorA;
            const uint32_t cB = (uint32_t)(kk * 32 + colB0) ^ xorB;
            uint32_t ah[4][4], al[4][4], bb[2][4];
            #pragma unroll
            for (int mi = 0; mi < 4; ++mi) {
                const uint32_t ra = baseA + (uint32_t)mi * 1024;
                ldsm4(ah[mi], st + ra + cA);
                ldsm4(al[mi], st + 8192 + ra + cA);
            }
            #pragma unroll
            for (int nj = 0; nj < 2; ++nj)
                ldsm4(bb[nj], st + CHUNK_A + baseB + (uint32_t)nj * 1024 + cB);
            #pragma unroll
            for (int nj = 0; nj < 2; ++nj) {
                #pragma unroll
                for (int mi = 0; mi < 4; ++mi) {
                    mma16816(acc[mi][nj*2],   ah[mi], bb[nj][0], bb[nj][1]);
                    mma16816(acc[mi][nj*2+1], ah[mi], bb[nj][2], bb[nj][3]);
                }
                #pragma unroll
                for (int mi = 0; mi < 4; ++mi) {
                    mma16816(acc[mi][nj*2],   al[mi], bb[nj][0], bb[nj][1]);
                    mma16816(acc[mi][nj*2+1], al[mi], bb[nj][2], bb[nj][3]);
                }
            }
        }
        __syncthreads();
        if (c + NSTAGE < NC && tid == 0) {
            MBAR_EXPECT_TX(mb + 8 * s, STAGE_BYTES);
            bulk_g2s(st,           aSrc + (size_t)(c + NSTAGE) * CHUNK_A, CHUNK_A, mb + 8 * s);
            bulk_g2s(st + CHUNK_A, bSrc + (size_t)(c + NSTAGE) * CHUNK_B, CHUNK_B, mb + 8 * s);
        }
    }

    // epilogue: + bias, store fp16 z
    const int g  = lane >> 2;
    const int tg = lane & 3;
    #pragma unroll
    for (int mi = 0; mi < 4; ++mi) {
        const int r0 = mblk * 128 + wm * 64 + mi * 16 + g;
        #pragma unroll
        for (int ni = 0; ni < 4; ++ni) {
            const int n = nblk * 128 + wn * 32 + ni * 8 + tg * 2;
            const float2 bia = *reinterpret_cast<const float2*>(&bias[n]);
            const __half2 v0 = __floats2half2_rn(acc[mi][ni][0] + bia.x,
                                                 acc[mi][ni][1] + bia.y);
            const __half2 v1 = __floats2half2_rn(acc[mi][ni][2] + bia.x,
                                                 acc[mi][ni][3] + bia.y);
            *reinterpret_cast<__half2*>(&Z[(size_t)r0 * H_DIM + n])       = v0;
            *reinterpret_cast<__half2*>(&Z[(size_t)(r0 + 8) * H_DIM + n]) = v1;
        }
    }
}

// ---------------- layer-0 prep: x pack + W0 pack in ONE launch -------------
__global__ __launch_bounds__(32)
void prep_layer0(const float* __restrict__ x, const float* __restrict__ W0,
                 unsigned char* __restrict__ apack, unsigned char* __restrict__ bpack)
{
    const int blk = blockIdx.x;
    const int k0 = threadIdx.x * 8;
    if (k0 >= NC0 * 32) return;       // 160
    if (blk < MTOT) {
        const int m = blk;
        float v[8];
        if (k0 < IN_RAW) {
            *reinterpret_cast<float4*>(&v[0]) = *reinterpret_cast<const float4*>(&x[(size_t)m * IN_RAW + k0]);
            *reinterpret_cast<float4*>(&v[4]) = *reinterpret_cast<const float4*>(&x[(size_t)m * IN_RAW + k0 + 4]);
        } else {
            #pragma unroll
            for (int i = 0; i < 8; ++i) v[i] = 0.0f;
        }
        const int mblk = m >> 7, row = m & 127, kc = k0 >> 5;
        split_store8(apack + (size_t)(mblk * NC0 + kc) * CHUNK_A,
                     sw64_off(row, (k0 & 31) * 2), v);
    } else {
        const int n = blk - MTOT;
        float v[8];
        if (k0 < IN_RAW) {
            *reinterpret_cast<float4*>(&v[0]) = *reinterpret_cast<const float4*>(&W0[(size_t)n * IN_RAW + k0]);
            *reinterpret_cast<float4*>(&v[4]) = *reinterpret_cast<const float4*>(&W0[(size_t)n * IN_RAW + k0 + 4]);
        } else {
            #pragma unroll
            for (int i = 0; i < 8; ++i) v[i] = 0.0f;
        }
        const int nblk = n >> 7, row = n & 127, kc = k0 >> 5;
        half_store8(bpack + (size_t)(nblk * NC0 + kc) * CHUNK_B,
                    sw64_off(row, (k0 & 31) * 2), v);
    }
}

// ---------------- per-layer weight prep: fold BN scale into W, shift into bias
__global__ __launch_bounds__(256)
void prep_w(const float* __restrict__ W, const float* __restrict__ scale,
            const float* __restrict__ shift, const float* __restrict__ bias_in,
            unsigned char* __restrict__ bpack, float* __restrict__ biasadj)
{
    __shared__ float red[8];
    const int n = blockIdx.x;
    const int tid = threadIdx.x;
    const int lane = tid & 31;
    const int wrp  = tid >> 5;
    const int k0 = tid * 8;

    float w[8], v[8], sc[8], sh[8];
    const float* wrow = W + (size_t)n * H_DIM + k0;
    *reinterpret_cast<float4*>(&w[0])  = *reinterpret_cast<const float4*>(wrow);
    *reinterpret_cast<float4*>(&w[4])  = *reinterpret_cast<const float4*>(wrow + 4);
    *reinterpret_cast<float4*>(&sc[0]) = *reinterpret_cast<const float4*>(&scale[k0]);
    *reinterpret_cast<float4*>(&sc[4]) = *reinterpret_cast<const float4*>(&scale[k0 + 4]);
    *reinterpret_cast<float4*>(&sh[0]) = *reinterpret_cast<const float4*>(&shift[k0]);
    *reinterpret_cast<float4*>(&sh[4]) = *reinterpret_cast<const float4*>(&shift[k0 + 4]);

    float s = 0.0f;
    #pragma unroll
    for (int i = 0; i < 8; ++i) {
        v[i] = w[i] * sc[i];
        s = fmaf(sh[i], w[i], s);
    }
    const int nblk = n >> 7, row = n & 127, kc = k0 >> 5;
    half_store8(bpack + (size_t)(nblk * NCH + kc) * CHUNK_B,
                sw64_off(row, (k0 & 31) * 2), v);

    #pragma unroll
    for (int o = 16; o > 0; o >>= 1) s += __shfl_xor_sync(0xFFFFFFFFu, s, o);
    if (lane == 0) red[wrp] = s;
    __syncthreads();
    if (tid == 0) {
        float t = 0.0f;
        #pragma unroll
        for (int i = 0; i < 8; ++i) t += red[i];
        biasadj[n] = bias_in[n] + t;
    }
}

// ---------------- IndRNN scan: fp16 z, 16-deep z prefetch, packs raw-h A ---
__global__ __launch_bounds__(256)
void scan_pack(const __half* __restrict__ Z, const float* __restrict__ u,
               unsigned char* __restrict__ apack, float* __restrict__ hlast,
               float* __restrict__ psum, float* __restrict__ psumsq, int writeA)
{
    const int j2 = blockIdx.x * 256 + threadIdx.x;   // 0..65535 (h-pair index)
    const int b  = j2 >> 10;                         // 0..63
    const int h0 = (j2 & 1023) * 2;                  // even h
    const int kc = h0 >> 5;
    const int colB = (h0 & 31) * 2;

    const float2 uh = *reinterpret_cast<const float2*>(&u[h0]);
    float hc0 = 0.0f, hc1 = 0.0f, s0 = 0.0f, s1 = 0.0f, q0 = 0.0f, q1 = 0.0f;

    const __half2* zp = reinterpret_cast<const __half2*>(Z + (size_t)b * H_DIM + h0);
    unsigned char* chunkBase = apack + (size_t)kc * CHUNK_A;
    const uint32_t swc = (uint32_t)colB;

    #pragma unroll 1
    for (int tb = 0; tb < T_DIM; tb += 16) {
        // batch-issue 16 independent streaming loads (MLP=16)
        __half2 zl[16];
        #pragma unroll
        for (int i = 0; i < 16; ++i)
            zl[i] = __ldcs(zp + (size_t)(tb + i) * (BH / 2));
        #pragma unroll
        for (int i = 0; i < 16; ++i) {
            const int t = tb + i;
            const float2 zv = __half22float2(zl[i]);
            hc0 = fmaxf(fmaf(uh.x, hc0, zv.x), 0.0f);
            hc1 = fmaxf(fmaf(uh.y, hc1, zv.y), 0.0f);
            s0 += hc0; s1 += hc1;
            q0 = fmaf(hc0, hc0, q0); q1 = fmaf(hc1, hc1, q1);
            if (writeA) {
                const int m = t * B_DIM + b;
                const int mblk = m >> 7, row = m & 127;
                const __half h0h = __float2half(hc0);
                const __half h1h = __float2half(hc1);
                const uint32_t hi = (uint32_t)__half_as_ushort(h0h)
                                  | ((uint32_t)__half_as_ushort(h1h) << 16);
                const uint32_t lo = (uint32_t)__half_as_ushort(__float2half(hc0 - __half2float(h0h)))
                                  | ((uint32_t)__half_as_ushort(__float2half(hc1 - __half2float(h1h))) << 16);
                unsigned char* d = chunkBase + (size_t)mblk * (NCH * CHUNK_A)
                                 + (uint32_t)row * 64
                                 + (swc ^ (uint32_t)(((row >> 1) & 3) << 4));
                *reinterpret_cast<uint32_t*>(d)        = hi;
                *reinterpret_cast<uint32_t*>(d + 8192) = lo;
            }
        }
    }
    const int j = b * H_DIM + h0;
    *reinterpret_cast<float2*>(&hlast[j])  = make_float2(hc0, hc1);
    *reinterpret_cast<float2*>(&psum[j])   = make_float2(s0, s1);
    *reinterpret_cast<float2*>(&psumsq[j]) = make_float2(q0, q1);
}

// ---------------- BN stats -> folded affine (16 thr per h, 4 b each) -------
__global__ __launch_bounds__(256)
void bn_finalize(const float* __restrict__ psum, const float* __restrict__ psumsq,
                 const float* __restrict__ gamma, const float* __restrict__ beta,
                 float* __restrict__ scale, float* __restrict__ shift)
{
    __shared__ float ss[2][256];
    const int tid = threadIdx.x;
    const int hl  = tid >> 4;            // 0..15
    const int bg  = tid & 15;            // 0..15
    const int h   = blockIdx.x * 16 + hl;

    float s = 0.0f, s2 = 0.0f;
    #pragma unroll
    for (int i = 0; i < 4; ++i) {
        const int b = bg * 4 + i;
        s  += psum[b * H_DIM + h];
        s2 += psumsq[b * H_DIM + h];
    }
    ss[0][tid] = s;
    ss[1][tid] = s2;
    __syncthreads();
    if (bg == 0) {
        float S = 0.0f, S2 = 0.0f;
        #pragma unroll
        for (int i = 0; i < 16; ++i) {
            S  += ss[0][hl * 16 + i];
            S2 += ss[1][hl * 16 + i];
        }
        const float inv_n = 1.0f / (float)(T_DIM * B_DIM);
        const float mean  = S * inv_n;
        const float var   = S2 * inv_n - mean * mean;
        const float rstd  = rsqrtf(var + BN_EPS);
        const float sc    = gamma[h] * rstd;
        scale[h] = sc;
        shift[h] = fmaf(-mean, sc, beta[h]);
    }
}

// ---------------- final projection -----------------------------------------
__global__ __launch_bounds__(256)
void final_proj(const float* __restrict__ Hlast,
                const float* __restrict__ scale, const float* __restrict__ shift,
                const float* __restrict__ Wl, const float* __restrict__ bl,
                float* __restrict__ out)
{
    const int b = blockIdx.x, c = blockIdx.y;
    __shared__ float red[256];
    float s = 0.0f;
    for (int h = threadIdx.x; h < H_DIM; h += 256) {
        const float hn = fmaf(Hlast[b * H_DIM + h], scale[h], shift[h]);
        s = fmaf(hn, Wl[c * H_DIM + h], s);
    }
    red[threadIdx.x] = s;
    __syncthreads();
    for (int o = 128; o > 0; o >>= 1) {
        if (threadIdx.x < o) red[threadIdx.x] += red[threadIdx.x + o];
        __syncthreads();
    }
    if (threadIdx.x == 0) out[b * C_DIM + c] = red[0] + bl[c];
}

// ---------------- launcher --------------------------------------------------
extern "C" void kernel_launch(void* const* d_in, const int* in_sizes, int n_in,
                              void* d_out, int out_size)
{
    const float* x      = (const float*)d_in[0];
    const float* W0     = (const float*)d_in[1];
    const float* Ws     = (const float*)d_in[2];
    const float* bs     = (const float*)d_in[3];
    const float* us     = (const float*)d_in[4];
    const float* gammas = (const float*)d_in[5];
    const float* betas  = (const float*)d_in[6];
    const float* Wlast  = (const float*)d_in[7];
    const float* blast  = (const float*)d_in[8];
    float* out = (float*)d_out;

    unsigned char *apack, *bpack0, *bpackW;
    __half* z;
    float *biasadj, *psum, *psumsq, *scale, *shift, *hlast;
    cudaGetSymbolAddress((void**)&apack,   g_apack);
    cudaGetSymbolAddress((void**)&bpack0,  g_bpack0);
    cudaGetSymbolAddress((void**)&bpackW,  g_bpackW);
    cudaGetSymbolAddress((void**)&z,       g_z);
    cudaGetSymbolAddress((void**)&biasadj, g_biasadj);
    cudaGetSymbolAddress((void**)&psum,    g_psum);
    cudaGetSymbolAddress((void**)&psumsq,  g_psumsq);
    cudaGetSymbolAddress((void**)&scale,   g_scale);
    cudaGetSymbolAddress((void**)&shift,   g_shift);
    cudaGetSymbolAddress((void**)&hlast,   g_hlast);

    cudaFuncSetAttribute(gemm_mma, cudaFuncAttributeMaxDynamicSharedMemorySize, DSMEM_BYTES);

    const dim3 ggrid(H_DIM / 128, MTOT / 128);   // 16 x 64 = 1024 CTAs, 2/SM
    const int scanBlocks = (BH / 2) / 256;       // 256

    // ---- layer 0 ----
    prep_layer0<<<MTOT + H_DIM, 32>>>(x, W0, apack, bpack0);
    gemm_mma<<<ggrid, 256, DSMEM_BYTES>>>(apack, bpack0, bs, z, NC0);
    scan_pack<<<scanBlocks, 256>>>(z, us, apack, hlast, psum, psumsq, 1);
    bn_finalize<<<H_DIM / 16, 256>>>(psum, psumsq, gammas, betas, scale, shift);

    // ---- layers 1..3 ----
    for (int l = 1; l < 4; ++l) {
        prep_w<<<H_DIM, 256>>>(Ws + (size_t)(l - 1) * H_DIM * H_DIM, scale, shift,
                               bs + l * H_DIM, bpackW, biasadj);
        gemm_mma<<<ggrid, 256, DSMEM_BYTES>>>(apack, bpackW, biasadj, z, NCH);
        scan_pack<<<scanBlocks, 256>>>(z, us + l * H_DIM, apack, hlast, psum, psumsq,
                                       (l < 3) ? 1 : 0);
        bn_finalize<<<H_DIM / 16, 256>>>(psum, psumsq, gammas + l * H_DIM,
                                         betas + l * H_DIM, scale, shift);
    }

    final_proj<<<dim3(B_DIM, C_DIM), 256>>>(hlast, scale, shift, Wlast, blast, out);
}

// round 16
// speedup vs baseline: 1.7431x; 1.0007x over previous
#include <cuda_runtime.h>
#include <cuda_fp16.h>
#include <cstdint>

#define T_DIM  128
#define B_DIM  64
#define IN_RAW 144
#define H_DIM  2048
#define C_DIM  10
#define BN_EPS 1e-5f
#define MTOT   (T_DIM*B_DIM)   // 8192
#define BH     (B_DIM*H_DIM)   // 131072
#define NC0    5               // layer0 K=144 padded to 160 = 5 chunks of 32
#define NCH    64              // 2048/32

// GEMM tile: BM=BN=128, KC=32 fp16 (64B rows, SW64); 256 thr (8 warps, 2x4, 64x32)
#define CHUNK_A 16384          // A: hi+lo fp16 planes (8KB each)
#define CHUNK_B 8192           // B: single fp16 plane
#define STAGE_BYTES (CHUNK_A + CHUNK_B)    // 24576
#define NSTAGE 4
#define DSMEM_BYTES (NSTAGE*STAGE_BYTES)   // 98304/CTA -> 2 CTAs = 192KB

// ---------------- scratch (allocation-free device globals) -----------------
__device__ __align__(128) unsigned char g_apack[64u*64u*CHUNK_A];     // 64MB
__device__ __align__(128) unsigned char g_bpack0[16u*NC0*CHUNK_B];
__device__ __align__(128) unsigned char g_bpackW[16u*NCH*CHUNK_B];    // 8MB, per-layer
__device__ __half g_z[MTOT*H_DIM];      // 32MB (fp16 pre-activation)
__device__ float g_biasadj[H_DIM];
__device__ float g_psum[BH];
__device__ float g_psumsq[BH];
__device__ float g_scale[H_DIM];
__device__ float g_shift[H_DIM];
__device__ float g_hlast[BH];

// ---------------- PTX helpers ----------------
__device__ __forceinline__ uint32_t smem_u32(const void* p) {
    uint32_t a;
    asm("{ .reg .u64 t; cvta.to.shared.u64 t, %1; cvt.u32.u64 %0, t; }" : "=r"(a) : "l"(p));
    return a;
}
__device__ __forceinline__ void bulk_g2s(uint32_t dst, const void* src,
                                         uint32_t bytes, uint32_t mbar) {
    asm volatile(
        "cp.async.bulk.shared::cluster.global.mbarrier::complete_tx::bytes [%0], [%1], %2, [%3];"
        :: "r"(dst), "l"(src), "r"(bytes), "r"(mbar) : "memory");
}
#define MBAR_INIT(a, c) asm volatile("mbarrier.init.shared.b64 [%0], %1;" :: "r"(a), "r"(c) : "memory")
#define MBAR_EXPECT_TX(a, b) asm volatile("mbarrier.arrive.expect_tx.shared.b64 _, [%0], %1;" :: "r"(a), "r"(b) : "memory")
#define FENCE_ASYNC() asm volatile("fence.proxy.async.shared::cta;" ::: "memory")
#define MBAR_WAIT(a, ph) do { \
    uint32_t _done; \
    asm volatile("{\n\t.reg .pred p;\n\tmbarrier.try_wait.parity.acquire.cta.shared::cta.b64 p, [%1], %2;\n\tselp.b32 %0,1,0,p;\n\t}" \
        : "=r"(_done) : "r"(a), "r"(ph) : "memory"); \
    if (!_done) { \
        asm volatile("{\n\t.reg .pred P1;\n\tWL_%=:\n\tmbarrier.try_wait.parity.acquire.cta.shared::cta.b64 P1, [%0], %1, 0x989680;\n\t@P1 bra.uni WD_%=;\n\tbra.uni WL_%=;\n\tWD_%=:\n\t}" \
            :: "r"(a), "r"(ph) : "memory"); \
    } \
} while (0)

__device__ __forceinline__ void ldsm4(uint32_t r[4], uint32_t addr) {
    asm volatile("ldmatrix.sync.aligned.m8n8.x4.shared.b16 {%0,%1,%2,%3}, [%4];"
        : "=r"(r[0]), "=r"(r[1]), "=r"(r[2]), "=r"(r[3]) : "r"(addr));
}
__device__ __forceinline__ void mma16816(float c[4], const uint32_t a[4],
                                         uint32_t b0, uint32_t b1) {
    asm volatile(
        "mma.sync.aligned.m16n8k16.row.col.f32.f16.f16.f32 "
        "{%0,%1,%2,%3}, {%4,%5,%6,%7}, {%8,%9}, {%0,%1,%2,%3};"
        : "+f"(c[0]), "+f"(c[1]), "+f"(c[2]), "+f"(c[3])
        : "r"(a[0]), "r"(a[1]), "r"(a[2]), "r"(a[3]), "r"(b0), "r"(b1));
}

// SW64 swizzled byte offset inside one 128-row x 64B plane
__device__ __forceinline__ uint32_t sw64_off(int row, int colBytes) {
    return (uint32_t)row * 64 + (((uint32_t)colBytes) ^ (uint32_t)(((row >> 1) & 3) << 4));
}

// A: split 8 fp32 -> fp16 hi/lo planes (8KB apart)
__device__ __forceinline__ void split_store8(unsigned char* base, uint32_t off,
                                             const float v[8]) {
    union { uint4 q; unsigned short us[8]; } Hq, Lq;
    #pragma unroll
    for (int i = 0; i < 8; ++i) {
        __half h = __float2half(v[i]);
        Hq.us[i] = __half_as_ushort(h);
        Lq.us[i] = __half_as_ushort(__float2half(v[i] - __half2float(h)));
    }
    *reinterpret_cast<uint4*>(base + off)        = Hq.q;
    *reinterpret_cast<uint4*>(base + off + 8192) = Lq.q;
}
// B: 8 fp32 -> single fp16 plane
__device__ __forceinline__ void half_store8(unsigned char* base, uint32_t off,
                                            const float v[8]) {
    union { uint4 q; unsigned short us[8]; } Hq;
    #pragma unroll
    for (int i = 0; i < 8; ++i) Hq.us[i] = __half_as_ushort(__float2half(v[i]));
    *reinterpret_cast<uint4*>(base + off) = Hq.q;
}

// ---------------- GEMM: Z = A@W^T + bias (fp16 2-product split) ------------
__global__ __launch_bounds__(256, 2)
void gemm_mma(const unsigned char* __restrict__ apack,
              const unsigned char* __restrict__ bpack,
              const float* __restrict__ bias, __half* __restrict__ Z, int NC)
{
    extern __shared__ unsigned char dyn[];
    __shared__ __align__(8) uint64_t mbar_s[NSTAGE];
    const uint32_t sb = smem_u32(dyn);
    const uint32_t mb = smem_u32(mbar_s);

    const int tid  = threadIdx.x;
    const int lane = tid & 31;
    const int wid  = tid >> 5;
    const int wm   = wid >> 2;
    const int wn   = wid & 3;
    const int nblk = blockIdx.x;
    const int mblk = blockIdx.y;

    const unsigned char* aSrc = apack + (size_t)mblk * NC * CHUNK_A;
    const unsigned char* bSrc = bpack + (size_t)nblk * NC * CHUNK_B;

    if (tid == 0) {
        #pragma unroll
        for (int s = 0; s < NSTAGE; ++s) MBAR_INIT(mb + 8 * s, 1);
        FENCE_ASYNC();
    }
    __syncthreads();
    if (tid == 0) {
        #pragma unroll
        for (int s = 0; s < NSTAGE; ++s) {
            if (s < NC) {
                MBAR_EXPECT_TX(mb + 8 * s, STAGE_BYTES);
                bulk_g2s(sb + s * STAGE_BYTES,           aSrc + (size_t)s * CHUNK_A, CHUNK_A, mb + 8 * s);
                bulk_g2s(sb + s * STAGE_BYTES + CHUNK_A, bSrc + (size_t)s * CHUNK_B, CHUNK_B, mb + 8 * s);
            }
        }
    }

    const int rowA  = wm * 64 + (lane & 15);
    const int rowB  = wn * 32 + ((lane >> 4) << 3) + (lane & 7);
    const uint32_t xorA = (uint32_t)(((rowA >> 1) & 3) << 4);
    const uint32_t xorB = (uint32_t)(((rowB >> 1) & 3) << 4);
    const uint32_t colA0 = (uint32_t)((lane >> 4) * 16);
    const uint32_t colB0 = (uint32_t)(((lane >> 3) & 1) * 16);
    const uint32_t baseA = (uint32_t)rowA * 64;
    const uint32_t baseB = (uint32_t)rowB * 64;

    float acc[4][4][4];
    #pragma unroll
    for (int i = 0; i < 4; ++i)
        #pragma unroll
        for (int j = 0; j < 4; ++j)
            #pragma unroll
            for (int q = 0; q < 4; ++q) acc[i][j][q] = 0.0f;

    int ph[NSTAGE] = {0, 0, 0, 0};
    for (int c = 0; c < NC; ++c) {
        const int s = c & (NSTAGE - 1);
        MBAR_WAIT(mb + 8 * s, ph[s]);
        ph[s] ^= 1;
        const uint32_t st = sb + s * STAGE_BYTES;

        #pragma unroll
        for (int kk = 0; kk < 2; ++kk) {
            const uint32_t cA = (uint32_t)(kk * 32 + colA0) ^ xorA;
            const uint32_t cB = (uint32_t)(kk * 32 + colB0) ^ xorB;
            uint32_t ah[4][4], al[4][4], bb[2][4];
            #pragma unroll
            for (int mi = 0; mi < 4; ++mi) {
                const uint32_t ra = baseA + (uint32_t)mi * 1024;
                ldsm4(ah[mi], st + ra + cA);
                ldsm4(al[mi], st + 8192 + ra + cA);
            }
            #pragma unroll
            for (int nj = 0; nj < 2; ++nj)
                ldsm4(bb[nj], st + CHUNK_A + baseB + (uint32_t)nj * 1024 + cB);
            #pragma unroll
            for (int nj = 0; nj < 2; ++nj) {
                #pragma unroll
                for (int mi = 0; mi < 4; ++mi) {
                    mma16816(acc[mi][nj*2],   ah[mi], bb[nj][0], bb[nj][1]);
                    mma16816(acc[mi][nj*2+1], ah[mi], bb[nj][2], bb[nj][3]);
                }
                #pragma unroll
                for (int mi = 0; mi < 4; ++mi) {
                    mma16816(acc[mi][nj*2],   al[mi], bb[nj][0], bb[nj][1]);
                    mma16816(acc[mi][nj*2+1], al[mi], bb[nj][2], bb[nj][3]);
                }
            }
        }
        __syncthreads();
        if (c + NSTAGE < NC && tid == 0) {
            MBAR_EXPECT_TX(mb + 8 * s, STAGE_BYTES);
            bulk_g2s(st,           aSrc + (size_t)(c + NSTAGE) * CHUNK_A, CHUNK_A, mb + 8 * s);
            bulk_g2s(st + CHUNK_A, bSrc + (size_t)(c + NSTAGE) * CHUNK_B, CHUNK_B, mb + 8 * s);
        }
    }

    // epilogue: + bias, store fp16 z
    const int g  = lane >> 2;
    const int tg = lane & 3;
    #pragma unroll
    for (int mi = 0; mi < 4; ++mi) {
        const int r0 = mblk * 128 + wm * 64 + mi * 16 + g;
        #pragma unroll
        for (int ni = 0; ni < 4; ++ni) {
            const int n = nblk * 128 + wn * 32 + ni * 8 + tg * 2;
            const float2 bia = *reinterpret_cast<const float2*>(&bias[n]);
            const __half2 v0 = __floats2half2_rn(acc[mi][ni][0] + bia.x,
                                                 acc[mi][ni][1] + bia.y);
            const __half2 v1 = __floats2half2_rn(acc[mi][ni][2] + bia.x,
                                                 acc[mi][ni][3] + bia.y);
            *reinterpret_cast<__half2*>(&Z[(size_t)r0 * H_DIM + n])       = v0;
            *reinterpret_cast<__half2*>(&Z[(size_t)(r0 + 8) * H_DIM + n]) = v1;
        }
    }
}

// ---------------- layer-0 prep: x pack + W0 pack in ONE launch -------------
__global__ __launch_bounds__(32)
void prep_layer0(const float* __restrict__ x, const float* __restrict__ W0,
                 unsigned char* __restrict__ apack, unsigned char* __restrict__ bpack)
{
    const int blk = blockIdx.x;
    const int k0 = threadIdx.x * 8;
    if (k0 >= NC0 * 32) return;       // 160
    if (blk < MTOT) {
        const int m = blk;
        float v[8];
        if (k0 < IN_RAW) {
            *reinterpret_cast<float4*>(&v[0]) = *reinterpret_cast<const float4*>(&x[(size_t)m * IN_RAW + k0]);
            *reinterpret_cast<float4*>(&v[4]) = *reinterpret_cast<const float4*>(&x[(size_t)m * IN_RAW + k0 + 4]);
        } else {
            #pragma unroll
            for (int i = 0; i < 8; ++i) v[i] = 0.0f;
        }
        const int mblk = m >> 7, row = m & 127, kc = k0 >> 5;
        split_store8(apack + (size_t)(mblk * NC0 + kc) * CHUNK_A,
                     sw64_off(row, (k0 & 31) * 2), v);
    } else {
        const int n = blk - MTOT;
        float v[8];
        if (k0 < IN_RAW) {
            *reinterpret_cast<float4*>(&v[0]) = *reinterpret_cast<const float4*>(&W0[(size_t)n * IN_RAW + k0]);
            *reinterpret_cast<float4*>(&v[4]) = *reinterpret_cast<const float4*>(&W0[(size_t)n * IN_RAW + k0 + 4]);
        } else {
            #pragma unroll
            for (int i = 0; i < 8; ++i) v[i] = 0.0f;
        }
        const int nblk = n >> 7, row = n & 127, kc = k0 >> 5;
        half_store8(bpack + (size_t)(nblk * NC0 + kc) * CHUNK_B,
                    sw64_off(row, (k0 & 31) * 2), v);
    }
}

// ---------------- per-layer weight prep: fold BN scale into W, shift into bias
__global__ __launch_bounds__(256)
void prep_w(const float* __restrict__ W, const float* __restrict__ scale,
            const float* __restrict__ shift, const float* __restrict__ bias_in,
            unsigned char* __restrict__ bpack, float* __restrict__ biasadj)
{
    __shared__ float red[8];
    const int n = blockIdx.x;
    const int tid = threadIdx.x;
    const int lane = tid & 31;
    const int wrp  = tid >> 5;
    const int k0 = tid * 8;

    float w[8], v[8], sc[8], sh[8];
    const float* wrow = W + (size_t)n * H_DIM + k0;
    *reinterpret_cast<float4*>(&w[0])  = *reinterpret_cast<const float4*>(wrow);
    *reinterpret_cast<float4*>(&w[4])  = *reinterpret_cast<const float4*>(wrow + 4);
    *reinterpret_cast<float4*>(&sc[0]) = *reinterpret_cast<const float4*>(&scale[k0]);
    *reinterpret_cast<float4*>(&sc[4]) = *reinterpret_cast<const float4*>(&scale[k0 + 4]);
    *reinterpret_cast<float4*>(&sh[0]) = *reinterpret_cast<const float4*>(&shift[k0]);
    *reinterpret_cast<float4*>(&sh[4]) = *reinterpret_cast<const float4*>(&shift[k0 + 4]);

    float s = 0.0f;
    #pragma unroll
    for (int i = 0; i < 8; ++i) {
        v[i] = w[i] * sc[i];
        s = fmaf(sh[i], w[i], s);
    }
    const int nblk = n >> 7, row = n & 127, kc = k0 >> 5;
    half_store8(bpack + (size_t)(nblk * NCH + kc) * CHUNK_B,
                sw64_off(row, (k0 & 31) * 2), v);

    #pragma unroll
    for (int o = 16; o > 0; o >>= 1) s += __shfl_xor_sync(0xFFFFFFFFu, s, o);
    if (lane == 0) red[wrp] = s;
    __syncthreads();
    if (tid == 0) {
        float t = 0.0f;
        #pragma unroll
        for (int i = 0; i < 8; ++i) t += red[i];
        biasadj[n] = bias_in[n] + t;
    }
}

// ---------------- IndRNN scan: fp16 z, 16-deep z prefetch, packs raw-h A ---
__global__ __launch_bounds__(256)
void scan_pack(const __half* __restrict__ Z, const float* __restrict__ u,
               unsigned char* __restrict__ apack, float* __restrict__ hlast,
               float* __restrict__ psum, float* __restrict__ psumsq, int writeA)
{
    const int j2 = blockIdx.x * 256 + threadIdx.x;   // 0..65535 (h-pair index)
    const int b  = j2 >> 10;                         // 0..63
    const int h0 = (j2 & 1023) * 2;                  // even h
    const int kc = h0 >> 5;
    const int colB = (h0 & 31) * 2;

    const float2 uh = *reinterpret_cast<const float2*>(&u[h0]);
    float hc0 = 0.0f, hc1 = 0.0f, s0 = 0.0f, s1 = 0.0f, q0 = 0.0f, q1 = 0.0f;

    const __half2* zp = reinterpret_cast<const __half2*>(Z + (size_t)b * H_DIM + h0);
    unsigned char* chunkBase = apack + (size_t)kc * CHUNK_A;
    const uint32_t swc = (uint32_t)colB;

    #pragma unroll 1
    for (int tb = 0; tb < T_DIM; tb += 16) {
        // batch-issue 16 independent streaming loads (MLP=16)
        __half2 zl[16];
        #pragma unroll
        for (int i = 0; i < 16; ++i)
            zl[i] = __ldcs(zp + (size_t)(tb + i) * (BH / 2));
        #pragma unroll
        for (int i = 0; i < 16; ++i) {
            const int t = tb + i;
            const float2 zv = __half22float2(zl[i]);
            hc0 = fmaxf(fmaf(uh.x, hc0, zv.x), 0.0f);
            hc1 = fmaxf(fmaf(uh.y, hc1, zv.y), 0.0f);
            s0 += hc0; s1 += hc1;
            q0 = fmaf(hc0, hc0, q0); q1 = fmaf(hc1, hc1, q1);
            if (writeA) {
                const int m = t * B_DIM + b;
                const int mblk = m >> 7, row = m & 127;
                const __half h0h = __float2half(hc0);
                const __half h1h = __float2half(hc1);
                const uint32_t hi = (uint32_t)__half_as_ushort(h0h)
                                  | ((uint32_t)__half_as_ushort(h1h) << 16);
                const uint32_t lo = (uint32_t)__half_as_ushort(__float2half(hc0 - __half2float(h0h)))
                                  | ((uint32_t)__half_as_ushort(__float2half(hc1 - __half2float(h1h))) << 16);
                unsigned char* d = chunkBase + (size_t)mblk * (NCH * CHUNK_A)
                                 + (uint32_t)row * 64
                                 + (swc ^ (uint32_t)(((row >> 1) & 3) << 4));
                *reinterpret_cast<uint32_t*>(d)        = hi;
                *reinterpret_cast<uint32_t*>(d + 8192) = lo;
            }
        }
    }
    const int j = b * H_DIM + h0;
    *reinterpret_cast<float2*>(&hlast[j])  = make_float2(hc0, hc1);
    *reinterpret_cast<float2*>(&psum[j])   = make_float2(s0, s1);
    *reinterpret_cast<float2*>(&psumsq[j]) = make_float2(q0, q1);
}

// ---------------- BN stats -> folded affine (16 thr per h, 4 b each) -------
__global__ __launch_bounds__(256)
void bn_finalize(const float* __restrict__ psum, const float* __restrict__ psumsq,
                 const float* __restrict__ gamma, const float* __restrict__ beta,
                 float* __restrict__ scale, float* __restrict__ shift)
{
    __shared__ float ss[2][256];
    const int tid = threadIdx.x;
    const int hl  = tid >> 4;            // 0..15
    const int bg  = tid & 15;            // 0..15
    const int h   = blockIdx.x * 16 + hl;

    float s = 0.0f, s2 = 0.0f;
    #pragma unroll
    for (int i = 0; i < 4; ++i) {
        const int b = bg * 4 + i;
        s  += psum[b * H_DIM + h];
        s2 += psumsq[b * H_DIM + h];
    }
    ss[0][tid] = s;
    ss[1][tid] = s2;
    __syncthreads();
    if (bg == 0) {
        float S = 0.0f, S2 = 0.0f;
        #pragma unroll
        for (int i = 0; i < 16; ++i) {
            S  += ss[0][hl * 16 + i];
            S2 += ss[1][hl * 16 + i];
        }
        const float inv_n = 1.0f / (float)(T_DIM * B_DIM);
        const float mean  = S * inv_n;
        const float var   = S2 * inv_n - mean * mean;
        const float rstd  = rsqrtf(var + BN_EPS);
        const float sc    = gamma[h] * rstd;
        scale[h] = sc;
        shift[h] = fmaf(-mean, sc, beta[h]);
    }
}

// ---------------- final projection -----------------------------------------
__global__ __launch_bounds__(256)
void final_proj(const float* __restrict__ Hlast,
                const float* __restrict__ scale, const float* __restrict__ shift,
                const float* __restrict__ Wl, const float* __restrict__ bl,
                float* __restrict__ out)
{
    const int b = blockIdx.x, c = blockIdx.y;
    __shared__ float red[256];
    float s = 0.0f;
    for (int h = threadIdx.x; h < H_DIM; h += 256) {
        const float hn = fmaf(Hlast[b * H_DIM + h], scale[h], shift[h]);
        s = fmaf(hn, Wl[c * H_DIM + h], s);
    }
    red[threadIdx.x] = s;
    __syncthreads();
    for (int o = 128; o > 0; o >>= 1) {
        if (threadIdx.x < o) red[threadIdx.x] += red[threadIdx.x + o];
        __syncthreads();
    }
    if (threadIdx.x == 0) out[b * C_DIM + c] = red[0] + bl[c];
}

// ---------------- launcher --------------------------------------------------
extern "C" void kernel_launch(void* const* d_in, const int* in_sizes, int n_in,
                              void* d_out, int out_size)
{
    const float* x      = (const float*)d_in[0];
    const float* W0     = (const float*)d_in[1];
    const float* Ws     = (const float*)d_in[2];
    const float* bs     = (const float*)d_in[3];
    const float* us     = (const float*)d_in[4];
    const float* gammas = (const float*)d_in[5];
    const float* betas  = (const float*)d_in[6];
    const float* Wlast  = (const float*)d_in[7];
    const float* blast  = (const float*)d_in[8];
    float* out = (float*)d_out;

    unsigned char *apack, *bpack0, *bpackW;
    __half* z;
    float *biasadj, *psum, *psumsq, *scale, *shift, *hlast;
    cudaGetSymbolAddress((void**)&apack,   g_apack);
    cudaGetSymbolAddress((void**)&bpack0,  g_bpack0);
    cudaGetSymbolAddress((void**)&bpackW,  g_bpackW);
    cudaGetSymbolAddress((void**)&z,       g_z);
    cudaGetSymbolAddress((void**)&biasadj, g_biasadj);
    cudaGetSymbolAddress((void**)&psum,    g_psum);
    cudaGetSymbolAddress((void**)&psumsq,  g_psumsq);
    cudaGetSymbolAddress((void**)&scale,   g_scale);
    cudaGetSymbolAddress((void**)&shift,   g_shift);
    cudaGetSymbolAddress((void**)&hlast,   g_hlast);

    cudaFuncSetAttribute(gemm_mma, cudaFuncAttributeMaxDynamicSharedMemorySize, DSMEM_BYTES);

    const dim3 ggrid(H_DIM / 128, MTOT / 128);   // 16 x 64 = 1024 CTAs, 2/SM
    const int scanBlocks = (BH / 2) / 256;       // 256

    // ---- layer 0 ----
    prep_layer0<<<MTOT + H_DIM, 32>>>(x, W0, apack, bpack0);
    gemm_mma<<<ggrid, 256, DSMEM_BYTES>>>(apack, bpack0, bs, z, NC0);
    scan_pack<<<scanBlocks, 256>>>(z, us, apack, hlast, psum, psumsq, 1);
    bn_finalize<<<H_DIM / 16, 256>>>(psum, psumsq, gammas, betas, scale, shift);

    // ---- layers 1..3 ----
    for (int l = 1; l < 4; ++l) {
        prep_w<<<H_DIM, 256>>>(Ws + (size_t)(l - 1) * H_DIM * H_DIM, scale, shift,
                               bs + l * H_DIM, bpackW, biasadj);
        gemm_mma<<<ggrid, 256, DSMEM_BYTES>>>(apack, bpackW, biasadj, z, NCH);
        scan_pack<<<scanBlocks, 256>>>(z, us + l * H_DIM, apack, hlast, psum, psumsq,
                                       (l < 3) ? 1 : 0);
        bn_finalize<<<H_DIM / 16, 256>>>(psum, psumsq, gammas + l * H_DIM,
                                         betas + l * H_DIM, scale, shift);
    }

    final_proj<<<dim3(B_DIM, C_DIM), 256>>>(hlast, scale, shift, Wlast, blast, out);
}